// round 6
// baseline (speedup 1.0000x reference)
#include <cuda_runtime.h>
#include <cuda_bf16.h>
#include <math.h>
#include <stdint.h>

// ---------------- Problem constants ----------------
#define LAYERS 2
#define D      2048
#define H      16
#define FF     8192
#define BATCH  2
#define SEQ    1024
#define DH     128
#define TD     (3 * D)
#define BS     (BATCH * SEQ)
#define NEGB   (-1e9f)
#define SCALE  0.08838834764831845f

// ---------------- Scratch (static device globals) ----------------
__device__ float g_x   [BS * D];
__device__ float g_h   [BS * D];
__device__ float g_qkv [BS * TD];
__device__ float g_mean[BATCH * D];
__device__ float g_t   [BATCH * D];
// bf16x3 split buffers
__device__ __nv_bfloat16 g_a3s  [BS * 3 * D];
__device__ __nv_bfloat16 g_a3f  [BS * 3 * FF];
__device__ __nv_bfloat16 g_wqkv3[TD * 3 * D];
__device__ __nv_bfloat16 g_wo3  [D  * 3 * D];
__device__ __nv_bfloat16 g_w13  [FF * 3 * D];
__device__ __nv_bfloat16 g_w23  [D  * 3 * FF];

// ---------------- Embedding gather ----------------
__global__ void embed_kernel(const int* __restrict__ ids,
                             const float* __restrict__ emb,
                             float* __restrict__ x) {
    int idx = blockIdx.x * blockDim.x + threadIdx.x;
    int tok = ids[idx / D];
    x[idx] = emb[(size_t)tok * D + (idx % D)];
}

// ---------------- LayerNorm; SPLIT=1 writes bf16x3 (K=D), else fp32 ----------------
template<int SPLIT>
__global__ void ln_kernel(const float* __restrict__ x,
                          const float* __restrict__ g,
                          const float* __restrict__ b,
                          float* __restrict__ outf,
                          __nv_bfloat16* __restrict__ out3) {
    __shared__ float row[D];
    __shared__ float red[256];
    const int tid = threadIdx.x;
    const float* xr = x + (size_t)blockIdx.x * D;

    float s = 0.f;
    for (int i = tid; i < D; i += 256) { float v = xr[i]; row[i] = v; s += v; }
    red[tid] = s; __syncthreads();
    for (int st = 128; st > 0; st >>= 1) {
        if (tid < st) red[tid] += red[tid + st];
        __syncthreads();
    }
    const float mean = red[0] * (1.0f / D);
    __syncthreads();

    float s2 = 0.f;
    for (int i = tid; i < D; i += 256) { float v = row[i] - mean; s2 += v * v; }
    red[tid] = s2; __syncthreads();
    for (int st = 128; st > 0; st >>= 1) {
        if (tid < st) red[tid] += red[tid + st];
        __syncthreads();
    }
    const float rstd = rsqrtf(red[0] * (1.0f / D) + 1e-5f);

    if (SPLIT) {
        __nv_bfloat16* o3 = out3 + (size_t)blockIdx.x * (3 * D);
        for (int i = tid; i < D; i += 256) {
            float v = (row[i] - mean) * rstd * g[i] + b[i];
            __nv_bfloat16 hi = __float2bfloat16(v);
            __nv_bfloat16 lo = __float2bfloat16(v - __bfloat162float(hi));
            o3[i]         = hi;
            o3[D + i]     = lo;
            o3[2 * D + i] = hi;
        }
    } else {
        float* orow = outf + (size_t)blockIdx.x * D;
        for (int i = tid; i < D; i += 256)
            orow[i] = (row[i] - mean) * rstd * g[i] + b[i];
    }
}

// ---------------- Split-convert + transpose weights: W[K,N] fp32 -> Wt3[N,3K] bf16 ----------------
// 64k x 32n tiles, bf16x2 vectorized writes.
__global__ void convw_kernel(const float* __restrict__ W,
                             __nv_bfloat16* __restrict__ Wt3, int K, int N) {
    __shared__ float tile[64][33];
    int n0 = blockIdx.x * 32, k0 = blockIdx.y * 64;
    int tx = threadIdx.x, ty = threadIdx.y;   // (32, 8)
    #pragma unroll
    for (int i = 0; i < 64; i += 8)
        tile[ty + i][tx] = W[(size_t)(k0 + ty + i) * N + n0 + tx];
    __syncthreads();
    #pragma unroll
    for (int i = 0; i < 32; i += 8) {
        int nn = ty + i;                       // local n
        int n = n0 + nn;
        float x0 = tile[2 * tx][nn];
        float x1 = tile[2 * tx + 1][nn];
        __nv_bfloat162 hi, lo;
        hi.x = __float2bfloat16(x0);
        hi.y = __float2bfloat16(x1);
        lo.x = __float2bfloat16(x0 - __bfloat162float(hi.x));
        lo.y = __float2bfloat16(x1 - __bfloat162float(hi.y));
        size_t base = (size_t)n * (3 * K);
        int k = k0 + 2 * tx;
        *(__nv_bfloat162*)(Wt3 + base + k)         = hi;
        *(__nv_bfloat162*)(Wt3 + base + K + k)     = hi;
        *(__nv_bfloat162*)(Wt3 + base + 2 * K + k) = lo;
    }
}

// ================= mma.sync bf16 GEMM, BK=64, 4 stages, reg double-buffer =================
// C[M,N] fp32 = A[M,K3] bf16 row-major @ Bt[N,K3]^T
// EPI: 0 = store f32, 1 = residual add f32, 2 = gelu -> bf16x3 split into A3out
#define BG_STAGE  32768                 // 16KB A + 16KB B
#define BG_SMEM   (4 * BG_STAGE)        // 128KB

__device__ __forceinline__ unsigned swz(unsigned o) { return o ^ ((o >> 3) & 0x70); }

__device__ __forceinline__ void ldsm4(unsigned addr, unsigned& r0, unsigned& r1,
                                      unsigned& r2, unsigned& r3) {
    asm volatile("ldmatrix.sync.aligned.m8n8.x4.shared.b16 {%0,%1,%2,%3}, [%4];\n"
                 : "=r"(r0), "=r"(r1), "=r"(r2), "=r"(r3) : "r"(addr));
}
__device__ __forceinline__ void mma16816(float* c, unsigned a0, unsigned a1,
                                         unsigned a2, unsigned a3,
                                         unsigned b0, unsigned b1) {
    asm volatile(
        "mma.sync.aligned.m16n8k16.row.col.f32.bf16.bf16.f32 "
        "{%0,%1,%2,%3},{%4,%5,%6,%7},{%8,%9},{%0,%1,%2,%3};\n"
        : "+f"(c[0]), "+f"(c[1]), "+f"(c[2]), "+f"(c[3])
        : "r"(a0), "r"(a1), "r"(a2), "r"(a3), "r"(b0), "r"(b1));
}
__device__ __forceinline__ void cpasync16(unsigned saddr, const void* g) {
    asm volatile("cp.async.cg.shared.global [%0], [%1], 16;\n" :: "r"(saddr), "l"(g));
}

// load one 128-row x 64-col bf16 tile (128B rows, SW128) into smem (16KB)
__device__ __forceinline__ void load_tile64(const __nv_bfloat16* gbase, unsigned sbase,
                                            int ld, int k0) {
    int t = threadIdx.x;
    #pragma unroll
    for (int i = 0; i < 4; i++) {
        int c = t + i * 256;              // 0..1023
        int row = c >> 3, seg = c & 7;
        cpasync16(sbase + swz((unsigned)(row * 128 + seg * 16)),
                  gbase + (size_t)row * ld + k0 + seg * 8);
    }
}

// NOTE: ldsm address for k-step offset `off` (bits 5-6 only) is swz(base)^off,
// NOT swz(base)+off -- the swizzle XOR can make addition carry into row bits.
__device__ __forceinline__ void ldsm_frags(const unsigned aA[4], const unsigned bA[2],
                                           unsigned off,
                                           unsigned fa[4][4], unsigned fb[2][4]) {
    #pragma unroll
    for (int mi = 0; mi < 4; mi++)
        ldsm4(aA[mi] ^ off, fa[mi][0], fa[mi][1], fa[mi][2], fa[mi][3]);
    #pragma unroll
    for (int np = 0; np < 2; np++)
        ldsm4(bA[np] ^ off, fb[np][0], fb[np][1], fb[np][2], fb[np][3]);
}

__device__ __forceinline__ void mma_tile(float acc[4][4][4],
                                         unsigned fa[4][4], unsigned fb[2][4]) {
    #pragma unroll
    for (int mi = 0; mi < 4; mi++)
        #pragma unroll
        for (int ni = 0; ni < 4; ni++) {
            unsigned b0 = fb[ni >> 1][ni & 1];
            unsigned b1 = fb[ni >> 1][2 + (ni & 1)];
            mma16816(acc[mi][ni], fa[mi][0], fa[mi][1], fa[mi][2], fa[mi][3], b0, b1);
        }
}

__device__ __forceinline__ float gelu_f(float xx) {
    return 0.5f * xx * (1.0f + tanhf(0.7978845608028654f *
                                     (xx + 0.044715f * xx * xx * xx)));
}
__device__ __forceinline__ __nv_bfloat162 hi2(float a, float b) {
    __nv_bfloat162 r;
    r.x = __float2bfloat16(a); r.y = __float2bfloat16(b);
    return r;
}
__device__ __forceinline__ __nv_bfloat162 lo2(float a, float b, __nv_bfloat162 h) {
    __nv_bfloat162 r;
    r.x = __float2bfloat16(a - __bfloat162float(h.x));
    r.y = __float2bfloat16(b - __bfloat162float(h.y));
    return r;
}

template<int EPI>
__global__ void __launch_bounds__(256)
bgemm_kernel(const __nv_bfloat16* __restrict__ A,
             const __nv_bfloat16* __restrict__ Bt,
             float* __restrict__ C,
             __nv_bfloat16* __restrict__ A3out,
             int M, int N, int K3) {
    extern __shared__ __align__(128) char smem[];
    unsigned sbase = (unsigned)__cvta_generic_to_shared(smem);

    const int tid = threadIdx.x, lane = tid & 31, warp = tid >> 5;
    const int warpM = warp & 1, warpN = warp >> 1;
    const int rowBase = blockIdx.x * 128;       // M fastest for B-slab L2 reuse
    const int colBase = blockIdx.y * 128;
    const __nv_bfloat16* Ab = A  + (size_t)rowBase * K3;
    const __nv_bfloat16* Bb = Bt + (size_t)colBase * K3;

    float acc[4][4][4];
    #pragma unroll
    for (int i = 0; i < 4; i++)
        #pragma unroll
        for (int j = 0; j < 4; j++)
            #pragma unroll
            for (int r = 0; r < 4; r++) acc[i][j][r] = 0.f;

    const int KT = K3 >> 6;
    #pragma unroll
    for (int s = 0; s < 3; s++) {                 // prologue: 3 stages
        unsigned st = sbase + s * BG_STAGE;
        load_tile64(Ab, st, K3, s << 6);
        load_tile64(Bb, st + 16384, K3, s << 6);
        asm volatile("cp.async.commit_group;\n");
    }

    // ldsm base addresses (within-stage, swizzled); k-step applied via XOR
    unsigned aAB[4], bAB[2];
    #pragma unroll
    for (int mi = 0; mi < 4; mi++) {
        int row = warpM * 64 + mi * 16 + (lane & 15);
        aAB[mi] = swz((unsigned)(row * 128 + (lane >> 4) * 16));
    }
    #pragma unroll
    for (int np = 0; np < 2; np++) {
        int rown = warpN * 32 + np * 16 + (lane & 15);
        bAB[np] = 16384u + swz((unsigned)(rown * 128 + (lane >> 4) * 16));
    }

    unsigned fa0[4][4], fb0[2][4], fa1[4][4], fb1[2][4];

    for (int kt = 0; kt < KT; kt++) {
        asm volatile("cp.async.wait_group 2;\n");
        __syncthreads();

        unsigned stg = sbase + (unsigned)(kt & 3) * BG_STAGE;
        unsigned aA[4] = { stg + aAB[0], stg + aAB[1], stg + aAB[2], stg + aAB[3] };
        unsigned bA[2] = { stg + bAB[0], stg + bAB[1] };

        ldsm_frags(aA, bA, 0, fa0, fb0);

        const int next = kt + 3;
        if (next < KT) {
            unsigned ns = sbase + (unsigned)(next & 3) * BG_STAGE;
            load_tile64(Ab, ns, K3, next << 6);
            load_tile64(Bb, ns + 16384, K3, next << 6);
        }
        asm volatile("cp.async.commit_group;\n");

        ldsm_frags(aA, bA, 32, fa1, fb1);
        mma_tile(acc, fa0, fb0);
        ldsm_frags(aA, bA, 64, fa0, fb0);
        mma_tile(acc, fa1, fb1);
        ldsm_frags(aA, bA, 96, fa1, fb1);
        mma_tile(acc, fa0, fb0);
        mma_tile(acc, fa1, fb1);
    }

    // epilogue
    #pragma unroll
    for (int mi = 0; mi < 4; mi++)
        #pragma unroll
        for (int ni = 0; ni < 4; ni++) {
            int row = rowBase + warpM * 64 + mi * 16 + (lane >> 2);
            int col = colBase + warpN * 32 + ni * 8 + 2 * (lane & 3);
            float v0 = acc[mi][ni][0], v1 = acc[mi][ni][1];
            float v2 = acc[mi][ni][2], v3 = acc[mi][ni][3];
            if (EPI == 2) {
                v0 = gelu_f(v0); v1 = gelu_f(v1);
                v2 = gelu_f(v2); v3 = gelu_f(v3);
                size_t b0 = (size_t)row * (3 * (size_t)N);
                size_t b1 = (size_t)(row + 8) * (3 * (size_t)N);
                __nv_bfloat162 h01 = hi2(v0, v1), l01 = lo2(v0, v1, h01);
                __nv_bfloat162 h23 = hi2(v2, v3), l23 = lo2(v2, v3, h23);
                *(__nv_bfloat162*)(A3out + b0 + col)         = h01;
                *(__nv_bfloat162*)(A3out + b0 + N + col)     = l01;
                *(__nv_bfloat162*)(A3out + b0 + 2 * N + col) = h01;
                *(__nv_bfloat162*)(A3out + b1 + col)         = h23;
                *(__nv_bfloat162*)(A3out + b1 + N + col)     = l23;
                *(__nv_bfloat162*)(A3out + b1 + 2 * N + col) = h23;
            } else {
                float* p = C + (size_t)row * N + col;
                float* q = C + (size_t)(row + 8) * N + col;
                if (EPI == 1) { v0 += p[0]; v1 += p[1]; v2 += q[0]; v3 += q[1]; }
                *(float2*)p = make_float2(v0, v1);
                *(float2*)q = make_float2(v2, v3);
            }
        }
}

// ---------------- Tiled causal attention ----------------
__global__ void __launch_bounds__(256)
attn_kernel(const float* __restrict__ qkv,
            const int* __restrict__ mask,
            __nv_bfloat16* __restrict__ a3) {
    __shared__ float Qs[8][132];
    __shared__ float Kc[32][132];
    __shared__ float Vc[32][132];

    const int tid = threadIdx.x, lane = tid & 31, warp = tid >> 5;
    const int q0 = blockIdx.x * 8;
    const int h  = blockIdx.y;
    const int b  = blockIdx.z;
    const int q  = q0 + warp;
    const size_t base = (size_t)b * SEQ * TD;

    {
        int r = tid >> 5, c = (tid & 31) * 4;
        *(float4*)&Qs[r][c] = *(const float4*)&qkv[base + (size_t)(q0 + r) * TD + h * DH + c];
    }

    float m = -1e30f, l = 0.f;
    float4 o = make_float4(0.f, 0.f, 0.f, 0.f);
    const int jmax = q0 + 7;

    for (int j0 = 0; j0 <= jmax; j0 += 32) {
        __syncthreads();
        #pragma unroll
        for (int i = 0; i < 4; i++) {
            int idx = tid + i * 256;
            int r = idx >> 5, c = (idx & 31) * 4;
            const float* src = qkv + base + (size_t)(j0 + r) * TD + h * DH + c;
            *(float4*)&Kc[r][c] = *(const float4*)(src + D);
            *(float4*)&Vc[r][c] = *(const float4*)(src + 2 * D);
        }
        __syncthreads();

        const int j = j0 + lane;
        float s = -1e30f;
        if (j <= q) {
            float dot = 0.f;
            #pragma unroll 8
            for (int d = 0; d < DH; d += 4) {
                float4 kv = *(const float4*)&Kc[lane][d];
                float4 qv = *(const float4*)&Qs[warp][d];
                dot = fmaf(kv.x, qv.x, dot);
                dot = fmaf(kv.y, qv.y, dot);
                dot = fmaf(kv.z, qv.z, dot);
                dot = fmaf(kv.w, qv.w, dot);
            }
            s = dot * SCALE;
            if (mask[b * SEQ + j] == 0) s += NEGB;
        }

        float cmax = s;
        #pragma unroll
        for (int off = 16; off > 0; off >>= 1)
            cmax = fmaxf(cmax, __shfl_xor_sync(0xffffffffu, cmax, off));
        float newm = fmaxf(m, cmax);
        float corr = expf(m - newm);
        float p = expf(s - newm);
        float psum = p;
        #pragma unroll
        for (int off = 16; off > 0; off >>= 1)
            psum += __shfl_xor_sync(0xffffffffu, psum, off);
        l = l * corr + psum;
        o.x *= corr; o.y *= corr; o.z *= corr; o.w *= corr;

        #pragma unroll 8
        for (int jj = 0; jj < 32; jj++) {
            float pj = __shfl_sync(0xffffffffu, p, jj);
            float4 v = *(const float4*)&Vc[jj][lane * 4];
            o.x = fmaf(pj, v.x, o.x);
            o.y = fmaf(pj, v.y, o.y);
            o.z = fmaf(pj, v.z, o.z);
            o.w = fmaf(pj, v.w, o.w);
        }
        m = newm;
    }

    const float inv = 1.f / l;
    float v0 = o.x * inv, v1 = o.y * inv, v2 = o.z * inv, v3 = o.w * inv;
    size_t r3 = (size_t)(b * SEQ + q) * (3 * D);
    int col = h * DH + lane * 4;
    __nv_bfloat162 h01 = hi2(v0, v1), l01 = lo2(v0, v1, h01);
    __nv_bfloat162 h23 = hi2(v2, v3), l23 = lo2(v2, v3, h23);
    *(__nv_bfloat162*)(a3 + r3 + col)             = h01;
    *(__nv_bfloat162*)(a3 + r3 + col + 2)         = h23;
    *(__nv_bfloat162*)(a3 + r3 + D + col)         = l01;
    *(__nv_bfloat162*)(a3 + r3 + D + col + 2)     = l23;
    *(__nv_bfloat162*)(a3 + r3 + 2 * D + col)     = h01;
    *(__nv_bfloat162*)(a3 + r3 + 2 * D + col + 2) = h23;
}

// ---------------- Pool + head ----------------
__global__ void meanpool_kernel(const float* __restrict__ hs,
                                const int* __restrict__ mask,
                                float* __restrict__ mean) {
    int idx = blockIdx.x * blockDim.x + threadIdx.x;
    int b = idx / D;
    int d = idx % D;
    float acc = 0.f, msum = 0.f;
    const float* hb = hs + (size_t)b * SEQ * D + d;
    const int* mb = mask + b * SEQ;
    for (int s = 0; s < SEQ; s++) {
        float mf = (float)mb[s];
        acc = fmaf(mf, hb[(size_t)s * D], acc);
        msum += mf;
    }
    mean[idx] = acc / fmaxf(msum, 1e-9f);
}

__global__ void head1_kernel(const float* __restrict__ mean,
                             const float* __restrict__ Wc1,
                             const float* __restrict__ bc1,
                             float* __restrict__ t) {
    int idx = blockIdx.x * blockDim.x + threadIdx.x;
    int b = idx / D;
    int j = idx % D;
    float acc = bc1[j];
    const float* mb = mean + (size_t)b * D;
    for (int k = 0; k < D; k++)
        acc = fmaf(mb[k], Wc1[(size_t)k * D + j], acc);
    t[idx] = tanhf(acc);
}

__global__ void head2_kernel(const float* __restrict__ t,
                             const float* __restrict__ Wc2,
                             const float* __restrict__ bc2,
                             float* __restrict__ out) {
    __shared__ float red[256];
    __shared__ float logits[4];
    const int tid = threadIdx.x;
    float part[4] = {0.f, 0.f, 0.f, 0.f};
    for (int j = tid; j < D; j += 256) {
        float t0 = t[j], t1 = t[D + j];
        float w0 = Wc2[2 * j], w1 = Wc2[2 * j + 1];
        part[0] = fmaf(t0, w0, part[0]);
        part[1] = fmaf(t0, w1, part[1]);
        part[2] = fmaf(t1, w0, part[2]);
        part[3] = fmaf(t1, w1, part[3]);
    }
    for (int c = 0; c < 4; c++) {
        __syncthreads();
        red[tid] = part[c]; __syncthreads();
        for (int st = 128; st > 0; st >>= 1) {
            if (tid < st) red[tid] += red[tid + st];
            __syncthreads();
        }
        if (tid == 0) logits[c] = red[0] + bc2[c & 1];
    }
    __syncthreads();
    if (tid == 0) {
        for (int b = 0; b < BATCH; b++) {
            float l0 = logits[2 * b], l1 = logits[2 * b + 1];
            float m = fmaxf(l0, l1);
            float e0 = expf(l0 - m), e1 = expf(l1 - m);
            out[b] = e1 / (e0 + e1);
        }
    }
}

// ---------------- Launch ----------------
extern "C" void kernel_launch(void* const* d_in, const int* in_sizes, int n_in,
                              void* d_out, int out_size) {
    const int*   ids   = (const int*)d_in[0];
    const int*   amask = (const int*)d_in[1];
    const float* emb   = (const float*)d_in[2];
    const float* ln1_g = (const float*)d_in[3];
    const float* ln1_b = (const float*)d_in[4];
    const float* Wqkv  = (const float*)d_in[5];
    const float* Wo    = (const float*)d_in[6];
    const float* ln2_g = (const float*)d_in[7];
    const float* ln2_b = (const float*)d_in[8];
    const float* W1    = (const float*)d_in[9];
    const float* W2    = (const float*)d_in[10];
    const float* lnf_g = (const float*)d_in[11];
    const float* lnf_b = (const float*)d_in[12];
    const float* Wc1   = (const float*)d_in[13];
    const float* bc1   = (const float*)d_in[14];
    const float* Wc2   = (const float*)d_in[15];
    const float* bc2   = (const float*)d_in[16];
    float* out = (float*)d_out;

    float *x, *h, *qkv, *mean, *t;
    __nv_bfloat16 *a3s, *a3f, *wqkv3, *wo3, *w13, *w23;
    cudaGetSymbolAddress((void**)&x,    g_x);
    cudaGetSymbolAddress((void**)&h,    g_h);
    cudaGetSymbolAddress((void**)&qkv,  g_qkv);
    cudaGetSymbolAddress((void**)&mean, g_mean);
    cudaGetSymbolAddress((void**)&t,    g_t);
    cudaGetSymbolAddress((void**)&a3s,   g_a3s);
    cudaGetSymbolAddress((void**)&a3f,   g_a3f);
    cudaGetSymbolAddress((void**)&wqkv3, g_wqkv3);
    cudaGetSymbolAddress((void**)&wo3,   g_wo3);
    cudaGetSymbolAddress((void**)&w13,   g_w13);
    cudaGetSymbolAddress((void**)&w23,   g_w23);

    cudaFuncSetAttribute(bgemm_kernel<0>,
                         cudaFuncAttributeMaxDynamicSharedMemorySize, BG_SMEM);
    cudaFuncSetAttribute(bgemm_kernel<1>,
                         cudaFuncAttributeMaxDynamicSharedMemorySize, BG_SMEM);
    cudaFuncSetAttribute(bgemm_kernel<2>,
                         cudaFuncAttributeMaxDynamicSharedMemorySize, BG_SMEM);

    embed_kernel<<<(BS * D) / 256, 256>>>(ids, emb, x);

    for (int l = 0; l < LAYERS; l++) {
        // attention block
        ln_kernel<1><<<BS, 256>>>(x, ln1_g + (size_t)l * D, ln1_b + (size_t)l * D,
                                  nullptr, a3s);
        convw_kernel<<<dim3(TD / 32, D / 64), dim3(32, 8)>>>(
            Wqkv + (size_t)l * D * TD, wqkv3, D, TD);
        bgemm_kernel<0><<<dim3(BS / 128, TD / 128), 256, BG_SMEM>>>(
            a3s, wqkv3, qkv, nullptr, BS, TD, 3 * D);
        attn_kernel<<<dim3(SEQ / 8, H, BATCH), 256>>>(qkv, amask, a3s);
        convw_kernel<<<dim3(D / 32, D / 64), dim3(32, 8)>>>(
            Wo + (size_t)l * D * D, wo3, D, D);
        bgemm_kernel<1><<<dim3(BS / 128, D / 128), 256, BG_SMEM>>>(
            a3s, wo3, x, nullptr, BS, D, 3 * D);
        // mlp block
        ln_kernel<1><<<BS, 256>>>(x, ln2_g + (size_t)l * D, ln2_b + (size_t)l * D,
                                  nullptr, a3s);
        convw_kernel<<<dim3(FF / 32, D / 64), dim3(32, 8)>>>(
            W1 + (size_t)l * D * FF, w13, D, FF);
        bgemm_kernel<2><<<dim3(BS / 128, FF / 128), 256, BG_SMEM>>>(
            a3s, w13, nullptr, a3f, BS, FF, 3 * D);
        convw_kernel<<<dim3(D / 32, FF / 64), dim3(32, 8)>>>(
            W2 + (size_t)l * FF * D, w23, FF, D);
        bgemm_kernel<1><<<dim3(BS / 128, D / 128), 256, BG_SMEM>>>(
            a3f, w23, x, nullptr, BS, D, 3 * FF);
    }

    ln_kernel<0><<<BS, 256>>>(x, lnf_g, lnf_b, h, nullptr);
    meanpool_kernel<<<(BATCH * D) / 256, 256>>>(h, amask, mean);
    head1_kernel<<<(BATCH * D) / 256, 256>>>(mean, Wc1, bc1, t);
    head2_kernel<<<1, 256>>>(t, Wc2, bc2, out);
}

// round 7
// speedup vs baseline: 1.5980x; 1.5980x over previous
#include <cuda_runtime.h>
#include <cuda_bf16.h>
#include <math.h>
#include <stdint.h>

// ---------------- Problem constants ----------------
#define LAYERS 2
#define D      2048
#define H      16
#define FF     8192
#define BATCH  2
#define SEQ    1024
#define DH     128
#define TD     (3 * D)
#define BS     (BATCH * SEQ)
#define NEGB   (-1e9f)
#define SCALE  0.08838834764831845f

// ---------------- Scratch (static device globals) ----------------
__device__ float g_x   [BS * D];
__device__ float g_h   [BS * D];
__device__ float g_qkv [BS * TD];
__device__ float g_mean[BATCH * D];
__device__ float g_t   [BATCH * D];
// bf16x3 split buffers
__device__ __nv_bfloat16 g_a3s  [BS * 3 * D];
__device__ __nv_bfloat16 g_a3f  [BS * 3 * FF];
__device__ __nv_bfloat16 g_wqkv3[TD * 3 * D];
__device__ __nv_bfloat16 g_wo3  [D  * 3 * D];
__device__ __nv_bfloat16 g_w13  [FF * 3 * D];
__device__ __nv_bfloat16 g_w23  [D  * 3 * FF];

// ---------------- Embedding gather ----------------
__global__ void embed_kernel(const int* __restrict__ ids,
                             const float* __restrict__ emb,
                             float* __restrict__ x) {
    int idx = blockIdx.x * blockDim.x + threadIdx.x;
    int tok = ids[idx / D];
    x[idx] = emb[(size_t)tok * D + (idx % D)];
}

// ---------------- LayerNorm; SPLIT=1 writes bf16x3 (K=D), else fp32 ----------------
template<int SPLIT>
__global__ void ln_kernel(const float* __restrict__ x,
                          const float* __restrict__ g,
                          const float* __restrict__ b,
                          float* __restrict__ outf,
                          __nv_bfloat16* __restrict__ out3) {
    __shared__ float row[D];
    __shared__ float red[256];
    const int tid = threadIdx.x;
    const float* xr = x + (size_t)blockIdx.x * D;

    float s = 0.f;
    for (int i = tid; i < D; i += 256) { float v = xr[i]; row[i] = v; s += v; }
    red[tid] = s; __syncthreads();
    for (int st = 128; st > 0; st >>= 1) {
        if (tid < st) red[tid] += red[tid + st];
        __syncthreads();
    }
    const float mean = red[0] * (1.0f / D);
    __syncthreads();

    float s2 = 0.f;
    for (int i = tid; i < D; i += 256) { float v = row[i] - mean; s2 += v * v; }
    red[tid] = s2; __syncthreads();
    for (int st = 128; st > 0; st >>= 1) {
        if (tid < st) red[tid] += red[tid + st];
        __syncthreads();
    }
    const float rstd = rsqrtf(red[0] * (1.0f / D) + 1e-5f);

    if (SPLIT) {
        __nv_bfloat16* o3 = out3 + (size_t)blockIdx.x * (3 * D);
        for (int i = tid; i < D; i += 256) {
            float v = (row[i] - mean) * rstd * g[i] + b[i];
            __nv_bfloat16 hi = __float2bfloat16(v);
            __nv_bfloat16 lo = __float2bfloat16(v - __bfloat162float(hi));
            o3[i]         = hi;
            o3[D + i]     = lo;
            o3[2 * D + i] = hi;
        }
    } else {
        float* orow = outf + (size_t)blockIdx.x * D;
        for (int i = tid; i < D; i += 256)
            orow[i] = (row[i] - mean) * rstd * g[i] + b[i];
    }
}

// ---------------- Split-convert + transpose weights: W[K,N] fp32 -> Wt3[N,3K] bf16 ----------------
__global__ void convw_kernel(const float* __restrict__ W,
                             __nv_bfloat16* __restrict__ Wt3, int K, int N) {
    __shared__ float tile[64][33];
    int n0 = blockIdx.x * 32, k0 = blockIdx.y * 64;
    int tx = threadIdx.x, ty = threadIdx.y;   // (32, 8)
    #pragma unroll
    for (int i = 0; i < 64; i += 8)
        tile[ty + i][tx] = W[(size_t)(k0 + ty + i) * N + n0 + tx];
    __syncthreads();
    #pragma unroll
    for (int i = 0; i < 32; i += 8) {
        int nn = ty + i;
        int n = n0 + nn;
        float x0 = tile[2 * tx][nn];
        float x1 = tile[2 * tx + 1][nn];
        __nv_bfloat162 hi, lo;
        hi.x = __float2bfloat16(x0);
        hi.y = __float2bfloat16(x1);
        lo.x = __float2bfloat16(x0 - __bfloat162float(hi.x));
        lo.y = __float2bfloat16(x1 - __bfloat162float(hi.y));
        size_t base = (size_t)n * (3 * K);
        int k = k0 + 2 * tx;
        *(__nv_bfloat162*)(Wt3 + base + k)         = hi;
        *(__nv_bfloat162*)(Wt3 + base + K + k)     = hi;
        *(__nv_bfloat162*)(Wt3 + base + 2 * K + k) = lo;
    }
}

// ========= mma.sync bf16 GEMM: BK=32, 4 stages x 16KB, 2 CTAs/SM, reg double-buffer =========
// C[M,N] fp32 = A[M,K3] bf16 row-major @ Bt[N,K3]^T
// EPI: 0 = store f32, 1 = residual add f32, 2 = gelu -> bf16x3 split into A3out
#define BG_STAGE  16384                 // 8KB A + 8KB B
#define BG_SMEM   (4 * BG_STAGE)        // 64KB -> 2 CTAs/SM

__device__ __forceinline__ unsigned swz(unsigned o) { return o ^ ((o >> 3) & 0x70); }

__device__ __forceinline__ void ldsm4(unsigned addr, unsigned& r0, unsigned& r1,
                                      unsigned& r2, unsigned& r3) {
    asm volatile("ldmatrix.sync.aligned.m8n8.x4.shared.b16 {%0,%1,%2,%3}, [%4];\n"
                 : "=r"(r0), "=r"(r1), "=r"(r2), "=r"(r3) : "r"(addr));
}
__device__ __forceinline__ void mma16816(float* c, unsigned a0, unsigned a1,
                                         unsigned a2, unsigned a3,
                                         unsigned b0, unsigned b1) {
    asm volatile(
        "mma.sync.aligned.m16n8k16.row.col.f32.bf16.bf16.f32 "
        "{%0,%1,%2,%3},{%4,%5,%6,%7},{%8,%9},{%0,%1,%2,%3};\n"
        : "+f"(c[0]), "+f"(c[1]), "+f"(c[2]), "+f"(c[3])
        : "r"(a0), "r"(a1), "r"(a2), "r"(a3), "r"(b0), "r"(b1));
}
__device__ __forceinline__ void cpasync16(unsigned saddr, const void* g) {
    asm volatile("cp.async.cg.shared.global [%0], [%1], 16;\n" :: "r"(saddr), "l"(g));
}

// load 128-row x 32-col bf16 tile into paired-row swizzled smem (8KB)
__device__ __forceinline__ void load_tile(const __nv_bfloat16* gbase, unsigned sbase,
                                          int ld, int k0) {
    int t = threadIdx.x;
    #pragma unroll
    for (int i = 0; i < 2; i++) {
        int c = t + i * 256;
        int row = c >> 2, seg = c & 3;
        unsigned so = swz((unsigned)((row >> 1) * 128 + (row & 1) * 64 + seg * 16));
        cpasync16(sbase + so, gbase + (size_t)row * ld + k0 + seg * 8);
    }
}

// frag fetch: ks offset (bit 5 only) applied via XOR on the swizzled base
__device__ __forceinline__ void ldsm_frags(const unsigned aA[4], const unsigned bA[2],
                                           unsigned off,
                                           unsigned fa[4][4], unsigned fb[2][4]) {
    #pragma unroll
    for (int mi = 0; mi < 4; mi++)
        ldsm4(aA[mi] ^ off, fa[mi][0], fa[mi][1], fa[mi][2], fa[mi][3]);
    #pragma unroll
    for (int np = 0; np < 2; np++)
        ldsm4(bA[np] ^ off, fb[np][0], fb[np][1], fb[np][2], fb[np][3]);
}

__device__ __forceinline__ void mma_tile(float acc[4][4][4],
                                         unsigned fa[4][4], unsigned fb[2][4]) {
    #pragma unroll
    for (int mi = 0; mi < 4; mi++)
        #pragma unroll
        for (int ni = 0; ni < 4; ni++) {
            unsigned b0 = fb[ni >> 1][ni & 1];
            unsigned b1 = fb[ni >> 1][2 + (ni & 1)];
            mma16816(acc[mi][ni], fa[mi][0], fa[mi][1], fa[mi][2], fa[mi][3], b0, b1);
        }
}

__device__ __forceinline__ float gelu_f(float xx) {
    return 0.5f * xx * (1.0f + tanhf(0.7978845608028654f *
                                     (xx + 0.044715f * xx * xx * xx)));
}
__device__ __forceinline__ __nv_bfloat162 hi2(float a, float b) {
    __nv_bfloat162 r;
    r.x = __float2bfloat16(a); r.y = __float2bfloat16(b);
    return r;
}
__device__ __forceinline__ __nv_bfloat162 lo2(float a, float b, __nv_bfloat162 h) {
    __nv_bfloat162 r;
    r.x = __float2bfloat16(a - __bfloat162float(h.x));
    r.y = __float2bfloat16(b - __bfloat162float(h.y));
    return r;
}

template<int EPI>
__global__ void __launch_bounds__(256, 2)
bgemm_kernel(const __nv_bfloat16* __restrict__ A,
             const __nv_bfloat16* __restrict__ Bt,
             float* __restrict__ C,
             __nv_bfloat16* __restrict__ A3out,
             int M, int N, int K3) {
    extern __shared__ __align__(128) char smem[];
    unsigned sbase = (unsigned)__cvta_generic_to_shared(smem);

    const int tid = threadIdx.x, lane = tid & 31, warp = tid >> 5;
    const int warpM = warp & 1, warpN = warp >> 1;
    const int rowBase = blockIdx.x * 128;       // M fastest for B-slab L2 reuse
    const int colBase = blockIdx.y * 128;
    const __nv_bfloat16* Ab = A  + (size_t)rowBase * K3;
    const __nv_bfloat16* Bb = Bt + (size_t)colBase * K3;

    float acc[4][4][4];
    #pragma unroll
    for (int i = 0; i < 4; i++)
        #pragma unroll
        for (int j = 0; j < 4; j++)
            #pragma unroll
            for (int r = 0; r < 4; r++) acc[i][j][r] = 0.f;

    const int KT = K3 >> 5;
    #pragma unroll
    for (int s = 0; s < 3; s++) {                 // prologue: 3 stages
        unsigned st = sbase + s * BG_STAGE;
        load_tile(Ab, st, K3, s << 5);
        load_tile(Bb, st + 8192, K3, s << 5);
        asm volatile("cp.async.commit_group;\n");
    }

    // ldsm base addresses at ks=0 (paired-row layout); ks applied via ^32
    unsigned aAB[4], bAB[2];
    #pragma unroll
    for (int mi = 0; mi < 4; mi++) {
        int row = warpM * 64 + mi * 16 + (lane & 15);
        aAB[mi] = swz((unsigned)((row >> 1) * 128 + (row & 1) * 64 + (lane >> 4) * 16));
    }
    #pragma unroll
    for (int np = 0; np < 2; np++) {
        int rown = warpN * 32 + np * 16 + (lane & 15);
        bAB[np] = 8192u + swz((unsigned)((rown >> 1) * 128 + (rown & 1) * 64 + (lane >> 4) * 16));
    }

    unsigned fa0[4][4], fb0[2][4], fa1[4][4], fb1[2][4];

    for (int kt = 0; kt < KT; kt++) {
        asm volatile("cp.async.wait_group 2;\n");
        __syncthreads();

        unsigned stg = sbase + (unsigned)(kt & 3) * BG_STAGE;
        unsigned aA[4] = { stg + aAB[0], stg + aAB[1], stg + aAB[2], stg + aAB[3] };
        unsigned bA[2] = { stg + bAB[0], stg + bAB[1] };

        ldsm_frags(aA, bA, 0, fa0, fb0);

        const int next = kt + 3;
        if (next < KT) {
            unsigned ns = sbase + (unsigned)(next & 3) * BG_STAGE;
            load_tile(Ab, ns, K3, next << 5);
            load_tile(Bb, ns + 8192, K3, next << 5);
        }
        asm volatile("cp.async.commit_group;\n");

        ldsm_frags(aA, bA, 32, fa1, fb1);   // overlaps with mma ks0 issue below
        mma_tile(acc, fa0, fb0);
        mma_tile(acc, fa1, fb1);
    }

    // epilogue
    #pragma unroll
    for (int mi = 0; mi < 4; mi++)
        #pragma unroll
        for (int ni = 0; ni < 4; ni++) {
            int row = rowBase + warpM * 64 + mi * 16 + (lane >> 2);
            int col = colBase + warpN * 32 + ni * 8 + 2 * (lane & 3);
            float v0 = acc[mi][ni][0], v1 = acc[mi][ni][1];
            float v2 = acc[mi][ni][2], v3 = acc[mi][ni][3];
            if (EPI == 2) {
                v0 = gelu_f(v0); v1 = gelu_f(v1);
                v2 = gelu_f(v2); v3 = gelu_f(v3);
                size_t b0 = (size_t)row * (3 * (size_t)N);
                size_t b1 = (size_t)(row + 8) * (3 * (size_t)N);
                __nv_bfloat162 h01 = hi2(v0, v1), l01 = lo2(v0, v1, h01);
                __nv_bfloat162 h23 = hi2(v2, v3), l23 = lo2(v2, v3, h23);
                *(__nv_bfloat162*)(A3out + b0 + col)         = h01;
                *(__nv_bfloat162*)(A3out + b0 + N + col)     = l01;
                *(__nv_bfloat162*)(A3out + b0 + 2 * N + col) = h01;
                *(__nv_bfloat162*)(A3out + b1 + col)         = h23;
                *(__nv_bfloat162*)(A3out + b1 + N + col)     = l23;
                *(__nv_bfloat162*)(A3out + b1 + 2 * N + col) = h23;
            } else {
                float* p = C + (size_t)row * N + col;
                float* q = C + (size_t)(row + 8) * N + col;
                if (EPI == 1) { v0 += p[0]; v1 += p[1]; v2 += q[0]; v3 += q[1]; }
                *(float2*)p = make_float2(v0, v1);
                *(float2*)q = make_float2(v2, v3);
            }
        }
}

// ---------------- Tiled causal attention ----------------
__global__ void __launch_bounds__(256)
attn_kernel(const float* __restrict__ qkv,
            const int* __restrict__ mask,
            __nv_bfloat16* __restrict__ a3) {
    __shared__ float Qs[8][132];
    __shared__ float Kc[32][132];
    __shared__ float Vc[32][132];

    const int tid = threadIdx.x, lane = tid & 31, warp = tid >> 5;
    const int q0 = blockIdx.x * 8;
    const int h  = blockIdx.y;
    const int b  = blockIdx.z;
    const int q  = q0 + warp;
    const size_t base = (size_t)b * SEQ * TD;

    {
        int r = tid >> 5, c = (tid & 31) * 4;
        *(float4*)&Qs[r][c] = *(const float4*)&qkv[base + (size_t)(q0 + r) * TD + h * DH + c];
    }

    float m = -1e30f, l = 0.f;
    float4 o = make_float4(0.f, 0.f, 0.f, 0.f);
    const int jmax = q0 + 7;

    for (int j0 = 0; j0 <= jmax; j0 += 32) {
        __syncthreads();
        #pragma unroll
        for (int i = 0; i < 4; i++) {
            int idx = tid + i * 256;
            int r = idx >> 5, c = (idx & 31) * 4;
            const float* src = qkv + base + (size_t)(j0 + r) * TD + h * DH + c;
            *(float4*)&Kc[r][c] = *(const float4*)(src + D);
            *(float4*)&Vc[r][c] = *(const float4*)(src + 2 * D);
        }
        __syncthreads();

        const int j = j0 + lane;
        float s = -1e30f;
        if (j <= q) {
            float dot = 0.f;
            #pragma unroll 8
            for (int d = 0; d < DH; d += 4) {
                float4 kv = *(const float4*)&Kc[lane][d];
                float4 qv = *(const float4*)&Qs[warp][d];
                dot = fmaf(kv.x, qv.x, dot);
                dot = fmaf(kv.y, qv.y, dot);
                dot = fmaf(kv.z, qv.z, dot);
                dot = fmaf(kv.w, qv.w, dot);
            }
            s = dot * SCALE;
            if (mask[b * SEQ + j] == 0) s += NEGB;
        }

        float cmax = s;
        #pragma unroll
        for (int off = 16; off > 0; off >>= 1)
            cmax = fmaxf(cmax, __shfl_xor_sync(0xffffffffu, cmax, off));
        float newm = fmaxf(m, cmax);
        float corr = expf(m - newm);
        float p = expf(s - newm);
        float psum = p;
        #pragma unroll
        for (int off = 16; off > 0; off >>= 1)
            psum += __shfl_xor_sync(0xffffffffu, psum, off);
        l = l * corr + psum;
        o.x *= corr; o.y *= corr; o.z *= corr; o.w *= corr;

        #pragma unroll 8
        for (int jj = 0; jj < 32; jj++) {
            float pj = __shfl_sync(0xffffffffu, p, jj);
            float4 v = *(const float4*)&Vc[jj][lane * 4];
            o.x = fmaf(pj, v.x, o.x);
            o.y = fmaf(pj, v.y, o.y);
            o.z = fmaf(pj, v.z, o.z);
            o.w = fmaf(pj, v.w, o.w);
        }
        m = newm;
    }

    const float inv = 1.f / l;
    float v0 = o.x * inv, v1 = o.y * inv, v2 = o.z * inv, v3 = o.w * inv;
    size_t r3 = (size_t)(b * SEQ + q) * (3 * D);
    int col = h * DH + lane * 4;
    __nv_bfloat162 h01 = hi2(v0, v1), l01 = lo2(v0, v1, h01);
    __nv_bfloat162 h23 = hi2(v2, v3), l23 = lo2(v2, v3, h23);
    *(__nv_bfloat162*)(a3 + r3 + col)             = h01;
    *(__nv_bfloat162*)(a3 + r3 + col + 2)         = h23;
    *(__nv_bfloat162*)(a3 + r3 + D + col)         = l01;
    *(__nv_bfloat162*)(a3 + r3 + D + col + 2)     = l23;
    *(__nv_bfloat162*)(a3 + r3 + 2 * D + col)     = h01;
    *(__nv_bfloat162*)(a3 + r3 + 2 * D + col + 2) = h23;
}

// ---------------- Pool + head ----------------
__global__ void meanpool_kernel(const float* __restrict__ hs,
                                const int* __restrict__ mask,
                                float* __restrict__ mean) {
    int idx = blockIdx.x * blockDim.x + threadIdx.x;
    int b = idx / D;
    int d = idx % D;
    float acc = 0.f, msum = 0.f;
    const float* hb = hs + (size_t)b * SEQ * D + d;
    const int* mb = mask + b * SEQ;
    for (int s = 0; s < SEQ; s++) {
        float mf = (float)mb[s];
        acc = fmaf(mf, hb[(size_t)s * D], acc);
        msum += mf;
    }
    mean[idx] = acc / fmaxf(msum, 1e-9f);
}

__global__ void head1_kernel(const float* __restrict__ mean,
                             const float* __restrict__ Wc1,
                             const float* __restrict__ bc1,
                             float* __restrict__ t) {
    int idx = blockIdx.x * blockDim.x + threadIdx.x;
    int b = idx / D;
    int j = idx % D;
    float acc = bc1[j];
    const float* mb = mean + (size_t)b * D;
    for (int k = 0; k < D; k++)
        acc = fmaf(mb[k], Wc1[(size_t)k * D + j], acc);
    t[idx] = tanhf(acc);
}

__global__ void head2_kernel(const float* __restrict__ t,
                             const float* __restrict__ Wc2,
                             const float* __restrict__ bc2,
                             float* __restrict__ out) {
    __shared__ float red[256];
    __shared__ float logits[4];
    const int tid = threadIdx.x;
    float part[4] = {0.f, 0.f, 0.f, 0.f};
    for (int j = tid; j < D; j += 256) {
        float t0 = t[j], t1 = t[D + j];
        float w0 = Wc2[2 * j], w1 = Wc2[2 * j + 1];
        part[0] = fmaf(t0, w0, part[0]);
        part[1] = fmaf(t0, w1, part[1]);
        part[2] = fmaf(t1, w0, part[2]);
        part[3] = fmaf(t1, w1, part[3]);
    }
    for (int c = 0; c < 4; c++) {
        __syncthreads();
        red[tid] = part[c]; __syncthreads();
        for (int st = 128; st > 0; st >>= 1) {
            if (tid < st) red[tid] += red[tid + st];
            __syncthreads();
        }
        if (tid == 0) logits[c] = red[0] + bc2[c & 1];
    }
    __syncthreads();
    if (tid == 0) {
        for (int b = 0; b < BATCH; b++) {
            float l0 = logits[2 * b], l1 = logits[2 * b + 1];
            float m = fmaxf(l0, l1);
            float e0 = expf(l0 - m), e1 = expf(l1 - m);
            out[b] = e1 / (e0 + e1);
        }
    }
}

// ---------------- Launch ----------------
extern "C" void kernel_launch(void* const* d_in, const int* in_sizes, int n_in,
                              void* d_out, int out_size) {
    const int*   ids   = (const int*)d_in[0];
    const int*   amask = (const int*)d_in[1];
    const float* emb   = (const float*)d_in[2];
    const float* ln1_g = (const float*)d_in[3];
    const float* ln1_b = (const float*)d_in[4];
    const float* Wqkv  = (const float*)d_in[5];
    const float* Wo    = (const float*)d_in[6];
    const float* ln2_g = (const float*)d_in[7];
    const float* ln2_b = (const float*)d_in[8];
    const float* W1    = (const float*)d_in[9];
    const float* W2    = (const float*)d_in[10];
    const float* lnf_g = (const float*)d_in[11];
    const float* lnf_b = (const float*)d_in[12];
    const float* Wc1   = (const float*)d_in[13];
    const float* bc1   = (const float*)d_in[14];
    const float* Wc2   = (const float*)d_in[15];
    const float* bc2   = (const float*)d_in[16];
    float* out = (float*)d_out;

    float *x, *h, *qkv, *mean, *t;
    __nv_bfloat16 *a3s, *a3f, *wqkv3, *wo3, *w13, *w23;
    cudaGetSymbolAddress((void**)&x,    g_x);
    cudaGetSymbolAddress((void**)&h,    g_h);
    cudaGetSymbolAddress((void**)&qkv,  g_qkv);
    cudaGetSymbolAddress((void**)&mean, g_mean);
    cudaGetSymbolAddress((void**)&t,    g_t);
    cudaGetSymbolAddress((void**)&a3s,   g_a3s);
    cudaGetSymbolAddress((void**)&a3f,   g_a3f);
    cudaGetSymbolAddress((void**)&wqkv3, g_wqkv3);
    cudaGetSymbolAddress((void**)&wo3,   g_wo3);
    cudaGetSymbolAddress((void**)&w13,   g_w13);
    cudaGetSymbolAddress((void**)&w23,   g_w23);

    cudaFuncSetAttribute(bgemm_kernel<0>,
                         cudaFuncAttributeMaxDynamicSharedMemorySize, BG_SMEM);
    cudaFuncSetAttribute(bgemm_kernel<1>,
                         cudaFuncAttributeMaxDynamicSharedMemorySize, BG_SMEM);
    cudaFuncSetAttribute(bgemm_kernel<2>,
                         cudaFuncAttributeMaxDynamicSharedMemorySize, BG_SMEM);

    embed_kernel<<<(BS * D) / 256, 256>>>(ids, emb, x);

    for (int l = 0; l < LAYERS; l++) {
        // attention block
        ln_kernel<1><<<BS, 256>>>(x, ln1_g + (size_t)l * D, ln1_b + (size_t)l * D,
                                  nullptr, a3s);
        convw_kernel<<<dim3(TD / 32, D / 64), dim3(32, 8)>>>(
            Wqkv + (size_t)l * D * TD, wqkv3, D, TD);
        bgemm_kernel<0><<<dim3(BS / 128, TD / 128), 256, BG_SMEM>>>(
            a3s, wqkv3, qkv, nullptr, BS, TD, 3 * D);
        attn_kernel<<<dim3(SEQ / 8, H, BATCH), 256>>>(qkv, amask, a3s);
        convw_kernel<<<dim3(D / 32, D / 64), dim3(32, 8)>>>(
            Wo + (size_t)l * D * D, wo3, D, D);
        bgemm_kernel<1><<<dim3(BS / 128, D / 128), 256, BG_SMEM>>>(
            a3s, wo3, x, nullptr, BS, D, 3 * D);
        // mlp block
        ln_kernel<1><<<BS, 256>>>(x, ln2_g + (size_t)l * D, ln2_b + (size_t)l * D,
                                  nullptr, a3s);
        convw_kernel<<<dim3(FF / 32, D / 64), dim3(32, 8)>>>(
            W1 + (size_t)l * D * FF, w13, D, FF);
        bgemm_kernel<2><<<dim3(BS / 128, FF / 128), 256, BG_SMEM>>>(
            a3s, w13, nullptr, a3f, BS, FF, 3 * D);
        convw_kernel<<<dim3(D / 32, FF / 64), dim3(32, 8)>>>(
            W2 + (size_t)l * FF * D, w23, FF, D);
        bgemm_kernel<1><<<dim3(BS / 128, D / 128), 256, BG_SMEM>>>(
            a3f, w23, x, nullptr, BS, D, 3 * FF);
    }

    ln_kernel<0><<<BS, 256>>>(x, lnf_g, lnf_b, h, nullptr);
    meanpool_kernel<<<(BATCH * D) / 256, 256>>>(h, amask, mean);
    head1_kernel<<<(BATCH * D) / 256, 256>>>(mean, Wc1, bc1, t);
    head2_kernel<<<1, 256>>>(t, Wc2, bc2, out);
}

// round 8
// speedup vs baseline: 1.8165x; 1.1367x over previous
#include <cuda_runtime.h>
#include <cuda_bf16.h>
#include <math.h>
#include <stdint.h>

// ---------------- Problem constants ----------------
#define LAYERS 2
#define D      2048
#define H      16
#define FF     8192
#define BATCH  2
#define SEQ    1024
#define DH     128
#define TD     (3 * D)
#define BS     (BATCH * SEQ)
#define NEGB   (-1e9f)
#define SCALE  0.08838834764831845f

// ---------------- Scratch (static device globals) ----------------
__device__ float g_x   [BS * D];
__device__ float g_h   [BS * D];
__device__ float g_qkv [BS * TD];
__device__ float g_mean[BATCH * D];
__device__ float g_t   [BATCH * D];
// bf16x3 split buffers
__device__ __nv_bfloat16 g_a3s  [BS * 3 * D];
__device__ __nv_bfloat16 g_a3f  [BS * 3 * FF];
__device__ __nv_bfloat16 g_wqkv3[TD * 3 * D];
__device__ __nv_bfloat16 g_wo3  [D  * 3 * D];
__device__ __nv_bfloat16 g_w13  [FF * 3 * D];
__device__ __nv_bfloat16 g_w23  [D  * 3 * FF];

// ---------------- Embedding gather ----------------
__global__ void embed_kernel(const int* __restrict__ ids,
                             const float* __restrict__ emb,
                             float* __restrict__ x) {
    int idx = blockIdx.x * blockDim.x + threadIdx.x;
    int tok = ids[idx / D];
    x[idx] = emb[(size_t)tok * D + (idx % D)];
}

// ---------------- LayerNorm; SPLIT=1 writes bf16x3 (K=D), else fp32 ----------------
template<int SPLIT>
__global__ void ln_kernel(const float* __restrict__ x,
                          const float* __restrict__ g,
                          const float* __restrict__ b,
                          float* __restrict__ outf,
                          __nv_bfloat16* __restrict__ out3) {
    __shared__ float row[D];
    __shared__ float red[256];
    const int tid = threadIdx.x;
    const float* xr = x + (size_t)blockIdx.x * D;

    float s = 0.f;
    for (int i = tid; i < D; i += 256) { float v = xr[i]; row[i] = v; s += v; }
    red[tid] = s; __syncthreads();
    for (int st = 128; st > 0; st >>= 1) {
        if (tid < st) red[tid] += red[tid + st];
        __syncthreads();
    }
    const float mean = red[0] * (1.0f / D);
    __syncthreads();

    float s2 = 0.f;
    for (int i = tid; i < D; i += 256) { float v = row[i] - mean; s2 += v * v; }
    red[tid] = s2; __syncthreads();
    for (int st = 128; st > 0; st >>= 1) {
        if (tid < st) red[tid] += red[tid + st];
        __syncthreads();
    }
    const float rstd = rsqrtf(red[0] * (1.0f / D) + 1e-5f);

    if (SPLIT) {
        __nv_bfloat16* o3 = out3 + (size_t)blockIdx.x * (3 * D);
        for (int i = tid; i < D; i += 256) {
            float v = (row[i] - mean) * rstd * g[i] + b[i];
            __nv_bfloat16 hi = __float2bfloat16(v);
            __nv_bfloat16 lo = __float2bfloat16(v - __bfloat162float(hi));
            o3[i]         = hi;
            o3[D + i]     = lo;
            o3[2 * D + i] = hi;
        }
    } else {
        float* orow = outf + (size_t)blockIdx.x * D;
        for (int i = tid; i < D; i += 256)
            orow[i] = (row[i] - mean) * rstd * g[i] + b[i];
    }
}

// ---------------- Split-convert + transpose weights: W[K,N] fp32 -> Wt3[N,3K] bf16 ----------------
__global__ void convw_kernel(const float* __restrict__ W,
                             __nv_bfloat16* __restrict__ Wt3, int K, int N) {
    __shared__ float tile[64][33];
    int n0 = blockIdx.x * 32, k0 = blockIdx.y * 64;
    int tx = threadIdx.x, ty = threadIdx.y;   // (32, 8)
    #pragma unroll
    for (int i = 0; i < 64; i += 8)
        tile[ty + i][tx] = W[(size_t)(k0 + ty + i) * N + n0 + tx];
    __syncthreads();
    #pragma unroll
    for (int i = 0; i < 32; i += 8) {
        int nn = ty + i;
        int n = n0 + nn;
        float x0 = tile[2 * tx][nn];
        float x1 = tile[2 * tx + 1][nn];
        __nv_bfloat162 hi, lo;
        hi.x = __float2bfloat16(x0);
        hi.y = __float2bfloat16(x1);
        lo.x = __float2bfloat16(x0 - __bfloat162float(hi.x));
        lo.y = __float2bfloat16(x1 - __bfloat162float(hi.y));
        size_t base = (size_t)n * (3 * K);
        int k = k0 + 2 * tx;
        *(__nv_bfloat162*)(Wt3 + base + k)         = hi;
        *(__nv_bfloat162*)(Wt3 + base + K + k)     = hi;
        *(__nv_bfloat162*)(Wt3 + base + 2 * K + k) = lo;
    }
}

// ========= mma.sync bf16 GEMM: BK=32, 4 stages x 16KB, 2 CTAs/SM =========
#define BG_STAGE  16384
#define BG_SMEM   (4 * BG_STAGE)        // 64KB -> 2 CTAs/SM

__device__ __forceinline__ unsigned swz(unsigned o) { return o ^ ((o >> 3) & 0x70); }

__device__ __forceinline__ void ldsm4(unsigned addr, unsigned& r0, unsigned& r1,
                                      unsigned& r2, unsigned& r3) {
    asm volatile("ldmatrix.sync.aligned.m8n8.x4.shared.b16 {%0,%1,%2,%3}, [%4];\n"
                 : "=r"(r0), "=r"(r1), "=r"(r2), "=r"(r3) : "r"(addr));
}
__device__ __forceinline__ void mma16816(float* c, unsigned a0, unsigned a1,
                                         unsigned a2, unsigned a3,
                                         unsigned b0, unsigned b1) {
    asm volatile(
        "mma.sync.aligned.m16n8k16.row.col.f32.bf16.bf16.f32 "
        "{%0,%1,%2,%3},{%4,%5,%6,%7},{%8,%9},{%0,%1,%2,%3};\n"
        : "+f"(c[0]), "+f"(c[1]), "+f"(c[2]), "+f"(c[3])
        : "r"(a0), "r"(a1), "r"(a2), "r"(a3), "r"(b0), "r"(b1));
}
__device__ __forceinline__ void cpasync16(unsigned saddr, const void* g) {
    asm volatile("cp.async.cg.shared.global [%0], [%1], 16;\n" :: "r"(saddr), "l"(g));
}

__device__ __forceinline__ void load_tile(const __nv_bfloat16* gbase, unsigned sbase,
                                          int ld, int k0) {
    int t = threadIdx.x;
    #pragma unroll
    for (int i = 0; i < 2; i++) {
        int c = t + i * 256;
        int row = c >> 2, seg = c & 3;
        unsigned so = swz((unsigned)((row >> 1) * 128 + (row & 1) * 64 + seg * 16));
        cpasync16(sbase + so, gbase + (size_t)row * ld + k0 + seg * 8);
    }
}

__device__ __forceinline__ void ldsm_frags(const unsigned aA[4], const unsigned bA[2],
                                           unsigned off,
                                           unsigned fa[4][4], unsigned fb[2][4]) {
    #pragma unroll
    for (int mi = 0; mi < 4; mi++)
        ldsm4(aA[mi] ^ off, fa[mi][0], fa[mi][1], fa[mi][2], fa[mi][3]);
    #pragma unroll
    for (int np = 0; np < 2; np++)
        ldsm4(bA[np] ^ off, fb[np][0], fb[np][1], fb[np][2], fb[np][3]);
}

__device__ __forceinline__ void mma_tile(float acc[4][4][4],
                                         unsigned fa[4][4], unsigned fb[2][4]) {
    #pragma unroll
    for (int mi = 0; mi < 4; mi++)
        #pragma unroll
        for (int ni = 0; ni < 4; ni++) {
            unsigned b0 = fb[ni >> 1][ni & 1];
            unsigned b1 = fb[ni >> 1][2 + (ni & 1)];
            mma16816(acc[mi][ni], fa[mi][0], fa[mi][1], fa[mi][2], fa[mi][3], b0, b1);
        }
}

__device__ __forceinline__ float gelu_f(float xx) {
    return 0.5f * xx * (1.0f + tanhf(0.7978845608028654f *
                                     (xx + 0.044715f * xx * xx * xx)));
}
__device__ __forceinline__ __nv_bfloat162 hi2(float a, float b) {
    __nv_bfloat162 r;
    r.x = __float2bfloat16(a); r.y = __float2bfloat16(b);
    return r;
}
__device__ __forceinline__ __nv_bfloat162 lo2(float a, float b, __nv_bfloat162 h) {
    __nv_bfloat162 r;
    r.x = __float2bfloat16(a - __bfloat162float(h.x));
    r.y = __float2bfloat16(b - __bfloat162float(h.y));
    return r;
}

template<int EPI>
__global__ void __launch_bounds__(256, 2)
bgemm_kernel(const __nv_bfloat16* __restrict__ A,
             const __nv_bfloat16* __restrict__ Bt,
             float* __restrict__ C,
             __nv_bfloat16* __restrict__ A3out,
             int M, int N, int K3) {
    extern __shared__ __align__(128) char smem[];
    unsigned sbase = (unsigned)__cvta_generic_to_shared(smem);

    const int tid = threadIdx.x, lane = tid & 31, warp = tid >> 5;
    const int warpM = warp & 1, warpN = warp >> 1;
    const int rowBase = blockIdx.x * 128;
    const int colBase = blockIdx.y * 128;
    const __nv_bfloat16* Ab = A  + (size_t)rowBase * K3;
    const __nv_bfloat16* Bb = Bt + (size_t)colBase * K3;

    float acc[4][4][4];
    #pragma unroll
    for (int i = 0; i < 4; i++)
        #pragma unroll
        for (int j = 0; j < 4; j++)
            #pragma unroll
            for (int r = 0; r < 4; r++) acc[i][j][r] = 0.f;

    const int KT = K3 >> 5;
    #pragma unroll
    for (int s = 0; s < 3; s++) {
        unsigned st = sbase + s * BG_STAGE;
        load_tile(Ab, st, K3, s << 5);
        load_tile(Bb, st + 8192, K3, s << 5);
        asm volatile("cp.async.commit_group;\n");
    }

    unsigned aAB[4], bAB[2];
    #pragma unroll
    for (int mi = 0; mi < 4; mi++) {
        int row = warpM * 64 + mi * 16 + (lane & 15);
        aAB[mi] = swz((unsigned)((row >> 1) * 128 + (row & 1) * 64 + (lane >> 4) * 16));
    }
    #pragma unroll
    for (int np = 0; np < 2; np++) {
        int rown = warpN * 32 + np * 16 + (lane & 15);
        bAB[np] = 8192u + swz((unsigned)((rown >> 1) * 128 + (rown & 1) * 64 + (lane >> 4) * 16));
    }

    unsigned fa0[4][4], fb0[2][4], fa1[4][4], fb1[2][4];

    for (int kt = 0; kt < KT; kt++) {
        asm volatile("cp.async.wait_group 2;\n");
        __syncthreads();

        unsigned stg = sbase + (unsigned)(kt & 3) * BG_STAGE;
        unsigned aA[4] = { stg + aAB[0], stg + aAB[1], stg + aAB[2], stg + aAB[3] };
        unsigned bA[2] = { stg + bAB[0], stg + bAB[1] };

        ldsm_frags(aA, bA, 0, fa0, fb0);

        const int next = kt + 3;
        if (next < KT) {
            unsigned ns = sbase + (unsigned)(next & 3) * BG_STAGE;
            load_tile(Ab, ns, K3, next << 5);
            load_tile(Bb, ns + 8192, K3, next << 5);
        }
        asm volatile("cp.async.commit_group;\n");

        ldsm_frags(aA, bA, 32, fa1, fb1);
        mma_tile(acc, fa0, fb0);
        mma_tile(acc, fa1, fb1);
    }

    #pragma unroll
    for (int mi = 0; mi < 4; mi++)
        #pragma unroll
        for (int ni = 0; ni < 4; ni++) {
            int row = rowBase + warpM * 64 + mi * 16 + (lane >> 2);
            int col = colBase + warpN * 32 + ni * 8 + 2 * (lane & 3);
            float v0 = acc[mi][ni][0], v1 = acc[mi][ni][1];
            float v2 = acc[mi][ni][2], v3 = acc[mi][ni][3];
            if (EPI == 2) {
                v0 = gelu_f(v0); v1 = gelu_f(v1);
                v2 = gelu_f(v2); v3 = gelu_f(v3);
                size_t b0 = (size_t)row * (3 * (size_t)N);
                size_t b1 = (size_t)(row + 8) * (3 * (size_t)N);
                __nv_bfloat162 h01 = hi2(v0, v1), l01 = lo2(v0, v1, h01);
                __nv_bfloat162 h23 = hi2(v2, v3), l23 = lo2(v2, v3, h23);
                *(__nv_bfloat162*)(A3out + b0 + col)         = h01;
                *(__nv_bfloat162*)(A3out + b0 + N + col)     = l01;
                *(__nv_bfloat162*)(A3out + b0 + 2 * N + col) = h01;
                *(__nv_bfloat162*)(A3out + b1 + col)         = h23;
                *(__nv_bfloat162*)(A3out + b1 + N + col)     = l23;
                *(__nv_bfloat162*)(A3out + b1 + 2 * N + col) = h23;
            } else {
                float* p = C + (size_t)row * N + col;
                float* q = C + (size_t)(row + 8) * N + col;
                if (EPI == 1) { v0 += p[0]; v1 += p[1]; v2 += q[0]; v3 += q[1]; }
                *(float2*)p = make_float2(v0, v1);
                *(float2*)q = make_float2(v2, v3);
            }
        }
}

// ---------------- Tiled causal attention: 32 q-rows per block ----------------
// 8 warps x 4 q-rows; K/V streamed in 32-key chunks shared by all 32 rows.
// Smem (dynamic): Qs[32][128] | Kc[32][132] | Vc[32][128]  = 49664 bytes
#define ATT_SMEM ((32 * 128 + 32 * 132 + 32 * 128) * 4)

__global__ void __launch_bounds__(256)
attn_kernel(const float* __restrict__ qkv,
            const int* __restrict__ mask,
            __nv_bfloat16* __restrict__ a3) {
    extern __shared__ float asmem[];
    float* Qs = asmem;                 // [32][128]
    float* Kc = asmem + 32 * 128;      // [32][132]
    float* Vc = Kc + 32 * 132;         // [32][128]

    const int tid = threadIdx.x, lane = tid & 31, warp = tid >> 5;
    const int q0 = blockIdx.x * 32;
    const int h  = blockIdx.y;
    const int b  = blockIdx.z;
    const size_t base = (size_t)b * SEQ * TD;

    // load 32 q rows (1024 float4 by 256 threads)
    #pragma unroll
    for (int i = 0; i < 4; i++) {
        int idx = tid + i * 256;
        int r = idx >> 5, c = (idx & 31) * 4;
        *(float4*)&Qs[r * 128 + c] =
            *(const float4*)&qkv[base + (size_t)(q0 + r) * TD + h * DH + c];
    }

    const int qr0 = q0 + warp * 4;      // this warp's first q row
    float m[4] = {-1e30f, -1e30f, -1e30f, -1e30f};
    float l[4] = {0.f, 0.f, 0.f, 0.f};
    float4 o[4];
    #pragma unroll
    for (int r = 0; r < 4; r++) o[r] = make_float4(0.f, 0.f, 0.f, 0.f);

    const int jmax = q0 + 31;
    for (int j0 = 0; j0 <= jmax; j0 += 32) {
        __syncthreads();
        #pragma unroll
        for (int i = 0; i < 4; i++) {
            int idx = tid + i * 256;
            int r = idx >> 5, c = (idx & 31) * 4;
            const float* src = qkv + base + (size_t)(j0 + r) * TD + h * DH + c;
            *(float4*)&Kc[r * 132 + c] = *(const float4*)(src + D);
            *(float4*)&Vc[r * 128 + c] = *(const float4*)(src + 2 * D);
        }
        __syncthreads();

        const int j = j0 + lane;
        const float mbias = (mask[b * SEQ + j] == 0) ? NEGB : 0.f;

        float dot[4] = {0.f, 0.f, 0.f, 0.f};
        #pragma unroll 4
        for (int d = 0; d < DH; d += 4) {
            float4 kv = *(const float4*)&Kc[lane * 132 + d];
            #pragma unroll
            for (int r = 0; r < 4; r++) {
                float4 qv = *(const float4*)&Qs[(warp * 4 + r) * 128 + d];
                dot[r] = fmaf(kv.x, qv.x, dot[r]);
                dot[r] = fmaf(kv.y, qv.y, dot[r]);
                dot[r] = fmaf(kv.z, qv.z, dot[r]);
                dot[r] = fmaf(kv.w, qv.w, dot[r]);
            }
        }

        float p[4];
        #pragma unroll
        for (int r = 0; r < 4; r++) {
            float s = (j <= qr0 + r) ? (dot[r] * SCALE + mbias) : -1e30f;
            float cmax = s;
            #pragma unroll
            for (int off = 16; off > 0; off >>= 1)
                cmax = fmaxf(cmax, __shfl_xor_sync(0xffffffffu, cmax, off));
            float newm = fmaxf(m[r], cmax);
            float corr = expf(m[r] - newm);
            p[r] = expf(s - newm);
            float psum = p[r];
            #pragma unroll
            for (int off = 16; off > 0; off >>= 1)
                psum += __shfl_xor_sync(0xffffffffu, psum, off);
            l[r] = l[r] * corr + psum;
            o[r].x *= corr; o[r].y *= corr; o[r].z *= corr; o[r].w *= corr;
            m[r] = newm;
        }

        #pragma unroll 4
        for (int jj = 0; jj < 32; jj++) {
            float4 v = *(const float4*)&Vc[jj * 128 + lane * 4];
            #pragma unroll
            for (int r = 0; r < 4; r++) {
                float pj = __shfl_sync(0xffffffffu, p[r], jj);
                o[r].x = fmaf(pj, v.x, o[r].x);
                o[r].y = fmaf(pj, v.y, o[r].y);
                o[r].z = fmaf(pj, v.z, o[r].z);
                o[r].w = fmaf(pj, v.w, o[r].w);
            }
        }
    }

    const int col = h * DH + lane * 4;
    #pragma unroll
    for (int r = 0; r < 4; r++) {
        const float inv = 1.f / l[r];
        float v0 = o[r].x * inv, v1 = o[r].y * inv;
        float v2 = o[r].z * inv, v3 = o[r].w * inv;
        size_t r3 = (size_t)(b * SEQ + qr0 + r) * (3 * D);
        __nv_bfloat162 h01 = hi2(v0, v1), l01 = lo2(v0, v1, h01);
        __nv_bfloat162 h23 = hi2(v2, v3), l23 = lo2(v2, v3, h23);
        *(__nv_bfloat162*)(a3 + r3 + col)             = h01;
        *(__nv_bfloat162*)(a3 + r3 + col + 2)         = h23;
        *(__nv_bfloat162*)(a3 + r3 + D + col)         = l01;
        *(__nv_bfloat162*)(a3 + r3 + D + col + 2)     = l23;
        *(__nv_bfloat162*)(a3 + r3 + 2 * D + col)     = h01;
        *(__nv_bfloat162*)(a3 + r3 + 2 * D + col + 2) = h23;
    }
}

// ---------------- Pool + head ----------------
__global__ void meanpool_kernel(const float* __restrict__ hs,
                                const int* __restrict__ mask,
                                float* __restrict__ mean) {
    int idx = blockIdx.x * blockDim.x + threadIdx.x;
    int b = idx / D;
    int d = idx % D;
    float acc = 0.f, msum = 0.f;
    const float* hb = hs + (size_t)b * SEQ * D + d;
    const int* mb = mask + b * SEQ;
    for (int s = 0; s < SEQ; s++) {
        float mf = (float)mb[s];
        acc = fmaf(mf, hb[(size_t)s * D], acc);
        msum += mf;
    }
    mean[idx] = acc / fmaxf(msum, 1e-9f);
}

__global__ void head1_kernel(const float* __restrict__ mean,
                             const float* __restrict__ Wc1,
                             const float* __restrict__ bc1,
                             float* __restrict__ t) {
    int idx = blockIdx.x * blockDim.x + threadIdx.x;
    int b = idx / D;
    int j = idx % D;
    float acc = bc1[j];
    const float* mb = mean + (size_t)b * D;
    for (int k = 0; k < D; k++)
        acc = fmaf(mb[k], Wc1[(size_t)k * D + j], acc);
    t[idx] = tanhf(acc);
}

__global__ void head2_kernel(const float* __restrict__ t,
                             const float* __restrict__ Wc2,
                             const float* __restrict__ bc2,
                             float* __restrict__ out) {
    __shared__ float red[256];
    __shared__ float logits[4];
    const int tid = threadIdx.x;
    float part[4] = {0.f, 0.f, 0.f, 0.f};
    for (int j = tid; j < D; j += 256) {
        float t0 = t[j], t1 = t[D + j];
        float w0 = Wc2[2 * j], w1 = Wc2[2 * j + 1];
        part[0] = fmaf(t0, w0, part[0]);
        part[1] = fmaf(t0, w1, part[1]);
        part[2] = fmaf(t1, w0, part[2]);
        part[3] = fmaf(t1, w1, part[3]);
    }
    for (int c = 0; c < 4; c++) {
        __syncthreads();
        red[tid] = part[c]; __syncthreads();
        for (int st = 128; st > 0; st >>= 1) {
            if (tid < st) red[tid] += red[tid + st];
            __syncthreads();
        }
        if (tid == 0) logits[c] = red[0] + bc2[c & 1];
    }
    __syncthreads();
    if (tid == 0) {
        for (int b = 0; b < BATCH; b++) {
            float l0 = logits[2 * b], l1 = logits[2 * b + 1];
            float m = fmaxf(l0, l1);
            float e0 = expf(l0 - m), e1 = expf(l1 - m);
            out[b] = e1 / (e0 + e1);
        }
    }
}

// ---------------- Launch ----------------
extern "C" void kernel_launch(void* const* d_in, const int* in_sizes, int n_in,
                              void* d_out, int out_size) {
    const int*   ids   = (const int*)d_in[0];
    const int*   amask = (const int*)d_in[1];
    const float* emb   = (const float*)d_in[2];
    const float* ln1_g = (const float*)d_in[3];
    const float* ln1_b = (const float*)d_in[4];
    const float* Wqkv  = (const float*)d_in[5];
    const float* Wo    = (const float*)d_in[6];
    const float* ln2_g = (const float*)d_in[7];
    const float* ln2_b = (const float*)d_in[8];
    const float* W1    = (const float*)d_in[9];
    const float* W2    = (const float*)d_in[10];
    const float* lnf_g = (const float*)d_in[11];
    const float* lnf_b = (const float*)d_in[12];
    const float* Wc1   = (const float*)d_in[13];
    const float* bc1   = (const float*)d_in[14];
    const float* Wc2   = (const float*)d_in[15];
    const float* bc2   = (const float*)d_in[16];
    float* out = (float*)d_out;

    float *x, *h, *qkv, *mean, *t;
    __nv_bfloat16 *a3s, *a3f, *wqkv3, *wo3, *w13, *w23;
    cudaGetSymbolAddress((void**)&x,    g_x);
    cudaGetSymbolAddress((void**)&h,    g_h);
    cudaGetSymbolAddress((void**)&qkv,  g_qkv);
    cudaGetSymbolAddress((void**)&mean, g_mean);
    cudaGetSymbolAddress((void**)&t,    g_t);
    cudaGetSymbolAddress((void**)&a3s,   g_a3s);
    cudaGetSymbolAddress((void**)&a3f,   g_a3f);
    cudaGetSymbolAddress((void**)&wqkv3, g_wqkv3);
    cudaGetSymbolAddress((void**)&wo3,   g_wo3);
    cudaGetSymbolAddress((void**)&w13,   g_w13);
    cudaGetSymbolAddress((void**)&w23,   g_w23);

    cudaFuncSetAttribute(bgemm_kernel<0>,
                         cudaFuncAttributeMaxDynamicSharedMemorySize, BG_SMEM);
    cudaFuncSetAttribute(bgemm_kernel<1>,
                         cudaFuncAttributeMaxDynamicSharedMemorySize, BG_SMEM);
    cudaFuncSetAttribute(bgemm_kernel<2>,
                         cudaFuncAttributeMaxDynamicSharedMemorySize, BG_SMEM);
    cudaFuncSetAttribute(attn_kernel,
                         cudaFuncAttributeMaxDynamicSharedMemorySize, ATT_SMEM);

    embed_kernel<<<(BS * D) / 256, 256>>>(ids, emb, x);

    for (int l = 0; l < LAYERS; l++) {
        // attention block
        ln_kernel<1><<<BS, 256>>>(x, ln1_g + (size_t)l * D, ln1_b + (size_t)l * D,
                                  nullptr, a3s);
        convw_kernel<<<dim3(TD / 32, D / 64), dim3(32, 8)>>>(
            Wqkv + (size_t)l * D * TD, wqkv3, D, TD);
        bgemm_kernel<0><<<dim3(BS / 128, TD / 128), 256, BG_SMEM>>>(
            a3s, wqkv3, qkv, nullptr, BS, TD, 3 * D);
        attn_kernel<<<dim3(SEQ / 32, H, BATCH), 256, ATT_SMEM>>>(qkv, amask, a3s);
        convw_kernel<<<dim3(D / 32, D / 64), dim3(32, 8)>>>(
            Wo + (size_t)l * D * D, wo3, D, D);
        bgemm_kernel<1><<<dim3(BS / 128, D / 128), 256, BG_SMEM>>>(
            a3s, wo3, x, nullptr, BS, D, 3 * D);
        // mlp block
        ln_kernel<1><<<BS, 256>>>(x, ln2_g + (size_t)l * D, ln2_b + (size_t)l * D,
                                  nullptr, a3s);
        convw_kernel<<<dim3(FF / 32, D / 64), dim3(32, 8)>>>(
            W1 + (size_t)l * D * FF, w13, D, FF);
        bgemm_kernel<2><<<dim3(BS / 128, FF / 128), 256, BG_SMEM>>>(
            a3s, w13, nullptr, a3f, BS, FF, 3 * D);
        convw_kernel<<<dim3(D / 32, FF / 64), dim3(32, 8)>>>(
            W2 + (size_t)l * FF * D, w23, FF, D);
        bgemm_kernel<1><<<dim3(BS / 128, D / 128), 256, BG_SMEM>>>(
            a3f, w23, x, nullptr, BS, D, 3 * FF);
    }

    ln_kernel<0><<<BS, 256>>>(x, lnf_g, lnf_b, h, nullptr);
    meanpool_kernel<<<(BATCH * D) / 256, 256>>>(h, amask, mean);
    head1_kernel<<<(BATCH * D) / 256, 256>>>(mean, Wc1, bc1, t);
    head2_kernel<<<1, 256>>>(t, Wc2, bc2, out);
}

// round 9
// speedup vs baseline: 1.9300x; 1.0625x over previous
#include <cuda_runtime.h>
#include <cuda_bf16.h>
#include <math.h>
#include <stdint.h>

// ---------------- Problem constants ----------------
#define LAYERS 2
#define D      2048
#define H      16
#define FF     8192
#define BATCH  2
#define SEQ    1024
#define DH     128
#define TD     (3 * D)
#define BS     (BATCH * SEQ)
#define NEGB   (-1e9f)
#define SCALE  0.08838834764831845f

// ---------------- Scratch (static device globals) ----------------
__device__ float g_x   [BS * D];
__device__ float g_h   [BS * D];
__device__ float g_qkv [BS * TD];
__device__ float g_mean[BATCH * D];
__device__ float g_t   [BATCH * D];
// bf16x3 split buffers
__device__ __nv_bfloat16 g_a3s  [BS * 3 * D];
__device__ __nv_bfloat16 g_a3f  [BS * 3 * FF];
__device__ __nv_bfloat16 g_wqkv3[TD * 3 * D];
__device__ __nv_bfloat16 g_wo3  [D  * 3 * D];
__device__ __nv_bfloat16 g_w13  [FF * 3 * D];
__device__ __nv_bfloat16 g_w23  [D  * 3 * FF];

// ---------------- Embedding gather ----------------
__global__ void embed_kernel(const int* __restrict__ ids,
                             const float* __restrict__ emb,
                             float* __restrict__ x) {
    int idx = blockIdx.x * blockDim.x + threadIdx.x;
    int tok = ids[idx / D];
    x[idx] = emb[(size_t)tok * D + (idx % D)];
}

// ---------------- LayerNorm; SPLIT=1 writes bf16x3 (K=D), else fp32 ----------------
template<int SPLIT>
__global__ void ln_kernel(const float* __restrict__ x,
                          const float* __restrict__ g,
                          const float* __restrict__ b,
                          float* __restrict__ outf,
                          __nv_bfloat16* __restrict__ out3) {
    __shared__ float row[D];
    __shared__ float red[256];
    const int tid = threadIdx.x;
    const float* xr = x + (size_t)blockIdx.x * D;

    float s = 0.f;
    for (int i = tid; i < D; i += 256) { float v = xr[i]; row[i] = v; s += v; }
    red[tid] = s; __syncthreads();
    for (int st = 128; st > 0; st >>= 1) {
        if (tid < st) red[tid] += red[tid + st];
        __syncthreads();
    }
    const float mean = red[0] * (1.0f / D);
    __syncthreads();

    float s2 = 0.f;
    for (int i = tid; i < D; i += 256) { float v = row[i] - mean; s2 += v * v; }
    red[tid] = s2; __syncthreads();
    for (int st = 128; st > 0; st >>= 1) {
        if (tid < st) red[tid] += red[tid + st];
        __syncthreads();
    }
    const float rstd = rsqrtf(red[0] * (1.0f / D) + 1e-5f);

    if (SPLIT) {
        __nv_bfloat16* o3 = out3 + (size_t)blockIdx.x * (3 * D);
        for (int i = tid; i < D; i += 256) {
            float v = (row[i] - mean) * rstd * g[i] + b[i];
            __nv_bfloat16 hi = __float2bfloat16(v);
            __nv_bfloat16 lo = __float2bfloat16(v - __bfloat162float(hi));
            o3[i]         = hi;
            o3[D + i]     = lo;
            o3[2 * D + i] = hi;
        }
    } else {
        float* orow = outf + (size_t)blockIdx.x * D;
        for (int i = tid; i < D; i += 256)
            orow[i] = (row[i] - mean) * rstd * g[i] + b[i];
    }
}

// ---------------- Split-convert + transpose weights: W[K,N] fp32 -> Wt3[N,3K] bf16 ----------------
__global__ void convw_kernel(const float* __restrict__ W,
                             __nv_bfloat16* __restrict__ Wt3, int K, int N) {
    __shared__ float tile[64][33];
    int n0 = blockIdx.x * 32, k0 = blockIdx.y * 64;
    int tx = threadIdx.x, ty = threadIdx.y;   // (32, 8)
    #pragma unroll
    for (int i = 0; i < 64; i += 8)
        tile[ty + i][tx] = W[(size_t)(k0 + ty + i) * N + n0 + tx];
    __syncthreads();
    #pragma unroll
    for (int i = 0; i < 32; i += 8) {
        int nn = ty + i;
        int n = n0 + nn;
        float x0 = tile[2 * tx][nn];
        float x1 = tile[2 * tx + 1][nn];
        __nv_bfloat162 hi, lo;
        hi.x = __float2bfloat16(x0);
        hi.y = __float2bfloat16(x1);
        lo.x = __float2bfloat16(x0 - __bfloat162float(hi.x));
        lo.y = __float2bfloat16(x1 - __bfloat162float(hi.y));
        size_t base = (size_t)n * (3 * K);
        int k = k0 + 2 * tx;
        *(__nv_bfloat162*)(Wt3 + base + k)         = hi;
        *(__nv_bfloat162*)(Wt3 + base + K + k)     = hi;
        *(__nv_bfloat162*)(Wt3 + base + 2 * K + k) = lo;
    }
}

// ========= mma.sync bf16 GEMM: 128 threads, warp tile 64x64, BK=32, 4 stages =========
#define BG_STAGE  16384
#define BG_SMEM   (4 * BG_STAGE)        // 64KB -> 2 CTAs/SM

__device__ __forceinline__ unsigned swz(unsigned o) { return o ^ ((o >> 3) & 0x70); }

__device__ __forceinline__ void ldsm4(unsigned addr, unsigned& r0, unsigned& r1,
                                      unsigned& r2, unsigned& r3) {
    asm volatile("ldmatrix.sync.aligned.m8n8.x4.shared.b16 {%0,%1,%2,%3}, [%4];\n"
                 : "=r"(r0), "=r"(r1), "=r"(r2), "=r"(r3) : "r"(addr));
}
__device__ __forceinline__ void mma16816(float* c, unsigned a0, unsigned a1,
                                         unsigned a2, unsigned a3,
                                         unsigned b0, unsigned b1) {
    asm volatile(
        "mma.sync.aligned.m16n8k16.row.col.f32.bf16.bf16.f32 "
        "{%0,%1,%2,%3},{%4,%5,%6,%7},{%8,%9},{%0,%1,%2,%3};\n"
        : "+f"(c[0]), "+f"(c[1]), "+f"(c[2]), "+f"(c[3])
        : "r"(a0), "r"(a1), "r"(a2), "r"(a3), "r"(b0), "r"(b1));
}
__device__ __forceinline__ void cpasync16(unsigned saddr, const void* g) {
    asm volatile("cp.async.cg.shared.global [%0], [%1], 16;\n" :: "r"(saddr), "l"(g));
}

// load 128-row x 32-col bf16 tile (paired-row swizzled, 8KB) with 128 threads
__device__ __forceinline__ void load_tile(const __nv_bfloat16* gbase, unsigned sbase,
                                          int ld, int k0) {
    int t = threadIdx.x;
    #pragma unroll
    for (int i = 0; i < 4; i++) {
        int c = t + i * 128;              // 0..511
        int row = c >> 2, seg = c & 3;
        unsigned so = swz((unsigned)((row >> 1) * 128 + (row & 1) * 64 + seg * 16));
        cpasync16(sbase + so, gbase + (size_t)row * ld + k0 + seg * 8);
    }
}

// frag fetch: ks offset (bit 5 only) applied via XOR on the swizzled base
__device__ __forceinline__ void ldsm_frags(const unsigned aA[4], const unsigned bA[4],
                                           unsigned off,
                                           unsigned fa[4][4], unsigned fb[4][4]) {
    #pragma unroll
    for (int mi = 0; mi < 4; mi++)
        ldsm4(aA[mi] ^ off, fa[mi][0], fa[mi][1], fa[mi][2], fa[mi][3]);
    #pragma unroll
    for (int np = 0; np < 4; np++)
        ldsm4(bA[np] ^ off, fb[np][0], fb[np][1], fb[np][2], fb[np][3]);
}

__device__ __forceinline__ void mma_tile(float acc[4][8][4],
                                         unsigned fa[4][4], unsigned fb[4][4]) {
    #pragma unroll
    for (int mi = 0; mi < 4; mi++)
        #pragma unroll
        for (int ni = 0; ni < 8; ni++) {
            unsigned b0 = fb[ni >> 1][ni & 1];
            unsigned b1 = fb[ni >> 1][2 + (ni & 1)];
            mma16816(acc[mi][ni], fa[mi][0], fa[mi][1], fa[mi][2], fa[mi][3], b0, b1);
        }
}

__device__ __forceinline__ float gelu_f(float xx) {
    return 0.5f * xx * (1.0f + tanhf(0.7978845608028654f *
                                     (xx + 0.044715f * xx * xx * xx)));
}
__device__ __forceinline__ __nv_bfloat162 hi2(float a, float b) {
    __nv_bfloat162 r;
    r.x = __float2bfloat16(a); r.y = __float2bfloat16(b);
    return r;
}
__device__ __forceinline__ __nv_bfloat162 lo2(float a, float b, __nv_bfloat162 h) {
    __nv_bfloat162 r;
    r.x = __float2bfloat16(a - __bfloat162float(h.x));
    r.y = __float2bfloat16(b - __bfloat162float(h.y));
    return r;
}

template<int EPI>
__global__ void __launch_bounds__(128, 2)
bgemm_kernel(const __nv_bfloat16* __restrict__ A,
             const __nv_bfloat16* __restrict__ Bt,
             float* __restrict__ C,
             __nv_bfloat16* __restrict__ A3out,
             int M, int N, int K3) {
    extern __shared__ __align__(128) char smem[];
    unsigned sbase = (unsigned)__cvta_generic_to_shared(smem);

    const int tid = threadIdx.x, lane = tid & 31, warp = tid >> 5;  // 4 warps
    const int warpM = warp & 1, warpN = warp >> 1;                  // 2x2
    const int rowBase = blockIdx.x * 128;
    const int colBase = blockIdx.y * 128;
    const __nv_bfloat16* Ab = A  + (size_t)rowBase * K3;
    const __nv_bfloat16* Bb = Bt + (size_t)colBase * K3;

    float acc[4][8][4];
    #pragma unroll
    for (int i = 0; i < 4; i++)
        #pragma unroll
        for (int j = 0; j < 8; j++)
            #pragma unroll
            for (int r = 0; r < 4; r++) acc[i][j][r] = 0.f;

    const int KT = K3 >> 5;
    #pragma unroll
    for (int s = 0; s < 3; s++) {
        unsigned st = sbase + s * BG_STAGE;
        load_tile(Ab, st, K3, s << 5);
        load_tile(Bb, st + 8192, K3, s << 5);
        asm volatile("cp.async.commit_group;\n");
    }

    // ldsm base addresses at ks=0 (paired-row layout); ks applied via ^32
    unsigned aAB[4], bAB[4];
    #pragma unroll
    for (int mi = 0; mi < 4; mi++) {
        int row = warpM * 64 + mi * 16 + (lane & 15);
        aAB[mi] = swz((unsigned)((row >> 1) * 128 + (row & 1) * 64 + (lane >> 4) * 16));
    }
    #pragma unroll
    for (int np = 0; np < 4; np++) {
        int rown = warpN * 64 + np * 16 + (lane & 15);
        bAB[np] = 8192u + swz((unsigned)((rown >> 1) * 128 + (rown & 1) * 64 + (lane >> 4) * 16));
    }

    unsigned fa[4][4], fb[4][4];

    for (int kt = 0; kt < KT; kt++) {
        asm volatile("cp.async.wait_group 2;\n");
        __syncthreads();

        unsigned stg = sbase + (unsigned)(kt & 3) * BG_STAGE;
        unsigned aA[4] = { stg + aAB[0], stg + aAB[1], stg + aAB[2], stg + aAB[3] };
        unsigned bA[4] = { stg + bAB[0], stg + bAB[1], stg + bAB[2], stg + bAB[3] };

        ldsm_frags(aA, bA, 0, fa, fb);

        const int next = kt + 3;
        if (next < KT) {
            unsigned ns = sbase + (unsigned)(next & 3) * BG_STAGE;
            load_tile(Ab, ns, K3, next << 5);
            load_tile(Bb, ns + 8192, K3, next << 5);
        }
        asm volatile("cp.async.commit_group;\n");

        mma_tile(acc, fa, fb);
        ldsm_frags(aA, bA, 32, fa, fb);
        mma_tile(acc, fa, fb);
    }

    // epilogue
    #pragma unroll
    for (int mi = 0; mi < 4; mi++)
        #pragma unroll
        for (int ni = 0; ni < 8; ni++) {
            int row = rowBase + warpM * 64 + mi * 16 + (lane >> 2);
            int col = colBase + warpN * 64 + ni * 8 + 2 * (lane & 3);
            float v0 = acc[mi][ni][0], v1 = acc[mi][ni][1];
            float v2 = acc[mi][ni][2], v3 = acc[mi][ni][3];
            if (EPI == 2) {
                v0 = gelu_f(v0); v1 = gelu_f(v1);
                v2 = gelu_f(v2); v3 = gelu_f(v3);
                size_t b0 = (size_t)row * (3 * (size_t)N);
                size_t b1 = (size_t)(row + 8) * (3 * (size_t)N);
                __nv_bfloat162 h01 = hi2(v0, v1), l01 = lo2(v0, v1, h01);
                __nv_bfloat162 h23 = hi2(v2, v3), l23 = lo2(v2, v3, h23);
                *(__nv_bfloat162*)(A3out + b0 + col)         = h01;
                *(__nv_bfloat162*)(A3out + b0 + N + col)     = l01;
                *(__nv_bfloat162*)(A3out + b0 + 2 * N + col) = h01;
                *(__nv_bfloat162*)(A3out + b1 + col)         = h23;
                *(__nv_bfloat162*)(A3out + b1 + N + col)     = l23;
                *(__nv_bfloat162*)(A3out + b1 + 2 * N + col) = h23;
            } else {
                float* p = C + (size_t)row * N + col;
                float* q = C + (size_t)(row + 8) * N + col;
                if (EPI == 1) { v0 += p[0]; v1 += p[1]; v2 += q[0]; v3 += q[1]; }
                *(float2*)p = make_float2(v0, v1);
                *(float2*)q = make_float2(v2, v3);
            }
        }
}

// ---------------- Tiled causal attention: 32 q-rows per block ----------------
#define ATT_SMEM ((32 * 128 + 32 * 132 + 32 * 128) * 4)

__global__ void __launch_bounds__(256)
attn_kernel(const float* __restrict__ qkv,
            const int* __restrict__ mask,
            __nv_bfloat16* __restrict__ a3) {
    extern __shared__ float asmem[];
    float* Qs = asmem;                 // [32][128]
    float* Kc = asmem + 32 * 128;      // [32][132]
    float* Vc = Kc + 32 * 132;         // [32][128]

    const int tid = threadIdx.x, lane = tid & 31, warp = tid >> 5;
    const int q0 = blockIdx.x * 32;
    const int h  = blockIdx.y;
    const int b  = blockIdx.z;
    const size_t base = (size_t)b * SEQ * TD;

    #pragma unroll
    for (int i = 0; i < 4; i++) {
        int idx = tid + i * 256;
        int r = idx >> 5, c = (idx & 31) * 4;
        *(float4*)&Qs[r * 128 + c] =
            *(const float4*)&qkv[base + (size_t)(q0 + r) * TD + h * DH + c];
    }

    const int qr0 = q0 + warp * 4;
    float m[4] = {-1e30f, -1e30f, -1e30f, -1e30f};
    float l[4] = {0.f, 0.f, 0.f, 0.f};
    float4 o[4];
    #pragma unroll
    for (int r = 0; r < 4; r++) o[r] = make_float4(0.f, 0.f, 0.f, 0.f);

    const int jmax = q0 + 31;
    for (int j0 = 0; j0 <= jmax; j0 += 32) {
        __syncthreads();
        #pragma unroll
        for (int i = 0; i < 4; i++) {
            int idx = tid + i * 256;
            int r = idx >> 5, c = (idx & 31) * 4;
            const float* src = qkv + base + (size_t)(j0 + r) * TD + h * DH + c;
            *(float4*)&Kc[r * 132 + c] = *(const float4*)(src + D);
            *(float4*)&Vc[r * 128 + c] = *(const float4*)(src + 2 * D);
        }
        __syncthreads();

        const int j = j0 + lane;
        const float mbias = (mask[b * SEQ + j] == 0) ? NEGB : 0.f;

        float dot[4] = {0.f, 0.f, 0.f, 0.f};
        #pragma unroll 4
        for (int d = 0; d < DH; d += 4) {
            float4 kv = *(const float4*)&Kc[lane * 132 + d];
            #pragma unroll
            for (int r = 0; r < 4; r++) {
                float4 qv = *(const float4*)&Qs[(warp * 4 + r) * 128 + d];
                dot[r] = fmaf(kv.x, qv.x, dot[r]);
                dot[r] = fmaf(kv.y, qv.y, dot[r]);
                dot[r] = fmaf(kv.z, qv.z, dot[r]);
                dot[r] = fmaf(kv.w, qv.w, dot[r]);
            }
        }

        float p[4];
        #pragma unroll
        for (int r = 0; r < 4; r++) {
            float s = (j <= qr0 + r) ? (dot[r] * SCALE + mbias) : -1e30f;
            float cmax = s;
            #pragma unroll
            for (int off = 16; off > 0; off >>= 1)
                cmax = fmaxf(cmax, __shfl_xor_sync(0xffffffffu, cmax, off));
            float newm = fmaxf(m[r], cmax);
            float corr = expf(m[r] - newm);
            p[r] = expf(s - newm);
            float psum = p[r];
            #pragma unroll
            for (int off = 16; off > 0; off >>= 1)
                psum += __shfl_xor_sync(0xffffffffu, psum, off);
            l[r] = l[r] * corr + psum;
            o[r].x *= corr; o[r].y *= corr; o[r].z *= corr; o[r].w *= corr;
            m[r] = newm;
        }

        #pragma unroll 4
        for (int jj = 0; jj < 32; jj++) {
            float4 v = *(const float4*)&Vc[jj * 128 + lane * 4];
            #pragma unroll
            for (int r = 0; r < 4; r++) {
                float pj = __shfl_sync(0xffffffffu, p[r], jj);
                o[r].x = fmaf(pj, v.x, o[r].x);
                o[r].y = fmaf(pj, v.y, o[r].y);
                o[r].z = fmaf(pj, v.z, o[r].z);
                o[r].w = fmaf(pj, v.w, o[r].w);
            }
        }
    }

    const int col = h * DH + lane * 4;
    #pragma unroll
    for (int r = 0; r < 4; r++) {
        const float inv = 1.f / l[r];
        float v0 = o[r].x * inv, v1 = o[r].y * inv;
        float v2 = o[r].z * inv, v3 = o[r].w * inv;
        size_t r3 = (size_t)(b * SEQ + qr0 + r) * (3 * D);
        __nv_bfloat162 h01 = hi2(v0, v1), l01 = lo2(v0, v1, h01);
        __nv_bfloat162 h23 = hi2(v2, v3), l23 = lo2(v2, v3, h23);
        *(__nv_bfloat162*)(a3 + r3 + col)             = h01;
        *(__nv_bfloat162*)(a3 + r3 + col + 2)         = h23;
        *(__nv_bfloat162*)(a3 + r3 + D + col)         = l01;
        *(__nv_bfloat162*)(a3 + r3 + D + col + 2)     = l23;
        *(__nv_bfloat162*)(a3 + r3 + 2 * D + col)     = h01;
        *(__nv_bfloat162*)(a3 + r3 + 2 * D + col + 2) = h23;
    }
}

// ---------------- Pool + head ----------------
__global__ void meanpool_kernel(const float* __restrict__ hs,
                                const int* __restrict__ mask,
                                float* __restrict__ mean) {
    int idx = blockIdx.x * blockDim.x + threadIdx.x;
    int b = idx / D;
    int d = idx % D;
    float acc = 0.f, msum = 0.f;
    const float* hb = hs + (size_t)b * SEQ * D + d;
    const int* mb = mask + b * SEQ;
    for (int s = 0; s < SEQ; s++) {
        float mf = (float)mb[s];
        acc = fmaf(mf, hb[(size_t)s * D], acc);
        msum += mf;
    }
    mean[idx] = acc / fmaxf(msum, 1e-9f);
}

__global__ void head1_kernel(const float* __restrict__ mean,
                             const float* __restrict__ Wc1,
                             const float* __restrict__ bc1,
                             float* __restrict__ t) {
    int idx = blockIdx.x * blockDim.x + threadIdx.x;
    int b = idx / D;
    int j = idx % D;
    float acc = bc1[j];
    const float* mb = mean + (size_t)b * D;
    for (int k = 0; k < D; k++)
        acc = fmaf(mb[k], Wc1[(size_t)k * D + j], acc);
    t[idx] = tanhf(acc);
}

__global__ void head2_kernel(const float* __restrict__ t,
                             const float* __restrict__ Wc2,
                             const float* __restrict__ bc2,
                             float* __restrict__ out) {
    __shared__ float red[256];
    __shared__ float logits[4];
    const int tid = threadIdx.x;
    float part[4] = {0.f, 0.f, 0.f, 0.f};
    for (int j = tid; j < D; j += 256) {
        float t0 = t[j], t1 = t[D + j];
        float w0 = Wc2[2 * j], w1 = Wc2[2 * j + 1];
        part[0] = fmaf(t0, w0, part[0]);
        part[1] = fmaf(t0, w1, part[1]);
        part[2] = fmaf(t1, w0, part[2]);
        part[3] = fmaf(t1, w1, part[3]);
    }
    for (int c = 0; c < 4; c++) {
        __syncthreads();
        red[tid] = part[c]; __syncthreads();
        for (int st = 128; st > 0; st >>= 1) {
            if (tid < st) red[tid] += red[tid + st];
            __syncthreads();
        }
        if (tid == 0) logits[c] = red[0] + bc2[c & 1];
    }
    __syncthreads();
    if (tid == 0) {
        for (int b = 0; b < BATCH; b++) {
            float l0 = logits[2 * b], l1 = logits[2 * b + 1];
            float m = fmaxf(l0, l1);
            float e0 = expf(l0 - m), e1 = expf(l1 - m);
            out[b] = e1 / (e0 + e1);
        }
    }
}

// ---------------- Launch ----------------
extern "C" void kernel_launch(void* const* d_in, const int* in_sizes, int n_in,
                              void* d_out, int out_size) {
    const int*   ids   = (const int*)d_in[0];
    const int*   amask = (const int*)d_in[1];
    const float* emb   = (const float*)d_in[2];
    const float* ln1_g = (const float*)d_in[3];
    const float* ln1_b = (const float*)d_in[4];
    const float* Wqkv  = (const float*)d_in[5];
    const float* Wo    = (const float*)d_in[6];
    const float* ln2_g = (const float*)d_in[7];
    const float* ln2_b = (const float*)d_in[8];
    const float* W1    = (const float*)d_in[9];
    const float* W2    = (const float*)d_in[10];
    const float* lnf_g = (const float*)d_in[11];
    const float* lnf_b = (const float*)d_in[12];
    const float* Wc1   = (const float*)d_in[13];
    const float* bc1   = (const float*)d_in[14];
    const float* Wc2   = (const float*)d_in[15];
    const float* bc2   = (const float*)d_in[16];
    float* out = (float*)d_out;

    float *x, *h, *qkv, *mean, *t;
    __nv_bfloat16 *a3s, *a3f, *wqkv3, *wo3, *w13, *w23;
    cudaGetSymbolAddress((void**)&x,    g_x);
    cudaGetSymbolAddress((void**)&h,    g_h);
    cudaGetSymbolAddress((void**)&qkv,  g_qkv);
    cudaGetSymbolAddress((void**)&mean, g_mean);
    cudaGetSymbolAddress((void**)&t,    g_t);
    cudaGetSymbolAddress((void**)&a3s,   g_a3s);
    cudaGetSymbolAddress((void**)&a3f,   g_a3f);
    cudaGetSymbolAddress((void**)&wqkv3, g_wqkv3);
    cudaGetSymbolAddress((void**)&wo3,   g_wo3);
    cudaGetSymbolAddress((void**)&w13,   g_w13);
    cudaGetSymbolAddress((void**)&w23,   g_w23);

    cudaFuncSetAttribute(bgemm_kernel<0>,
                         cudaFuncAttributeMaxDynamicSharedMemorySize, BG_SMEM);
    cudaFuncSetAttribute(bgemm_kernel<1>,
                         cudaFuncAttributeMaxDynamicSharedMemorySize, BG_SMEM);
    cudaFuncSetAttribute(bgemm_kernel<2>,
                         cudaFuncAttributeMaxDynamicSharedMemorySize, BG_SMEM);
    cudaFuncSetAttribute(attn_kernel,
                         cudaFuncAttributeMaxDynamicSharedMemorySize, ATT_SMEM);

    embed_kernel<<<(BS * D) / 256, 256>>>(ids, emb, x);

    for (int l = 0; l < LAYERS; l++) {
        // attention block
        ln_kernel<1><<<BS, 256>>>(x, ln1_g + (size_t)l * D, ln1_b + (size_t)l * D,
                                  nullptr, a3s);
        convw_kernel<<<dim3(TD / 32, D / 64), dim3(32, 8)>>>(
            Wqkv + (size_t)l * D * TD, wqkv3, D, TD);
        bgemm_kernel<0><<<dim3(BS / 128, TD / 128), 128, BG_SMEM>>>(
            a3s, wqkv3, qkv, nullptr, BS, TD, 3 * D);
        attn_kernel<<<dim3(SEQ / 32, H, BATCH), 256, ATT_SMEM>>>(qkv, amask, a3s);
        convw_kernel<<<dim3(D / 32, D / 64), dim3(32, 8)>>>(
            Wo + (size_t)l * D * D, wo3, D, D);
        bgemm_kernel<1><<<dim3(BS / 128, D / 128), 128, BG_SMEM>>>(
            a3s, wo3, x, nullptr, BS, D, 3 * D);
        // mlp block
        ln_kernel<1><<<BS, 256>>>(x, ln2_g + (size_t)l * D, ln2_b + (size_t)l * D,
                                  nullptr, a3s);
        convw_kernel<<<dim3(FF / 32, D / 64), dim3(32, 8)>>>(
            W1 + (size_t)l * D * FF, w13, D, FF);
        bgemm_kernel<2><<<dim3(BS / 128, FF / 128), 128, BG_SMEM>>>(
            a3s, w13, nullptr, a3f, BS, FF, 3 * D);
        convw_kernel<<<dim3(D / 32, FF / 64), dim3(32, 8)>>>(
            W2 + (size_t)l * FF * D, w23, FF, D);
        bgemm_kernel<1><<<dim3(BS / 128, D / 128), 128, BG_SMEM>>>(
            a3f, w23, x, nullptr, BS, D, 3 * FF);
    }

    ln_kernel<0><<<BS, 256>>>(x, lnf_g, lnf_b, h, nullptr);
    meanpool_kernel<<<(BATCH * D) / 256, 256>>>(h, amask, mean);
    head1_kernel<<<(BATCH * D) / 256, 256>>>(mean, Wc1, bc1, t);
    head2_kernel<<<1, 256>>>(t, Wc2, bc2, out);
}

// round 10
// speedup vs baseline: 1.9689x; 1.0202x over previous
#include <cuda_runtime.h>
#include <cuda_bf16.h>
#include <math.h>
#include <stdint.h>

// ---------------- Problem constants ----------------
#define LAYERS 2
#define D      2048
#define H      16
#define FF     8192
#define BATCH  2
#define SEQ    1024
#define DH     128
#define TD     (3 * D)
#define BS     (BATCH * SEQ)
#define NEGB   (-1e9f)
#define SCALE  0.08838834764831845f

// ---------------- Scratch (static device globals) ----------------
__device__ float g_x   [BS * D];
__device__ float g_h   [BS * D];
__device__ float g_qkv [BS * TD];
__device__ float g_mean[BATCH * D];
__device__ float g_t   [BATCH * D];
// bf16x3 split buffers
__device__ __nv_bfloat16 g_a3s  [BS * 3 * D];
__device__ __nv_bfloat16 g_a3f  [BS * 3 * FF];
__device__ __nv_bfloat16 g_wqkv3[TD * 3 * D];
__device__ __nv_bfloat16 g_wo3  [D  * 3 * D];
__device__ __nv_bfloat16 g_w13  [FF * 3 * D];
__device__ __nv_bfloat16 g_w23  [D  * 3 * FF];

// ---------------- Embedding gather ----------------
__global__ void embed_kernel(const int* __restrict__ ids,
                             const float* __restrict__ emb,
                             float* __restrict__ x) {
    int idx = blockIdx.x * blockDim.x + threadIdx.x;
    int tok = ids[idx / D];
    x[idx] = emb[(size_t)tok * D + (idx % D)];
}

// ---------------- LayerNorm; SPLIT=1 writes bf16x3 (K=D), else fp32 ----------------
template<int SPLIT>
__global__ void ln_kernel(const float* __restrict__ x,
                          const float* __restrict__ g,
                          const float* __restrict__ b,
                          float* __restrict__ outf,
                          __nv_bfloat16* __restrict__ out3) {
    __shared__ float row[D];
    __shared__ float red[256];
    const int tid = threadIdx.x;
    const float* xr = x + (size_t)blockIdx.x * D;

    float s = 0.f;
    for (int i = tid; i < D; i += 256) { float v = xr[i]; row[i] = v; s += v; }
    red[tid] = s; __syncthreads();
    for (int st = 128; st > 0; st >>= 1) {
        if (tid < st) red[tid] += red[tid + st];
        __syncthreads();
    }
    const float mean = red[0] * (1.0f / D);
    __syncthreads();

    float s2 = 0.f;
    for (int i = tid; i < D; i += 256) { float v = row[i] - mean; s2 += v * v; }
    red[tid] = s2; __syncthreads();
    for (int st = 128; st > 0; st >>= 1) {
        if (tid < st) red[tid] += red[tid + st];
        __syncthreads();
    }
    const float rstd = rsqrtf(red[0] * (1.0f / D) + 1e-5f);

    if (SPLIT) {
        __nv_bfloat16* o3 = out3 + (size_t)blockIdx.x * (3 * D);
        for (int i = tid; i < D; i += 256) {
            float v = (row[i] - mean) * rstd * g[i] + b[i];
            __nv_bfloat16 hi = __float2bfloat16(v);
            __nv_bfloat16 lo = __float2bfloat16(v - __bfloat162float(hi));
            o3[i]         = hi;
            o3[D + i]     = lo;
            o3[2 * D + i] = hi;
        }
    } else {
        float* orow = outf + (size_t)blockIdx.x * D;
        for (int i = tid; i < D; i += 256)
            orow[i] = (row[i] - mean) * rstd * g[i] + b[i];
    }
}

// ---------------- Split-convert + transpose weights: W[K,N] fp32 -> Wt3[N,3K] bf16 ----------------
__global__ void convw_kernel(const float* __restrict__ W,
                             __nv_bfloat16* __restrict__ Wt3, int K, int N) {
    __shared__ float tile[64][33];
    int n0 = blockIdx.x * 32, k0 = blockIdx.y * 64;
    int tx = threadIdx.x, ty = threadIdx.y;   // (32, 8)
    #pragma unroll
    for (int i = 0; i < 64; i += 8)
        tile[ty + i][tx] = W[(size_t)(k0 + ty + i) * N + n0 + tx];
    __syncthreads();
    #pragma unroll
    for (int i = 0; i < 32; i += 8) {
        int nn = ty + i;
        int n = n0 + nn;
        float x0 = tile[2 * tx][nn];
        float x1 = tile[2 * tx + 1][nn];
        __nv_bfloat162 hi, lo;
        hi.x = __float2bfloat16(x0);
        hi.y = __float2bfloat16(x1);
        lo.x = __float2bfloat16(x0 - __bfloat162float(hi.x));
        lo.y = __float2bfloat16(x1 - __bfloat162float(hi.y));
        size_t base = (size_t)n * (3 * K);
        int k = k0 + 2 * tx;
        *(__nv_bfloat162*)(Wt3 + base + k)         = hi;
        *(__nv_bfloat162*)(Wt3 + base + K + k)     = hi;
        *(__nv_bfloat162*)(Wt3 + base + 2 * K + k) = lo;
    }
}

// ========= mma.sync bf16 GEMM: 128 threads, warp tile 64x64, BK=64, 3 stages =========
#define BG_STAGE  32768                 // 16KB A + 16KB B
#define BG_SMEM   (3 * BG_STAGE)        // 96KB -> 2 CTAs/SM

__device__ __forceinline__ unsigned swz(unsigned o) { return o ^ ((o >> 3) & 0x70); }

__device__ __forceinline__ void ldsm4(unsigned addr, unsigned& r0, unsigned& r1,
                                      unsigned& r2, unsigned& r3) {
    asm volatile("ldmatrix.sync.aligned.m8n8.x4.shared.b16 {%0,%1,%2,%3}, [%4];\n"
                 : "=r"(r0), "=r"(r1), "=r"(r2), "=r"(r3) : "r"(addr));
}
__device__ __forceinline__ void mma16816(float* c, unsigned a0, unsigned a1,
                                         unsigned a2, unsigned a3,
                                         unsigned b0, unsigned b1) {
    asm volatile(
        "mma.sync.aligned.m16n8k16.row.col.f32.bf16.bf16.f32 "
        "{%0,%1,%2,%3},{%4,%5,%6,%7},{%8,%9},{%0,%1,%2,%3};\n"
        : "+f"(c[0]), "+f"(c[1]), "+f"(c[2]), "+f"(c[3])
        : "r"(a0), "r"(a1), "r"(a2), "r"(a3), "r"(b0), "r"(b1));
}
__device__ __forceinline__ void cpasync16(unsigned saddr, const void* g) {
    asm volatile("cp.async.cg.shared.global [%0], [%1], 16;\n" :: "r"(saddr), "l"(g));
}

// load 128-row x 64-col bf16 tile (128B full rows, SW128) with 128 threads (16KB)
__device__ __forceinline__ void load_tile64(const __nv_bfloat16* gbase, unsigned sbase,
                                            int ld, int k0) {
    int t = threadIdx.x;
    #pragma unroll
    for (int i = 0; i < 8; i++) {
        int c = t + i * 128;              // 0..1023
        int row = c >> 3, seg = c & 7;
        cpasync16(sbase + swz((unsigned)(row * 128 + seg * 16)),
                  gbase + (size_t)row * ld + k0 + seg * 8);
    }
}

// frag fetch: k-slice offset (bits 5-6) applied via XOR on swizzled base
__device__ __forceinline__ void ldsm_frags(const unsigned aA[4], const unsigned bA[4],
                                           unsigned off,
                                           unsigned fa[4][4], unsigned fb[4][4]) {
    #pragma unroll
    for (int mi = 0; mi < 4; mi++)
        ldsm4(aA[mi] ^ off, fa[mi][0], fa[mi][1], fa[mi][2], fa[mi][3]);
    #pragma unroll
    for (int np = 0; np < 4; np++)
        ldsm4(bA[np] ^ off, fb[np][0], fb[np][1], fb[np][2], fb[np][3]);
}

__device__ __forceinline__ void mma_tile(float acc[4][8][4],
                                         unsigned fa[4][4], unsigned fb[4][4]) {
    #pragma unroll
    for (int mi = 0; mi < 4; mi++)
        #pragma unroll
        for (int ni = 0; ni < 8; ni++) {
            unsigned b0 = fb[ni >> 1][ni & 1];
            unsigned b1 = fb[ni >> 1][2 + (ni & 1)];
            mma16816(acc[mi][ni], fa[mi][0], fa[mi][1], fa[mi][2], fa[mi][3], b0, b1);
        }
}

__device__ __forceinline__ float gelu_f(float xx) {
    return 0.5f * xx * (1.0f + tanhf(0.7978845608028654f *
                                     (xx + 0.044715f * xx * xx * xx)));
}
__device__ __forceinline__ __nv_bfloat162 hi2(float a, float b) {
    __nv_bfloat162 r;
    r.x = __float2bfloat16(a); r.y = __float2bfloat16(b);
    return r;
}
__device__ __forceinline__ __nv_bfloat162 lo2(float a, float b, __nv_bfloat162 h) {
    __nv_bfloat162 r;
    r.x = __float2bfloat16(a - __bfloat162float(h.x));
    r.y = __float2bfloat16(b - __bfloat162float(h.y));
    return r;
}

template<int EPI>
__global__ void __launch_bounds__(128, 2)
bgemm_kernel(const __nv_bfloat16* __restrict__ A,
             const __nv_bfloat16* __restrict__ Bt,
             float* __restrict__ C,
             __nv_bfloat16* __restrict__ A3out,
             int M, int N, int K3) {
    extern __shared__ __align__(128) char smem[];
    unsigned sbase = (unsigned)__cvta_generic_to_shared(smem);

    const int tid = threadIdx.x, lane = tid & 31, warp = tid >> 5;  // 4 warps
    const int warpM = warp & 1, warpN = warp >> 1;                  // 2x2
    const int rowBase = blockIdx.x * 128;
    const int colBase = blockIdx.y * 128;
    const __nv_bfloat16* Ab = A  + (size_t)rowBase * K3;
    const __nv_bfloat16* Bb = Bt + (size_t)colBase * K3;

    float acc[4][8][4];
    #pragma unroll
    for (int i = 0; i < 4; i++)
        #pragma unroll
        for (int j = 0; j < 8; j++)
            #pragma unroll
            for (int r = 0; r < 4; r++) acc[i][j][r] = 0.f;

    const int KT = K3 >> 6;
    #pragma unroll
    for (int s = 0; s < 2; s++) {                 // prologue: 2 stages
        unsigned st = sbase + s * BG_STAGE;
        load_tile64(Ab, st, K3, s << 6);
        load_tile64(Bb, st + 16384, K3, s << 6);
        asm volatile("cp.async.commit_group;\n");
    }

    // ldsm base addresses at k-slice 0 (128B rows); slice applied via XOR {32,64,96}
    unsigned aAB[4], bAB[4];
    #pragma unroll
    for (int mi = 0; mi < 4; mi++) {
        int row = warpM * 64 + mi * 16 + (lane & 15);
        aAB[mi] = swz((unsigned)(row * 128 + (lane >> 4) * 16));
    }
    #pragma unroll
    for (int np = 0; np < 4; np++) {
        int rown = warpN * 64 + np * 16 + (lane & 15);
        bAB[np] = 16384u + swz((unsigned)(rown * 128 + (lane >> 4) * 16));
    }

    unsigned fa[4][4], fb[4][4];
    int buf = 0;

    for (int kt = 0; kt < KT; kt++) {
        asm volatile("cp.async.wait_group 1;\n");
        __syncthreads();

        unsigned stg = sbase + (unsigned)buf * BG_STAGE;
        unsigned aA[4] = { stg + aAB[0], stg + aAB[1], stg + aAB[2], stg + aAB[3] };
        unsigned bA[4] = { stg + bAB[0], stg + bAB[1], stg + bAB[2], stg + bAB[3] };

        ldsm_frags(aA, bA, 0, fa, fb);

        const int next = kt + 2;
        if (next < KT) {
            int nb = buf + 2; if (nb >= 3) nb -= 3;
            unsigned ns = sbase + (unsigned)nb * BG_STAGE;
            load_tile64(Ab, ns, K3, next << 6);
            load_tile64(Bb, ns + 16384, K3, next << 6);
        }
        asm volatile("cp.async.commit_group;\n");

        mma_tile(acc, fa, fb);
        ldsm_frags(aA, bA, 32, fa, fb);
        mma_tile(acc, fa, fb);
        ldsm_frags(aA, bA, 64, fa, fb);
        mma_tile(acc, fa, fb);
        ldsm_frags(aA, bA, 96, fa, fb);
        mma_tile(acc, fa, fb);

        if (++buf == 3) buf = 0;
    }

    // epilogue
    #pragma unroll
    for (int mi = 0; mi < 4; mi++)
        #pragma unroll
        for (int ni = 0; ni < 8; ni++) {
            int row = rowBase + warpM * 64 + mi * 16 + (lane >> 2);
            int col = colBase + warpN * 64 + ni * 8 + 2 * (lane & 3);
            float v0 = acc[mi][ni][0], v1 = acc[mi][ni][1];
            float v2 = acc[mi][ni][2], v3 = acc[mi][ni][3];
            if (EPI == 2) {
                v0 = gelu_f(v0); v1 = gelu_f(v1);
                v2 = gelu_f(v2); v3 = gelu_f(v3);
                size_t b0 = (size_t)row * (3 * (size_t)N);
                size_t b1 = (size_t)(row + 8) * (3 * (size_t)N);
                __nv_bfloat162 h01 = hi2(v0, v1), l01 = lo2(v0, v1, h01);
                __nv_bfloat162 h23 = hi2(v2, v3), l23 = lo2(v2, v3, h23);
                *(__nv_bfloat162*)(A3out + b0 + col)         = h01;
                *(__nv_bfloat162*)(A3out + b0 + N + col)     = l01;
                *(__nv_bfloat162*)(A3out + b0 + 2 * N + col) = h01;
                *(__nv_bfloat162*)(A3out + b1 + col)         = h23;
                *(__nv_bfloat162*)(A3out + b1 + N + col)     = l23;
                *(__nv_bfloat162*)(A3out + b1 + 2 * N + col) = h23;
            } else {
                float* p = C + (size_t)row * N + col;
                float* q = C + (size_t)(row + 8) * N + col;
                if (EPI == 1) { v0 += p[0]; v1 += p[1]; v2 += q[0]; v3 += q[1]; }
                *(float2*)p = make_float2(v0, v1);
                *(float2*)q = make_float2(v2, v3);
            }
        }
}

// ---------------- Tiled causal attention: 64 q-rows per block ----------------
// 8 warps x 8 q-rows; K/V streamed in 32-key chunks shared by all 64 rows.
// Smem: Qs[64][128] | Kc[32][132] | Vc[32][128] = 66048 bytes
#define ATT_SMEM ((64 * 128 + 32 * 132 + 32 * 128) * 4)

__global__ void __launch_bounds__(256)
attn_kernel(const float* __restrict__ qkv,
            const int* __restrict__ mask,
            __nv_bfloat16* __restrict__ a3) {
    extern __shared__ float asmem[];
    float* Qs = asmem;                 // [64][128]
    float* Kc = asmem + 64 * 128;      // [32][132]
    float* Vc = Kc + 32 * 132;         // [32][128]

    const int tid = threadIdx.x, lane = tid & 31, warp = tid >> 5;
    const int q0 = blockIdx.x * 64;
    const int h  = blockIdx.y;
    const int b  = blockIdx.z;
    const size_t base = (size_t)b * SEQ * TD;

    // load 64 q rows (2048 float4 by 256 threads)
    #pragma unroll
    for (int i = 0; i < 8; i++) {
        int idx = tid + i * 256;
        int r = idx >> 5, c = (idx & 31) * 4;
        *(float4*)&Qs[r * 128 + c] =
            *(const float4*)&qkv[base + (size_t)(q0 + r) * TD + h * DH + c];
    }

    const int qr0 = q0 + warp * 8;
    float m[8], l[8];
    float4 o[8];
    #pragma unroll
    for (int r = 0; r < 8; r++) {
        m[r] = -1e30f; l[r] = 0.f;
        o[r] = make_float4(0.f, 0.f, 0.f, 0.f);
    }

    const int jmax = q0 + 63;
    for (int j0 = 0; j0 <= jmax; j0 += 32) {
        __syncthreads();
        #pragma unroll
        for (int i = 0; i < 4; i++) {
            int idx = tid + i * 256;
            int r = idx >> 5, c = (idx & 31) * 4;
            const float* src = qkv + base + (size_t)(j0 + r) * TD + h * DH + c;
            *(float4*)&Kc[r * 132 + c] = *(const float4*)(src + D);
            *(float4*)&Vc[r * 128 + c] = *(const float4*)(src + 2 * D);
        }
        __syncthreads();

        const int j = j0 + lane;
        const float mbias = (mask[b * SEQ + j] == 0) ? NEGB : 0.f;

        float dot[8];
        #pragma unroll
        for (int r = 0; r < 8; r++) dot[r] = 0.f;
        #pragma unroll 2
        for (int d = 0; d < DH; d += 4) {
            float4 kv = *(const float4*)&Kc[lane * 132 + d];
            #pragma unroll
            for (int r = 0; r < 8; r++) {
                float4 qv = *(const float4*)&Qs[(warp * 8 + r) * 128 + d];
                dot[r] = fmaf(kv.x, qv.x, dot[r]);
                dot[r] = fmaf(kv.y, qv.y, dot[r]);
                dot[r] = fmaf(kv.z, qv.z, dot[r]);
                dot[r] = fmaf(kv.w, qv.w, dot[r]);
            }
        }

        float p[8];
        #pragma unroll
        for (int r = 0; r < 8; r++) {
            float s = (j <= qr0 + r) ? (dot[r] * SCALE + mbias) : -1e30f;
            float cmax = s;
            #pragma unroll
            for (int off = 16; off > 0; off >>= 1)
                cmax = fmaxf(cmax, __shfl_xor_sync(0xffffffffu, cmax, off));
            float newm = fmaxf(m[r], cmax);
            float corr = expf(m[r] - newm);
            p[r] = expf(s - newm);
            float psum = p[r];
            #pragma unroll
            for (int off = 16; off > 0; off >>= 1)
                psum += __shfl_xor_sync(0xffffffffu, psum, off);
            l[r] = l[r] * corr + psum;
            o[r].x *= corr; o[r].y *= corr; o[r].z *= corr; o[r].w *= corr;
            m[r] = newm;
        }

        #pragma unroll 2
        for (int jj = 0; jj < 32; jj++) {
            float4 v = *(const float4*)&Vc[jj * 128 + lane * 4];
            #pragma unroll
            for (int r = 0; r < 8; r++) {
                float pj = __shfl_sync(0xffffffffu, p[r], jj);
                o[r].x = fmaf(pj, v.x, o[r].x);
                o[r].y = fmaf(pj, v.y, o[r].y);
                o[r].z = fmaf(pj, v.z, o[r].z);
                o[r].w = fmaf(pj, v.w, o[r].w);
            }
        }
    }

    const int col = h * DH + lane * 4;
    #pragma unroll
    for (int r = 0; r < 8; r++) {
        const float inv = 1.f / l[r];
        float v0 = o[r].x * inv, v1 = o[r].y * inv;
        float v2 = o[r].z * inv, v3 = o[r].w * inv;
        size_t r3 = (size_t)(b * SEQ + qr0 + r) * (3 * D);
        __nv_bfloat162 h01 = hi2(v0, v1), l01 = lo2(v0, v1, h01);
        __nv_bfloat162 h23 = hi2(v2, v3), l23 = lo2(v2, v3, h23);
        *(__nv_bfloat162*)(a3 + r3 + col)             = h01;
        *(__nv_bfloat162*)(a3 + r3 + col + 2)         = h23;
        *(__nv_bfloat162*)(a3 + r3 + D + col)         = l01;
        *(__nv_bfloat162*)(a3 + r3 + D + col + 2)     = l23;
        *(__nv_bfloat162*)(a3 + r3 + 2 * D + col)     = h01;
        *(__nv_bfloat162*)(a3 + r3 + 2 * D + col + 2) = h23;
    }
}

// ---------------- Pool + head ----------------
__global__ void meanpool_kernel(const float* __restrict__ hs,
                                const int* __restrict__ mask,
                                float* __restrict__ mean) {
    int idx = blockIdx.x * blockDim.x + threadIdx.x;
    int b = idx / D;
    int d = idx % D;
    float acc = 0.f, msum = 0.f;
    const float* hb = hs + (size_t)b * SEQ * D + d;
    const int* mb = mask + b * SEQ;
    for (int s = 0; s < SEQ; s++) {
        float mf = (float)mb[s];
        acc = fmaf(mf, hb[(size_t)s * D], acc);
        msum += mf;
    }
    mean[idx] = acc / fmaxf(msum, 1e-9f);
}

__global__ void head1_kernel(const float* __restrict__ mean,
                             const float* __restrict__ Wc1,
                             const float* __restrict__ bc1,
                             float* __restrict__ t) {
    int idx = blockIdx.x * blockDim.x + threadIdx.x;
    int b = idx / D;
    int j = idx % D;
    float acc = bc1[j];
    const float* mb = mean + (size_t)b * D;
    for (int k = 0; k < D; k++)
        acc = fmaf(mb[k], Wc1[(size_t)k * D + j], acc);
    t[idx] = tanhf(acc);
}

__global__ void head2_kernel(const float* __restrict__ t,
                             const float* __restrict__ Wc2,
                             const float* __restrict__ bc2,
                             float* __restrict__ out) {
    __shared__ float red[256];
    __shared__ float logits[4];
    const int tid = threadIdx.x;
    float part[4] = {0.f, 0.f, 0.f, 0.f};
    for (int j = tid; j < D; j += 256) {
        float t0 = t[j], t1 = t[D + j];
        float w0 = Wc2[2 * j], w1 = Wc2[2 * j + 1];
        part[0] = fmaf(t0, w0, part[0]);
        part[1] = fmaf(t0, w1, part[1]);
        part[2] = fmaf(t1, w0, part[2]);
        part[3] = fmaf(t1, w1, part[3]);
    }
    for (int c = 0; c < 4; c++) {
        __syncthreads();
        red[tid] = part[c]; __syncthreads();
        for (int st = 128; st > 0; st >>= 1) {
            if (tid < st) red[tid] += red[tid + st];
            __syncthreads();
        }
        if (tid == 0) logits[c] = red[0] + bc2[c & 1];
    }
    __syncthreads();
    if (tid == 0) {
        for (int b = 0; b < BATCH; b++) {
            float l0 = logits[2 * b], l1 = logits[2 * b + 1];
            float m = fmaxf(l0, l1);
            float e0 = expf(l0 - m), e1 = expf(l1 - m);
            out[b] = e1 / (e0 + e1);
        }
    }
}

// ---------------- Launch ----------------
extern "C" void kernel_launch(void* const* d_in, const int* in_sizes, int n_in,
                              void* d_out, int out_size) {
    const int*   ids   = (const int*)d_in[0];
    const int*   amask = (const int*)d_in[1];
    const float* emb   = (const float*)d_in[2];
    const float* ln1_g = (const float*)d_in[3];
    const float* ln1_b = (const float*)d_in[4];
    const float* Wqkv  = (const float*)d_in[5];
    const float* Wo    = (const float*)d_in[6];
    const float* ln2_g = (const float*)d_in[7];
    const float* ln2_b = (const float*)d_in[8];
    const float* W1    = (const float*)d_in[9];
    const float* W2    = (const float*)d_in[10];
    const float* lnf_g = (const float*)d_in[11];
    const float* lnf_b = (const float*)d_in[12];
    const float* Wc1   = (const float*)d_in[13];
    const float* bc1   = (const float*)d_in[14];
    const float* Wc2   = (const float*)d_in[15];
    const float* bc2   = (const float*)d_in[16];
    float* out = (float*)d_out;

    float *x, *h, *qkv, *mean, *t;
    __nv_bfloat16 *a3s, *a3f, *wqkv3, *wo3, *w13, *w23;
    cudaGetSymbolAddress((void**)&x,    g_x);
    cudaGetSymbolAddress((void**)&h,    g_h);
    cudaGetSymbolAddress((void**)&qkv,  g_qkv);
    cudaGetSymbolAddress((void**)&mean, g_mean);
    cudaGetSymbolAddress((void**)&t,    g_t);
    cudaGetSymbolAddress((void**)&a3s,   g_a3s);
    cudaGetSymbolAddress((void**)&a3f,   g_a3f);
    cudaGetSymbolAddress((void**)&wqkv3, g_wqkv3);
    cudaGetSymbolAddress((void**)&wo3,   g_wo3);
    cudaGetSymbolAddress((void**)&w13,   g_w13);
    cudaGetSymbolAddress((void**)&w23,   g_w23);

    cudaFuncSetAttribute(bgemm_kernel<0>,
                         cudaFuncAttributeMaxDynamicSharedMemorySize, BG_SMEM);
    cudaFuncSetAttribute(bgemm_kernel<1>,
                         cudaFuncAttributeMaxDynamicSharedMemorySize, BG_SMEM);
    cudaFuncSetAttribute(bgemm_kernel<2>,
                         cudaFuncAttributeMaxDynamicSharedMemorySize, BG_SMEM);
    cudaFuncSetAttribute(attn_kernel,
                         cudaFuncAttributeMaxDynamicSharedMemorySize, ATT_SMEM);

    embed_kernel<<<(BS * D) / 256, 256>>>(ids, emb, x);

    for (int l = 0; l < LAYERS; l++) {
        // attention block
        ln_kernel<1><<<BS, 256>>>(x, ln1_g + (size_t)l * D, ln1_b + (size_t)l * D,
                                  nullptr, a3s);
        convw_kernel<<<dim3(TD / 32, D / 64), dim3(32, 8)>>>(
            Wqkv + (size_t)l * D * TD, wqkv3, D, TD);
        bgemm_kernel<0><<<dim3(BS / 128, TD / 128), 128, BG_SMEM>>>(
            a3s, wqkv3, qkv, nullptr, BS, TD, 3 * D);
        attn_kernel<<<dim3(SEQ / 64, H, BATCH), 256, ATT_SMEM>>>(qkv, amask, a3s);
        convw_kernel<<<dim3(D / 32, D / 64), dim3(32, 8)>>>(
            Wo + (size_t)l * D * D, wo3, D, D);
        bgemm_kernel<1><<<dim3(BS / 128, D / 128), 128, BG_SMEM>>>(
            a3s, wo3, x, nullptr, BS, D, 3 * D);
        // mlp block
        ln_kernel<1><<<BS, 256>>>(x, ln2_g + (size_t)l * D, ln2_b + (size_t)l * D,
                                  nullptr, a3s);
        convw_kernel<<<dim3(FF / 32, D / 64), dim3(32, 8)>>>(
            W1 + (size_t)l * D * FF, w13, D, FF);
        bgemm_kernel<2><<<dim3(BS / 128, FF / 128), 128, BG_SMEM>>>(
            a3s, w13, nullptr, a3f, BS, FF, 3 * D);
        convw_kernel<<<dim3(D / 32, FF / 64), dim3(32, 8)>>>(
            W2 + (size_t)l * FF * D, w23, FF, D);
        bgemm_kernel<1><<<dim3(BS / 128, D / 128), 128, BG_SMEM>>>(
            a3f, w23, x, nullptr, BS, D, 3 * FF);
    }

    ln_kernel<0><<<BS, 256>>>(x, lnf_g, lnf_b, h, nullptr);
    meanpool_kernel<<<(BATCH * D) / 256, 256>>>(h, amask, mean);
    head1_kernel<<<(BATCH * D) / 256, 256>>>(mean, Wc1, bc1, t);
    head2_kernel<<<1, 256>>>(t, Wc2, bc2, out);
}

// round 11
// speedup vs baseline: 2.6158x; 1.3286x over previous
#include <cuda_runtime.h>
#include <cuda_bf16.h>
#include <math.h>
#include <stdint.h>

// ---------------- Problem constants ----------------
#define LAYERS 2
#define D      2048
#define H      16
#define FF     8192
#define BATCH  2
#define SEQ    1024
#define DH     128
#define TD     (3 * D)
#define BS     (BATCH * SEQ)
#define NEGB   (-1e9f)
#define SCALE  0.08838834764831845f

// ---------------- Scratch (static device globals) ----------------
__device__ float g_x   [BS * D];
__device__ float g_h   [BS * D];    // ln output (tf32-rounded when GEMM input)
__device__ float g_qkv [BS * TD];
__device__ float g_ao  [BS * D];    // attention output (tf32-rounded)
__device__ float g_ff  [BS * FF];   // gelu output (tf32-rounded)
__device__ float g_mean[BATCH * D];
__device__ float g_t   [BATCH * D];
// fp32 transposed (+tf32-rounded) weights: Wt[N][K]
__device__ float g_wqkvT[TD * D];
__device__ float g_woT  [D * D];
__device__ float g_w1T  [FF * D];
__device__ float g_w2T  [D * FF];

__device__ __forceinline__ float rna_tf32(float x) {
    unsigned u;
    asm("cvt.rna.tf32.f32 %0, %1;" : "=r"(u) : "f"(x));
    return __uint_as_float(u);
}

// ---------------- Embedding gather ----------------
__global__ void embed_kernel(const int* __restrict__ ids,
                             const float* __restrict__ emb,
                             float* __restrict__ x) {
    int idx = blockIdx.x * blockDim.x + threadIdx.x;
    int tok = ids[idx / D];
    x[idx] = emb[(size_t)tok * D + (idx % D)];
}

// ---------------- LayerNorm; ROUND=1 rounds output to tf32 ----------------
template<int ROUND>
__global__ void ln_kernel(const float* __restrict__ x,
                          const float* __restrict__ g,
                          const float* __restrict__ b,
                          float* __restrict__ out) {
    __shared__ float row[D];
    __shared__ float red[256];
    const int tid = threadIdx.x;
    const float* xr = x + (size_t)blockIdx.x * D;

    float s = 0.f;
    for (int i = tid; i < D; i += 256) { float v = xr[i]; row[i] = v; s += v; }
    red[tid] = s; __syncthreads();
    for (int st = 128; st > 0; st >>= 1) {
        if (tid < st) red[tid] += red[tid + st];
        __syncthreads();
    }
    const float mean = red[0] * (1.0f / D);
    __syncthreads();

    float s2 = 0.f;
    for (int i = tid; i < D; i += 256) { float v = row[i] - mean; s2 += v * v; }
    red[tid] = s2; __syncthreads();
    for (int st = 128; st > 0; st >>= 1) {
        if (tid < st) red[tid] += red[tid + st];
        __syncthreads();
    }
    const float rstd = rsqrtf(red[0] * (1.0f / D) + 1e-5f);

    float* orow = out + (size_t)blockIdx.x * D;
    for (int i = tid; i < D; i += 256) {
        float v = (row[i] - mean) * rstd * g[i] + b[i];
        orow[i] = ROUND ? rna_tf32(v) : v;
    }
}

// ---------------- Transpose + tf32-round weights: W[K,N] -> Wt[N,K] ----------------
__global__ void transw_kernel(const float* __restrict__ W,
                              float* __restrict__ Wt, int K, int N) {
    __shared__ float tile[32][33];
    int n0 = blockIdx.x * 32, k0 = blockIdx.y * 32;
    int tx = threadIdx.x, ty = threadIdx.y;   // (32, 8)
    #pragma unroll
    for (int i = 0; i < 32; i += 8)
        tile[ty + i][tx] = W[(size_t)(k0 + ty + i) * N + n0 + tx];
    __syncthreads();
    #pragma unroll
    for (int i = 0; i < 32; i += 8) {
        int nn = ty + i;
        Wt[(size_t)(n0 + nn) * K + k0 + tx] = rna_tf32(tile[tx][nn]);
    }
}

// ========= tf32 mma.sync GEMM: 128 threads, warp tile 64x64, BK=32, 3 stages =========
// C[M,N] = A[M,K] fp32 row-major @ Bt[N,K]^T (both tf32-rounded)
// EPI: 0 = store, 1 = residual add, 2 = gelu + tf32-round
#define BG_STAGE  32768                 // 16KB A + 16KB B (fp32, 128 rows x 128B)
#define BG_SMEM   (3 * BG_STAGE)        // 96KB -> 2 CTAs/SM

__device__ __forceinline__ unsigned swz(unsigned o) { return o ^ ((o >> 3) & 0x70); }

__device__ __forceinline__ void ldsm4(unsigned addr, unsigned& r0, unsigned& r1,
                                      unsigned& r2, unsigned& r3) {
    asm volatile("ldmatrix.sync.aligned.m8n8.x4.shared.b16 {%0,%1,%2,%3}, [%4];\n"
                 : "=r"(r0), "=r"(r1), "=r"(r2), "=r"(r3) : "r"(addr));
}
__device__ __forceinline__ void mma16888(float* c, unsigned a0, unsigned a1,
                                         unsigned a2, unsigned a3,
                                         unsigned b0, unsigned b1) {
    asm volatile(
        "mma.sync.aligned.m16n8k8.row.col.f32.tf32.tf32.f32 "
        "{%0,%1,%2,%3},{%4,%5,%6,%7},{%8,%9},{%0,%1,%2,%3};\n"
        : "+f"(c[0]), "+f"(c[1]), "+f"(c[2]), "+f"(c[3])
        : "r"(a0), "r"(a1), "r"(a2), "r"(a3), "r"(b0), "r"(b1));
}
__device__ __forceinline__ void cpasync16(unsigned saddr, const void* g) {
    asm volatile("cp.async.cg.shared.global [%0], [%1], 16;\n" :: "r"(saddr), "l"(g));
}

// load 128-row x 32-float tile (128B rows, SW128) with 128 threads (16KB)
__device__ __forceinline__ void load_tile32f(const float* gbase, unsigned sbase,
                                             int ld, int k0) {
    int t = threadIdx.x;
    #pragma unroll
    for (int i = 0; i < 8; i++) {
        int c = t + i * 128;              // 0..1023
        int row = c >> 3, seg = c & 7;
        cpasync16(sbase + swz((unsigned)(row * 128 + seg * 16)),
                  gbase + (size_t)row * ld + k0 + seg * 4);
    }
}

// frag fetch: k8-slice offset (bits 5-6, {0,32,64,96}) applied via XOR
__device__ __forceinline__ void ldsm_frags(const unsigned aA[4], const unsigned bA[4],
                                           unsigned off,
                                           unsigned fa[4][4], unsigned fb[4][4]) {
    #pragma unroll
    for (int mi = 0; mi < 4; mi++)
        ldsm4(aA[mi] ^ off, fa[mi][0], fa[mi][1], fa[mi][2], fa[mi][3]);
    #pragma unroll
    for (int np = 0; np < 4; np++)
        ldsm4(bA[np] ^ off, fb[np][0], fb[np][1], fb[np][2], fb[np][3]);
}

__device__ __forceinline__ void mma_tile(float acc[4][8][4],
                                         unsigned fa[4][4], unsigned fb[4][4]) {
    #pragma unroll
    for (int mi = 0; mi < 4; mi++)
        #pragma unroll
        for (int ni = 0; ni < 8; ni++) {
            unsigned b0 = fb[ni >> 1][ni & 1];
            unsigned b1 = fb[ni >> 1][2 + (ni & 1)];
            mma16888(acc[mi][ni], fa[mi][0], fa[mi][1], fa[mi][2], fa[mi][3], b0, b1);
        }
}

__device__ __forceinline__ float gelu_f(float xx) {
    return 0.5f * xx * (1.0f + tanhf(0.7978845608028654f *
                                     (xx + 0.044715f * xx * xx * xx)));
}

template<int EPI>
__global__ void __launch_bounds__(128, 2)
bgemm_kernel(const float* __restrict__ A,
             const float* __restrict__ Bt,
             float* __restrict__ C,
             int M, int N, int K) {
    extern __shared__ __align__(128) char smem[];
    unsigned sbase = (unsigned)__cvta_generic_to_shared(smem);

    const int tid = threadIdx.x, lane = tid & 31, warp = tid >> 5;  // 4 warps
    const int warpM = warp & 1, warpN = warp >> 1;                  // 2x2
    const int rowBase = blockIdx.x * 128;
    const int colBase = blockIdx.y * 128;
    const float* Ab = A  + (size_t)rowBase * K;
    const float* Bb = Bt + (size_t)colBase * K;

    float acc[4][8][4];
    #pragma unroll
    for (int i = 0; i < 4; i++)
        #pragma unroll
        for (int j = 0; j < 8; j++)
            #pragma unroll
            for (int r = 0; r < 4; r++) acc[i][j][r] = 0.f;

    const int KT = K >> 5;
    #pragma unroll
    for (int s = 0; s < 2; s++) {                 // prologue: 2 stages
        unsigned st = sbase + s * BG_STAGE;
        load_tile32f(Ab, st, K, s << 5);
        load_tile32f(Bb, st + 16384, K, s << 5);
        asm volatile("cp.async.commit_group;\n");
    }

    // ldsm base addresses at k8-slice 0 (128B rows); slice via XOR {32,64,96}
    unsigned aAB[4], bAB[4];
    #pragma unroll
    for (int mi = 0; mi < 4; mi++) {
        int row = warpM * 64 + mi * 16 + (lane & 15);
        aAB[mi] = swz((unsigned)(row * 128 + (lane >> 4) * 16));
    }
    #pragma unroll
    for (int np = 0; np < 4; np++) {
        int rown = warpN * 64 + np * 16 + (lane & 15);
        bAB[np] = 16384u + swz((unsigned)(rown * 128 + (lane >> 4) * 16));
    }

    unsigned fa[4][4], fb[4][4];
    int buf = 0;

    for (int kt = 0; kt < KT; kt++) {
        asm volatile("cp.async.wait_group 1;\n");
        __syncthreads();

        unsigned stg = sbase + (unsigned)buf * BG_STAGE;
        unsigned aA[4] = { stg + aAB[0], stg + aAB[1], stg + aAB[2], stg + aAB[3] };
        unsigned bA[4] = { stg + bAB[0], stg + bAB[1], stg + bAB[2], stg + bAB[3] };

        ldsm_frags(aA, bA, 0, fa, fb);

        const int next = kt + 2;
        if (next < KT) {
            int nb = buf + 2; if (nb >= 3) nb -= 3;
            unsigned ns = sbase + (unsigned)nb * BG_STAGE;
            load_tile32f(Ab, ns, K, next << 5);
            load_tile32f(Bb, ns + 16384, K, next << 5);
        }
        asm volatile("cp.async.commit_group;\n");

        mma_tile(acc, fa, fb);
        ldsm_frags(aA, bA, 32, fa, fb);
        mma_tile(acc, fa, fb);
        ldsm_frags(aA, bA, 64, fa, fb);
        mma_tile(acc, fa, fb);
        ldsm_frags(aA, bA, 96, fa, fb);
        mma_tile(acc, fa, fb);

        if (++buf == 3) buf = 0;
    }

    // epilogue
    #pragma unroll
    for (int mi = 0; mi < 4; mi++)
        #pragma unroll
        for (int ni = 0; ni < 8; ni++) {
            int row = rowBase + warpM * 64 + mi * 16 + (lane >> 2);
            int col = colBase + warpN * 64 + ni * 8 + 2 * (lane & 3);
            float v0 = acc[mi][ni][0], v1 = acc[mi][ni][1];
            float v2 = acc[mi][ni][2], v3 = acc[mi][ni][3];
            float* p = C + (size_t)row * N + col;
            float* q = C + (size_t)(row + 8) * N + col;
            if (EPI == 1) { v0 += p[0]; v1 += p[1]; v2 += q[0]; v3 += q[1]; }
            if (EPI == 2) {
                v0 = rna_tf32(gelu_f(v0)); v1 = rna_tf32(gelu_f(v1));
                v2 = rna_tf32(gelu_f(v2)); v3 = rna_tf32(gelu_f(v3));
            }
            *(float2*)p = make_float2(v0, v1);
            *(float2*)q = make_float2(v2, v3);
        }
}

// ---------------- Tiled causal attention: 64 q-rows per block ----------------
#define ATT_SMEM ((64 * 128 + 32 * 132 + 32 * 128) * 4)

__global__ void __launch_bounds__(256)
attn_kernel(const float* __restrict__ qkv,
            const int* __restrict__ mask,
            float* __restrict__ ao) {
    extern __shared__ float asmem[];
    float* Qs = asmem;                 // [64][128]
    float* Kc = asmem + 64 * 128;      // [32][132]
    float* Vc = Kc + 32 * 132;         // [32][128]

    const int tid = threadIdx.x, lane = tid & 31, warp = tid >> 5;
    const int q0 = blockIdx.x * 64;
    const int h  = blockIdx.y;
    const int b  = blockIdx.z;
    const size_t base = (size_t)b * SEQ * TD;

    #pragma unroll
    for (int i = 0; i < 8; i++) {
        int idx = tid + i * 256;
        int r = idx >> 5, c = (idx & 31) * 4;
        *(float4*)&Qs[r * 128 + c] =
            *(const float4*)&qkv[base + (size_t)(q0 + r) * TD + h * DH + c];
    }

    const int qr0 = q0 + warp * 8;
    float m[8], l[8];
    float4 o[8];
    #pragma unroll
    for (int r = 0; r < 8; r++) {
        m[r] = -1e30f; l[r] = 0.f;
        o[r] = make_float4(0.f, 0.f, 0.f, 0.f);
    }

    const int jmax = q0 + 63;
    for (int j0 = 0; j0 <= jmax; j0 += 32) {
        __syncthreads();
        #pragma unroll
        for (int i = 0; i < 4; i++) {
            int idx = tid + i * 256;
            int r = idx >> 5, c = (idx & 31) * 4;
            const float* src = qkv + base + (size_t)(j0 + r) * TD + h * DH + c;
            *(float4*)&Kc[r * 132 + c] = *(const float4*)(src + D);
            *(float4*)&Vc[r * 128 + c] = *(const float4*)(src + 2 * D);
        }
        __syncthreads();

        const int j = j0 + lane;
        const float mbias = (mask[b * SEQ + j] == 0) ? NEGB : 0.f;

        float dot[8];
        #pragma unroll
        for (int r = 0; r < 8; r++) dot[r] = 0.f;
        #pragma unroll 2
        for (int d = 0; d < DH; d += 4) {
            float4 kv = *(const float4*)&Kc[lane * 132 + d];
            #pragma unroll
            for (int r = 0; r < 8; r++) {
                float4 qv = *(const float4*)&Qs[(warp * 8 + r) * 128 + d];
                dot[r] = fmaf(kv.x, qv.x, dot[r]);
                dot[r] = fmaf(kv.y, qv.y, dot[r]);
                dot[r] = fmaf(kv.z, qv.z, dot[r]);
                dot[r] = fmaf(kv.w, qv.w, dot[r]);
            }
        }

        float p[8];
        #pragma unroll
        for (int r = 0; r < 8; r++) {
            float s = (j <= qr0 + r) ? (dot[r] * SCALE + mbias) : -1e30f;
            float cmax = s;
            #pragma unroll
            for (int off = 16; off > 0; off >>= 1)
                cmax = fmaxf(cmax, __shfl_xor_sync(0xffffffffu, cmax, off));
            float newm = fmaxf(m[r], cmax);
            float corr = expf(m[r] - newm);
            p[r] = expf(s - newm);
            float psum = p[r];
            #pragma unroll
            for (int off = 16; off > 0; off >>= 1)
                psum += __shfl_xor_sync(0xffffffffu, psum, off);
            l[r] = l[r] * corr + psum;
            o[r].x *= corr; o[r].y *= corr; o[r].z *= corr; o[r].w *= corr;
            m[r] = newm;
        }

        #pragma unroll 2
        for (int jj = 0; jj < 32; jj++) {
            float4 v = *(const float4*)&Vc[jj * 128 + lane * 4];
            #pragma unroll
            for (int r = 0; r < 8; r++) {
                float pj = __shfl_sync(0xffffffffu, p[r], jj);
                o[r].x = fmaf(pj, v.x, o[r].x);
                o[r].y = fmaf(pj, v.y, o[r].y);
                o[r].z = fmaf(pj, v.z, o[r].z);
                o[r].w = fmaf(pj, v.w, o[r].w);
            }
        }
    }

    const int col = h * DH + lane * 4;
    #pragma unroll
    for (int r = 0; r < 8; r++) {
        const float inv = 1.f / l[r];
        float4 w;
        w.x = rna_tf32(o[r].x * inv);
        w.y = rna_tf32(o[r].y * inv);
        w.z = rna_tf32(o[r].z * inv);
        w.w = rna_tf32(o[r].w * inv);
        *(float4*)&ao[(size_t)(b * SEQ + qr0 + r) * D + col] = w;
    }
}

// ---------------- Pool + head ----------------
__global__ void meanpool_kernel(const float* __restrict__ hs,
                                const int* __restrict__ mask,
                                float* __restrict__ mean) {
    int idx = blockIdx.x * blockDim.x + threadIdx.x;
    int b = idx / D;
    int d = idx % D;
    float acc = 0.f, msum = 0.f;
    const float* hb = hs + (size_t)b * SEQ * D + d;
    const int* mb = mask + b * SEQ;
    for (int s = 0; s < SEQ; s++) {
        float mf = (float)mb[s];
        acc = fmaf(mf, hb[(size_t)s * D], acc);
        msum += mf;
    }
    mean[idx] = acc / fmaxf(msum, 1e-9f);
}

__global__ void head1_kernel(const float* __restrict__ mean,
                             const float* __restrict__ Wc1,
                             const float* __restrict__ bc1,
                             float* __restrict__ t) {
    int idx = blockIdx.x * blockDim.x + threadIdx.x;
    int b = idx / D;
    int j = idx % D;
    float acc = bc1[j];
    const float* mb = mean + (size_t)b * D;
    for (int k = 0; k < D; k++)
        acc = fmaf(mb[k], Wc1[(size_t)k * D + j], acc);
    t[idx] = tanhf(acc);
}

__global__ void head2_kernel(const float* __restrict__ t,
                             const float* __restrict__ Wc2,
                             const float* __restrict__ bc2,
                             float* __restrict__ out) {
    __shared__ float red[256];
    __shared__ float logits[4];
    const int tid = threadIdx.x;
    float part[4] = {0.f, 0.f, 0.f, 0.f};
    for (int j = tid; j < D; j += 256) {
        float t0 = t[j], t1 = t[D + j];
        float w0 = Wc2[2 * j], w1 = Wc2[2 * j + 1];
        part[0] = fmaf(t0, w0, part[0]);
        part[1] = fmaf(t0, w1, part[1]);
        part[2] = fmaf(t1, w0, part[2]);
        part[3] = fmaf(t1, w1, part[3]);
    }
    for (int c = 0; c < 4; c++) {
        __syncthreads();
        red[tid] = part[c]; __syncthreads();
        for (int st = 128; st > 0; st >>= 1) {
            if (tid < st) red[tid] += red[tid + st];
            __syncthreads();
        }
        if (tid == 0) logits[c] = red[0] + bc2[c & 1];
    }
    __syncthreads();
    if (tid == 0) {
        for (int b = 0; b < BATCH; b++) {
            float l0 = logits[2 * b], l1 = logits[2 * b + 1];
            float m = fmaxf(l0, l1);
            float e0 = expf(l0 - m), e1 = expf(l1 - m);
            out[b] = e1 / (e0 + e1);
        }
    }
}

// ---------------- Launch ----------------
extern "C" void kernel_launch(void* const* d_in, const int* in_sizes, int n_in,
                              void* d_out, int out_size) {
    const int*   ids   = (const int*)d_in[0];
    const int*   amask = (const int*)d_in[1];
    const float* emb   = (const float*)d_in[2];
    const float* ln1_g = (const float*)d_in[3];
    const float* ln1_b = (const float*)d_in[4];
    const float* Wqkv  = (const float*)d_in[5];
    const float* Wo    = (const float*)d_in[6];
    const float* ln2_g = (const float*)d_in[7];
    const float* ln2_b = (const float*)d_in[8];
    const float* W1    = (const float*)d_in[9];
    const float* W2    = (const float*)d_in[10];
    const float* lnf_g = (const float*)d_in[11];
    const float* lnf_b = (const float*)d_in[12];
    const float* Wc1   = (const float*)d_in[13];
    const float* bc1   = (const float*)d_in[14];
    const float* Wc2   = (const float*)d_in[15];
    const float* bc2   = (const float*)d_in[16];
    float* out = (float*)d_out;

    float *x, *h, *qkv, *ao, *ff, *mean, *t;
    float *wqkvT, *woT, *w1T, *w2T;
    cudaGetSymbolAddress((void**)&x,    g_x);
    cudaGetSymbolAddress((void**)&h,    g_h);
    cudaGetSymbolAddress((void**)&qkv,  g_qkv);
    cudaGetSymbolAddress((void**)&ao,   g_ao);
    cudaGetSymbolAddress((void**)&ff,   g_ff);
    cudaGetSymbolAddress((void**)&mean, g_mean);
    cudaGetSymbolAddress((void**)&t,    g_t);
    cudaGetSymbolAddress((void**)&wqkvT, g_wqkvT);
    cudaGetSymbolAddress((void**)&woT,   g_woT);
    cudaGetSymbolAddress((void**)&w1T,   g_w1T);
    cudaGetSymbolAddress((void**)&w2T,   g_w2T);

    cudaFuncSetAttribute(bgemm_kernel<0>,
                         cudaFuncAttributeMaxDynamicSharedMemorySize, BG_SMEM);
    cudaFuncSetAttribute(bgemm_kernel<1>,
                         cudaFuncAttributeMaxDynamicSharedMemorySize, BG_SMEM);
    cudaFuncSetAttribute(bgemm_kernel<2>,
                         cudaFuncAttributeMaxDynamicSharedMemorySize, BG_SMEM);
    cudaFuncSetAttribute(attn_kernel,
                         cudaFuncAttributeMaxDynamicSharedMemorySize, ATT_SMEM);

    embed_kernel<<<(BS * D) / 256, 256>>>(ids, emb, x);

    for (int l = 0; l < LAYERS; l++) {
        // attention block
        ln_kernel<1><<<BS, 256>>>(x, ln1_g + (size_t)l * D, ln1_b + (size_t)l * D, h);
        transw_kernel<<<dim3(TD / 32, D / 32), dim3(32, 8)>>>(
            Wqkv + (size_t)l * D * TD, wqkvT, D, TD);
        bgemm_kernel<0><<<dim3(BS / 128, TD / 128), 128, BG_SMEM>>>(
            h, wqkvT, qkv, BS, TD, D);
        attn_kernel<<<dim3(SEQ / 64, H, BATCH), 256, ATT_SMEM>>>(qkv, amask, ao);
        transw_kernel<<<dim3(D / 32, D / 32), dim3(32, 8)>>>(
            Wo + (size_t)l * D * D, woT, D, D);
        bgemm_kernel<1><<<dim3(BS / 128, D / 128), 128, BG_SMEM>>>(
            ao, woT, x, BS, D, D);
        // mlp block
        ln_kernel<1><<<BS, 256>>>(x, ln2_g + (size_t)l * D, ln2_b + (size_t)l * D, h);
        transw_kernel<<<dim3(FF / 32, D / 32), dim3(32, 8)>>>(
            W1 + (size_t)l * D * FF, w1T, D, FF);
        bgemm_kernel<2><<<dim3(BS / 128, FF / 128), 128, BG_SMEM>>>(
            h, w1T, ff, BS, FF, D);
        transw_kernel<<<dim3(D / 32, FF / 32), dim3(32, 8)>>>(
            W2 + (size_t)l * FF * D, w2T, FF, D);
        bgemm_kernel<1><<<dim3(BS / 128, D / 128), 128, BG_SMEM>>>(
            ff, w2T, x, BS, D, FF);
    }

    ln_kernel<0><<<BS, 256>>>(x, lnf_g, lnf_b, h);
    meanpool_kernel<<<(BATCH * D) / 256, 256>>>(h, amask, mean);
    head1_kernel<<<(BATCH * D) / 256, 256>>>(mean, Wc1, bc1, t);
    head2_kernel<<<1, 256>>>(t, Wc2, bc2, out);
}

// round 12
// speedup vs baseline: 3.7426x; 1.4308x over previous
#include <cuda_runtime.h>
#include <cuda_fp16.h>
#include <math.h>
#include <stdint.h>

// ---------------- Problem constants ----------------
#define LAYERS 2
#define D      2048
#define H      16
#define FF     8192
#define BATCH  2
#define SEQ    1024
#define DH     128
#define TD     (3 * D)
#define BS     (BATCH * SEQ)
#define NEGB   (-1e9f)
#define SCALE  0.08838834764831845f
#define WS     512.0f        // weight scale (keeps fp16 weights normal)
#define WS_INV (1.0f / 512.0f)

// ---------------- Scratch (static device globals) ----------------
__device__ float g_x   [BS * D];
__device__ float g_h   [BS * D];     // final ln output (fp32)
__device__ float g_qkv [BS * TD];
__device__ float g_mean[BATCH * D];
__device__ float g_t   [BATCH * D];
// fp16 activation buffers (GEMM A operands)
__device__ __half g_ha_d[BS * D];    // ln / attention outputs
__device__ __half g_ha_f[BS * FF];   // gelu outputs
// fp16 transposed scaled weights: Wt[N][K] = W^T * WS
__device__ __half g_wqkvT[TD * D];
__device__ __half g_woT  [D * D];
__device__ __half g_w1T  [FF * D];
__device__ __half g_w2T  [D * FF];

// ---------------- Embedding gather ----------------
__global__ void embed_kernel(const int* __restrict__ ids,
                             const float* __restrict__ emb,
                             float* __restrict__ x) {
    int idx = blockIdx.x * blockDim.x + threadIdx.x;
    int tok = ids[idx / D];
    x[idx] = emb[(size_t)tok * D + (idx % D)];
}

// ---------------- LayerNorm; HOUT=1 writes fp16, else fp32 ----------------
template<int HOUT>
__global__ void ln_kernel(const float* __restrict__ x,
                          const float* __restrict__ g,
                          const float* __restrict__ b,
                          float* __restrict__ outf,
                          __half* __restrict__ outh) {
    __shared__ float row[D];
    __shared__ float red[256];
    const int tid = threadIdx.x;
    const float* xr = x + (size_t)blockIdx.x * D;

    float s = 0.f;
    for (int i = tid; i < D; i += 256) { float v = xr[i]; row[i] = v; s += v; }
    red[tid] = s; __syncthreads();
    for (int st = 128; st > 0; st >>= 1) {
        if (tid < st) red[tid] += red[tid + st];
        __syncthreads();
    }
    const float mean = red[0] * (1.0f / D);
    __syncthreads();

    float s2 = 0.f;
    for (int i = tid; i < D; i += 256) { float v = row[i] - mean; s2 += v * v; }
    red[tid] = s2; __syncthreads();
    for (int st = 128; st > 0; st >>= 1) {
        if (tid < st) red[tid] += red[tid + st];
        __syncthreads();
    }
    const float rstd = rsqrtf(red[0] * (1.0f / D) + 1e-5f);

    if (HOUT) {
        __half* orow = outh + (size_t)blockIdx.x * D;
        for (int i = tid; i < D; i += 256)
            orow[i] = __float2half_rn((row[i] - mean) * rstd * g[i] + b[i]);
    } else {
        float* orow = outf + (size_t)blockIdx.x * D;
        for (int i = tid; i < D; i += 256)
            orow[i] = (row[i] - mean) * rstd * g[i] + b[i];
    }
}

// ---------------- Transpose + scale weights: W[K,N] fp32 -> Wt[N,K] fp16*WS ----------------
__global__ void transw_kernel(const float* __restrict__ W,
                              __half* __restrict__ Wt, int K, int N) {
    __shared__ float tile[32][33];
    int n0 = blockIdx.x * 32, k0 = blockIdx.y * 32;
    int tx = threadIdx.x, ty = threadIdx.y;   // (32, 8)
    #pragma unroll
    for (int i = 0; i < 32; i += 8)
        tile[ty + i][tx] = W[(size_t)(k0 + ty + i) * N + n0 + tx];
    __syncthreads();
    #pragma unroll
    for (int i = 0; i < 32; i += 8) {
        int nn = ty + i;
        Wt[(size_t)(n0 + nn) * K + k0 + tx] = __float2half_rn(tile[tx][nn] * WS);
    }
}

// ========= fp16 mma.sync GEMM: 128 threads, warp tile 64x64, BK=32, 4 stages =========
// C[M,N] = (A[M,K] fp16 @ Wt[N,K]^T fp16) * WS_INV
// EPI: 0 = store fp32, 1 = residual add fp32, 2 = gelu -> fp16
#define BG_STAGE  16384                 // 8KB A + 8KB B
#define BG_SMEM   (4 * BG_STAGE)        // 64KB -> 2 CTAs/SM

__device__ __forceinline__ unsigned swz(unsigned o) { return o ^ ((o >> 3) & 0x70); }

__device__ __forceinline__ void ldsm4(unsigned addr, unsigned& r0, unsigned& r1,
                                      unsigned& r2, unsigned& r3) {
    asm volatile("ldmatrix.sync.aligned.m8n8.x4.shared.b16 {%0,%1,%2,%3}, [%4];\n"
                 : "=r"(r0), "=r"(r1), "=r"(r2), "=r"(r3) : "r"(addr));
}
__device__ __forceinline__ void mma16816(float* c, unsigned a0, unsigned a1,
                                         unsigned a2, unsigned a3,
                                         unsigned b0, unsigned b1) {
    asm volatile(
        "mma.sync.aligned.m16n8k16.row.col.f32.f16.f16.f32 "
        "{%0,%1,%2,%3},{%4,%5,%6,%7},{%8,%9},{%0,%1,%2,%3};\n"
        : "+f"(c[0]), "+f"(c[1]), "+f"(c[2]), "+f"(c[3])
        : "r"(a0), "r"(a1), "r"(a2), "r"(a3), "r"(b0), "r"(b1));
}
__device__ __forceinline__ void cpasync16(unsigned saddr, const void* g) {
    asm volatile("cp.async.cg.shared.global [%0], [%1], 16;\n" :: "r"(saddr), "l"(g));
}

// load 128-row x 32-col fp16 tile into paired-row swizzled smem (8KB), 128 threads
__device__ __forceinline__ void load_tile(const __half* gbase, unsigned sbase,
                                          int ld, int k0) {
    int t = threadIdx.x;
    #pragma unroll
    for (int i = 0; i < 4; i++) {
        int c = t + i * 128;              // 0..511
        int row = c >> 2, seg = c & 3;
        unsigned so = swz((unsigned)((row >> 1) * 128 + (row & 1) * 64 + seg * 16));
        cpasync16(sbase + so, gbase + (size_t)row * ld + k0 + seg * 8);
    }
}

// frag fetch: k16-slice offset (bit 5 only) applied via XOR on swizzled base
__device__ __forceinline__ void ldsm_frags(const unsigned aA[4], const unsigned bA[4],
                                           unsigned off,
                                           unsigned fa[4][4], unsigned fb[4][4]) {
    #pragma unroll
    for (int mi = 0; mi < 4; mi++)
        ldsm4(aA[mi] ^ off, fa[mi][0], fa[mi][1], fa[mi][2], fa[mi][3]);
    #pragma unroll
    for (int np = 0; np < 4; np++)
        ldsm4(bA[np] ^ off, fb[np][0], fb[np][1], fb[np][2], fb[np][3]);
}

__device__ __forceinline__ void mma_tile(float acc[4][8][4],
                                         unsigned fa[4][4], unsigned fb[4][4]) {
    #pragma unroll
    for (int mi = 0; mi < 4; mi++)
        #pragma unroll
        for (int ni = 0; ni < 8; ni++) {
            unsigned b0 = fb[ni >> 1][ni & 1];
            unsigned b1 = fb[ni >> 1][2 + (ni & 1)];
            mma16816(acc[mi][ni], fa[mi][0], fa[mi][1], fa[mi][2], fa[mi][3], b0, b1);
        }
}

__device__ __forceinline__ float gelu_f(float xx) {
    return 0.5f * xx * (1.0f + tanhf(0.7978845608028654f *
                                     (xx + 0.044715f * xx * xx * xx)));
}

template<int EPI>
__global__ void __launch_bounds__(128, 2)
bgemm_kernel(const __half* __restrict__ A,
             const __half* __restrict__ Bt,
             float* __restrict__ C,
             __half* __restrict__ Hout,
             int M, int N, int K) {
    extern __shared__ __align__(128) char smem[];
    unsigned sbase = (unsigned)__cvta_generic_to_shared(smem);

    const int tid = threadIdx.x, lane = tid & 31, warp = tid >> 5;  // 4 warps
    const int warpM = warp & 1, warpN = warp >> 1;                  // 2x2
    const int rowBase = blockIdx.x * 128;
    const int colBase = blockIdx.y * 128;
    const __half* Ab = A  + (size_t)rowBase * K;
    const __half* Bb = Bt + (size_t)colBase * K;

    float acc[4][8][4];
    #pragma unroll
    for (int i = 0; i < 4; i++)
        #pragma unroll
        for (int j = 0; j < 8; j++)
            #pragma unroll
            for (int r = 0; r < 4; r++) acc[i][j][r] = 0.f;

    const int KT = K >> 5;
    #pragma unroll
    for (int s = 0; s < 3; s++) {                 // prologue: 3 stages
        unsigned st = sbase + s * BG_STAGE;
        load_tile(Ab, st, K, s << 5);
        load_tile(Bb, st + 8192, K, s << 5);
        asm volatile("cp.async.commit_group;\n");
    }

    // ldsm base addresses at k16-slice 0 (paired-row); slice via XOR ^32
    unsigned aAB[4], bAB[4];
    #pragma unroll
    for (int mi = 0; mi < 4; mi++) {
        int row = warpM * 64 + mi * 16 + (lane & 15);
        aAB[mi] = swz((unsigned)((row >> 1) * 128 + (row & 1) * 64 + (lane >> 4) * 16));
    }
    #pragma unroll
    for (int np = 0; np < 4; np++) {
        int rown = warpN * 64 + np * 16 + (lane & 15);
        bAB[np] = 8192u + swz((unsigned)((rown >> 1) * 128 + (rown & 1) * 64 + (lane >> 4) * 16));
    }

    unsigned fa[4][4], fb[4][4];

    for (int kt = 0; kt < KT; kt++) {
        asm volatile("cp.async.wait_group 2;\n");
        __syncthreads();

        unsigned stg = sbase + (unsigned)(kt & 3) * BG_STAGE;
        unsigned aA[4] = { stg + aAB[0], stg + aAB[1], stg + aAB[2], stg + aAB[3] };
        unsigned bA[4] = { stg + bAB[0], stg + bAB[1], stg + bAB[2], stg + bAB[3] };

        ldsm_frags(aA, bA, 0, fa, fb);

        const int next = kt + 3;
        if (next < KT) {
            unsigned ns = sbase + (unsigned)(next & 3) * BG_STAGE;
            load_tile(Ab, ns, K, next << 5);
            load_tile(Bb, ns + 8192, K, next << 5);
        }
        asm volatile("cp.async.commit_group;\n");

        mma_tile(acc, fa, fb);
        ldsm_frags(aA, bA, 32, fa, fb);
        mma_tile(acc, fa, fb);
    }

    // epilogue (un-scale weights by WS_INV)
    #pragma unroll
    for (int mi = 0; mi < 4; mi++)
        #pragma unroll
        for (int ni = 0; ni < 8; ni++) {
            int row = rowBase + warpM * 64 + mi * 16 + (lane >> 2);
            int col = colBase + warpN * 64 + ni * 8 + 2 * (lane & 3);
            float v0 = acc[mi][ni][0] * WS_INV, v1 = acc[mi][ni][1] * WS_INV;
            float v2 = acc[mi][ni][2] * WS_INV, v3 = acc[mi][ni][3] * WS_INV;
            if (EPI == 2) {
                __half2* hp = (__half2*)(Hout + (size_t)row * N + col);
                __half2* hq = (__half2*)(Hout + (size_t)(row + 8) * N + col);
                *hp = __floats2half2_rn(gelu_f(v0), gelu_f(v1));
                *hq = __floats2half2_rn(gelu_f(v2), gelu_f(v3));
            } else {
                float* p = C + (size_t)row * N + col;
                float* q = C + (size_t)(row + 8) * N + col;
                if (EPI == 1) { v0 += p[0]; v1 += p[1]; v2 += q[0]; v3 += q[1]; }
                *(float2*)p = make_float2(v0, v1);
                *(float2*)q = make_float2(v2, v3);
            }
        }
}

// ---------------- Tiled causal attention: 64 q-rows per block, fp16 output ----------------
#define ATT_SMEM ((64 * 128 + 32 * 132 + 32 * 128) * 4)

__global__ void __launch_bounds__(256)
attn_kernel(const float* __restrict__ qkv,
            const int* __restrict__ mask,
            __half* __restrict__ ao) {
    extern __shared__ float asmem[];
    float* Qs = asmem;                 // [64][128]
    float* Kc = asmem + 64 * 128;      // [32][132]
    float* Vc = Kc + 32 * 132;         // [32][128]

    const int tid = threadIdx.x, lane = tid & 31, warp = tid >> 5;
    const int q0 = blockIdx.x * 64;
    const int h  = blockIdx.y;
    const int b  = blockIdx.z;
    const size_t base = (size_t)b * SEQ * TD;

    #pragma unroll
    for (int i = 0; i < 8; i++) {
        int idx = tid + i * 256;
        int r = idx >> 5, c = (idx & 31) * 4;
        *(float4*)&Qs[r * 128 + c] =
            *(const float4*)&qkv[base + (size_t)(q0 + r) * TD + h * DH + c];
    }

    const int qr0 = q0 + warp * 8;
    float m[8], l[8];
    float4 o[8];
    #pragma unroll
    for (int r = 0; r < 8; r++) {
        m[r] = -1e30f; l[r] = 0.f;
        o[r] = make_float4(0.f, 0.f, 0.f, 0.f);
    }

    const int jmax = q0 + 63;
    for (int j0 = 0; j0 <= jmax; j0 += 32) {
        __syncthreads();
        #pragma unroll
        for (int i = 0; i < 4; i++) {
            int idx = tid + i * 256;
            int r = idx >> 5, c = (idx & 31) * 4;
            const float* src = qkv + base + (size_t)(j0 + r) * TD + h * DH + c;
            *(float4*)&Kc[r * 132 + c] = *(const float4*)(src + D);
            *(float4*)&Vc[r * 128 + c] = *(const float4*)(src + 2 * D);
        }
        __syncthreads();

        const int j = j0 + lane;
        const float mbias = (mask[b * SEQ + j] == 0) ? NEGB : 0.f;

        float dot[8];
        #pragma unroll
        for (int r = 0; r < 8; r++) dot[r] = 0.f;
        #pragma unroll 2
        for (int d = 0; d < DH; d += 4) {
            float4 kv = *(const float4*)&Kc[lane * 132 + d];
            #pragma unroll
            for (int r = 0; r < 8; r++) {
                float4 qv = *(const float4*)&Qs[(warp * 8 + r) * 128 + d];
                dot[r] = fmaf(kv.x, qv.x, dot[r]);
                dot[r] = fmaf(kv.y, qv.y, dot[r]);
                dot[r] = fmaf(kv.z, qv.z, dot[r]);
                dot[r] = fmaf(kv.w, qv.w, dot[r]);
            }
        }

        float p[8];
        #pragma unroll
        for (int r = 0; r < 8; r++) {
            float s = (j <= qr0 + r) ? (dot[r] * SCALE + mbias) : -1e30f;
            float cmax = s;
            #pragma unroll
            for (int off = 16; off > 0; off >>= 1)
                cmax = fmaxf(cmax, __shfl_xor_sync(0xffffffffu, cmax, off));
            float newm = fmaxf(m[r], cmax);
            float corr = expf(m[r] - newm);
            p[r] = expf(s - newm);
            float psum = p[r];
            #pragma unroll
            for (int off = 16; off > 0; off >>= 1)
                psum += __shfl_xor_sync(0xffffffffu, psum, off);
            l[r] = l[r] * corr + psum;
            o[r].x *= corr; o[r].y *= corr; o[r].z *= corr; o[r].w *= corr;
            m[r] = newm;
        }

        #pragma unroll 2
        for (int jj = 0; jj < 32; jj++) {
            float4 v = *(const float4*)&Vc[jj * 128 + lane * 4];
            #pragma unroll
            for (int r = 0; r < 8; r++) {
                float pj = __shfl_sync(0xffffffffu, p[r], jj);
                o[r].x = fmaf(pj, v.x, o[r].x);
                o[r].y = fmaf(pj, v.y, o[r].y);
                o[r].z = fmaf(pj, v.z, o[r].z);
                o[r].w = fmaf(pj, v.w, o[r].w);
            }
        }
    }

    const int col = h * DH + lane * 4;
    #pragma unroll
    for (int r = 0; r < 8; r++) {
        const float inv = 1.f / l[r];
        __half2* dst = (__half2*)(ao + (size_t)(b * SEQ + qr0 + r) * D + col);
        dst[0] = __floats2half2_rn(o[r].x * inv, o[r].y * inv);
        dst[1] = __floats2half2_rn(o[r].z * inv, o[r].w * inv);
    }
}

// ---------------- Pool + head ----------------
__global__ void meanpool_kernel(const float* __restrict__ hs,
                                const int* __restrict__ mask,
                                float* __restrict__ mean) {
    int idx = blockIdx.x * blockDim.x + threadIdx.x;
    int b = idx / D;
    int d = idx % D;
    float acc = 0.f, msum = 0.f;
    const float* hb = hs + (size_t)b * SEQ * D + d;
    const int* mb = mask + b * SEQ;
    for (int s = 0; s < SEQ; s++) {
        float mf = (float)mb[s];
        acc = fmaf(mf, hb[(size_t)s * D], acc);
        msum += mf;
    }
    mean[idx] = acc / fmaxf(msum, 1e-9f);
}

__global__ void head1_kernel(const float* __restrict__ mean,
                             const float* __restrict__ Wc1,
                             const float* __restrict__ bc1,
                             float* __restrict__ t) {
    int idx = blockIdx.x * blockDim.x + threadIdx.x;
    int b = idx / D;
    int j = idx % D;
    float acc = bc1[j];
    const float* mb = mean + (size_t)b * D;
    for (int k = 0; k < D; k++)
        acc = fmaf(mb[k], Wc1[(size_t)k * D + j], acc);
    t[idx] = tanhf(acc);
}

__global__ void head2_kernel(const float* __restrict__ t,
                             const float* __restrict__ Wc2,
                             const float* __restrict__ bc2,
                             float* __restrict__ out) {
    __shared__ float red[256];
    __shared__ float logits[4];
    const int tid = threadIdx.x;
    float part[4] = {0.f, 0.f, 0.f, 0.f};
    for (int j = tid; j < D; j += 256) {
        float t0 = t[j], t1 = t[D + j];
        float w0 = Wc2[2 * j], w1 = Wc2[2 * j + 1];
        part[0] = fmaf(t0, w0, part[0]);
        part[1] = fmaf(t0, w1, part[1]);
        part[2] = fmaf(t1, w0, part[2]);
        part[3] = fmaf(t1, w1, part[3]);
    }
    for (int c = 0; c < 4; c++) {
        __syncthreads();
        red[tid] = part[c]; __syncthreads();
        for (int st = 128; st > 0; st >>= 1) {
            if (tid < st) red[tid] += red[tid + st];
            __syncthreads();
        }
        if (tid == 0) logits[c] = red[0] + bc2[c & 1];
    }
    __syncthreads();
    if (tid == 0) {
        for (int b = 0; b < BATCH; b++) {
            float l0 = logits[2 * b], l1 = logits[2 * b + 1];
            float m = fmaxf(l0, l1);
            float e0 = expf(l0 - m), e1 = expf(l1 - m);
            out[b] = e1 / (e0 + e1);
        }
    }
}

// ---------------- Launch ----------------
extern "C" void kernel_launch(void* const* d_in, const int* in_sizes, int n_in,
                              void* d_out, int out_size) {
    const int*   ids   = (const int*)d_in[0];
    const int*   amask = (const int*)d_in[1];
    const float* emb   = (const float*)d_in[2];
    const float* ln1_g = (const float*)d_in[3];
    const float* ln1_b = (const float*)d_in[4];
    const float* Wqkv  = (const float*)d_in[5];
    const float* Wo    = (const float*)d_in[6];
    const float* ln2_g = (const float*)d_in[7];
    const float* ln2_b = (const float*)d_in[8];
    const float* W1    = (const float*)d_in[9];
    const float* W2    = (const float*)d_in[10];
    const float* lnf_g = (const float*)d_in[11];
    const float* lnf_b = (const float*)d_in[12];
    const float* Wc1   = (const float*)d_in[13];
    const float* bc1   = (const float*)d_in[14];
    const float* Wc2   = (const float*)d_in[15];
    const float* bc2   = (const float*)d_in[16];
    float* out = (float*)d_out;

    float *x, *h, *qkv, *mean, *t;
    __half *ha_d, *ha_f, *wqkvT, *woT, *w1T, *w2T;
    cudaGetSymbolAddress((void**)&x,    g_x);
    cudaGetSymbolAddress((void**)&h,    g_h);
    cudaGetSymbolAddress((void**)&qkv,  g_qkv);
    cudaGetSymbolAddress((void**)&mean, g_mean);
    cudaGetSymbolAddress((void**)&t,    g_t);
    cudaGetSymbolAddress((void**)&ha_d, g_ha_d);
    cudaGetSymbolAddress((void**)&ha_f, g_ha_f);
    cudaGetSymbolAddress((void**)&wqkvT, g_wqkvT);
    cudaGetSymbolAddress((void**)&woT,   g_woT);
    cudaGetSymbolAddress((void**)&w1T,   g_w1T);
    cudaGetSymbolAddress((void**)&w2T,   g_w2T);

    cudaFuncSetAttribute(bgemm_kernel<0>,
                         cudaFuncAttributeMaxDynamicSharedMemorySize, BG_SMEM);
    cudaFuncSetAttribute(bgemm_kernel<1>,
                         cudaFuncAttributeMaxDynamicSharedMemorySize, BG_SMEM);
    cudaFuncSetAttribute(bgemm_kernel<2>,
                         cudaFuncAttributeMaxDynamicSharedMemorySize, BG_SMEM);
    cudaFuncSetAttribute(attn_kernel,
                         cudaFuncAttributeMaxDynamicSharedMemorySize, ATT_SMEM);

    embed_kernel<<<(BS * D) / 256, 256>>>(ids, emb, x);

    for (int l = 0; l < LAYERS; l++) {
        // attention block
        ln_kernel<1><<<BS, 256>>>(x, ln1_g + (size_t)l * D, ln1_b + (size_t)l * D,
                                  nullptr, ha_d);
        transw_kernel<<<dim3(TD / 32, D / 32), dim3(32, 8)>>>(
            Wqkv + (size_t)l * D * TD, wqkvT, D, TD);
        bgemm_kernel<0><<<dim3(BS / 128, TD / 128), 128, BG_SMEM>>>(
            ha_d, wqkvT, qkv, nullptr, BS, TD, D);
        attn_kernel<<<dim3(SEQ / 64, H, BATCH), 256, ATT_SMEM>>>(qkv, amask, ha_d);
        transw_kernel<<<dim3(D / 32, D / 32), dim3(32, 8)>>>(
            Wo + (size_t)l * D * D, woT, D, D);
        bgemm_kernel<1><<<dim3(BS / 128, D / 128), 128, BG_SMEM>>>(
            ha_d, woT, x, nullptr, BS, D, D);
        // mlp block
        ln_kernel<1><<<BS, 256>>>(x, ln2_g + (size_t)l * D, ln2_b + (size_t)l * D,
                                  nullptr, ha_d);
        transw_kernel<<<dim3(FF / 32, D / 32), dim3(32, 8)>>>(
            W1 + (size_t)l * D * FF, w1T, D, FF);
        bgemm_kernel<2><<<dim3(BS / 128, FF / 128), 128, BG_SMEM>>>(
            ha_d, w1T, nullptr, ha_f, BS, FF, D);
        transw_kernel<<<dim3(D / 32, FF / 32), dim3(32, 8)>>>(
            W2 + (size_t)l * FF * D, w2T, FF, D);
        bgemm_kernel<1><<<dim3(BS / 128, D / 128), 128, BG_SMEM>>>(
            ha_f, w2T, x, nullptr, BS, D, FF);
    }

    ln_kernel<0><<<BS, 256>>>(x, lnf_g, lnf_b, h, nullptr);
    meanpool_kernel<<<(BATCH * D) / 256, 256>>>(h, amask, mean);
    head1_kernel<<<(BATCH * D) / 256, 256>>>(mean, Wc1, bc1, t);
    head2_kernel<<<1, 256>>>(t, Wc2, bc2, out);
}

// round 13
// speedup vs baseline: 5.0651x; 1.3534x over previous
#include <cuda_runtime.h>
#include <cuda_fp16.h>
#include <math.h>
#include <stdint.h>

// ---------------- Problem constants ----------------
#define LAYERS 2
#define D      2048
#define H      16
#define FF     8192
#define BATCH  2
#define SEQ    1024
#define DH     128
#define TD     (3 * D)
#define BS     (BATCH * SEQ)
#define NEGB   (-1e9f)
#define SCALE  0.08838834764831845f
#define WS     512.0f
#define WS_INV (1.0f / 512.0f)

// ---------------- Scratch (static device globals) ----------------
__device__ float g_x   [BS * D];
__device__ float g_h   [BS * D];
__device__ float g_qkv [BS * TD];
__device__ float g_mean[BATCH * D];
__device__ float g_t   [BATCH * D];
// fp16 activation buffers
__device__ __half g_ha_d[BS * D];    // ln outputs / attention outputs
__device__ __half g_ha_f[BS * FF];   // gelu outputs
// fp16 attention operands (head-major)
__device__ __half g_qh[BS * D];      // [b][h][q][d]
__device__ __half g_kh[BS * D];      // [b][h][j][d]
__device__ __half g_vt[BS * D];      // [b][h][d][j]  (V transposed)
// fp16 transposed scaled weights
__device__ __half g_wqkvT[TD * D];
__device__ __half g_woT  [D * D];
__device__ __half g_w1T  [FF * D];
__device__ __half g_w2T  [D * FF];

// ---------------- Embedding gather ----------------
__global__ void embed_kernel(const int* __restrict__ ids,
                             const float* __restrict__ emb,
                             float* __restrict__ x) {
    int idx = blockIdx.x * blockDim.x + threadIdx.x;
    int tok = ids[idx / D];
    x[idx] = emb[(size_t)tok * D + (idx % D)];
}

// ---------------- LayerNorm; HOUT=1 writes fp16 ----------------
template<int HOUT>
__global__ void ln_kernel(const float* __restrict__ x,
                          const float* __restrict__ g,
                          const float* __restrict__ b,
                          float* __restrict__ outf,
                          __half* __restrict__ outh) {
    __shared__ float row[D];
    __shared__ float red[256];
    const int tid = threadIdx.x;
    const float* xr = x + (size_t)blockIdx.x * D;

    float s = 0.f;
    for (int i = tid; i < D; i += 256) { float v = xr[i]; row[i] = v; s += v; }
    red[tid] = s; __syncthreads();
    for (int st = 128; st > 0; st >>= 1) {
        if (tid < st) red[tid] += red[tid + st];
        __syncthreads();
    }
    const float mean = red[0] * (1.0f / D);
    __syncthreads();

    float s2 = 0.f;
    for (int i = tid; i < D; i += 256) { float v = row[i] - mean; s2 += v * v; }
    red[tid] = s2; __syncthreads();
    for (int st = 128; st > 0; st >>= 1) {
        if (tid < st) red[tid] += red[tid + st];
        __syncthreads();
    }
    const float rstd = rsqrtf(red[0] * (1.0f / D) + 1e-5f);

    if (HOUT) {
        __half* orow = outh + (size_t)blockIdx.x * D;
        for (int i = tid; i < D; i += 256)
            orow[i] = __float2half_rn((row[i] - mean) * rstd * g[i] + b[i]);
    } else {
        float* orow = outf + (size_t)blockIdx.x * D;
        for (int i = tid; i < D; i += 256)
            orow[i] = (row[i] - mean) * rstd * g[i] + b[i];
    }
}

// ---------------- Transpose + scale weights ----------------
__global__ void transw_kernel(const float* __restrict__ W,
                              __half* __restrict__ Wt, int K, int N) {
    __shared__ float tile[32][33];
    int n0 = blockIdx.x * 32, k0 = blockIdx.y * 32;
    int tx = threadIdx.x, ty = threadIdx.y;
    #pragma unroll
    for (int i = 0; i < 32; i += 8)
        tile[ty + i][tx] = W[(size_t)(k0 + ty + i) * N + n0 + tx];
    __syncthreads();
    #pragma unroll
    for (int i = 0; i < 32; i += 8) {
        int nn = ty + i;
        Wt[(size_t)(n0 + nn) * K + k0 + tx] = __float2half_rn(tile[tx][nn] * WS);
    }
}

// ---------------- qkv -> fp16 head-major q/k ----------------
__global__ void qkconv_kernel(const float* __restrict__ qkv,
                              __half* __restrict__ qh,
                              __half* __restrict__ kh) {
    int t = blockIdx.x;                  // token
    int b = t / SEQ, sidx = t % SEQ;
    const float* src = qkv + (size_t)t * TD;
    for (int i = threadIdx.x; i < D; i += 256) {
        int h = i >> 7, d = i & 127;
        size_t o = ((size_t)(b * H + h) * SEQ + sidx) * DH + d;
        qh[o] = __float2half_rn(src[i]);
        kh[o] = __float2half_rn(src[D + i]);
    }
}

// ---------------- qkv V part -> fp16 transposed vt[b][h][d][j] ----------------
__global__ void vtrans_kernel(const float* __restrict__ qkv,
                              __half* __restrict__ vt) {
    __shared__ float tile[32][33];
    int j0 = blockIdx.x * 32, d0 = blockIdx.y * 32;
    int bh = blockIdx.z;
    int b = bh / H, h = bh % H;
    int tx = threadIdx.x, ty = threadIdx.y;   // (32, 8)
    #pragma unroll
    for (int i = 0; i < 32; i += 8)
        tile[ty + i][tx] = qkv[(size_t)(b * SEQ + j0 + ty + i) * TD +
                               2 * D + h * DH + d0 + tx];
    __syncthreads();
    #pragma unroll
    for (int i = 0; i < 32; i += 8) {
        int d = d0 + ty + i;
        vt[((size_t)bh * DH + d) * SEQ + j0 + tx] = __float2half_rn(tile[tx][ty + i]);
    }
}

// ---------------- Shared MMA helpers ----------------
__device__ __forceinline__ unsigned swz(unsigned o) { return o ^ ((o >> 3) & 0x70); }

__device__ __forceinline__ void ldsm4(unsigned addr, unsigned& r0, unsigned& r1,
                                      unsigned& r2, unsigned& r3) {
    asm volatile("ldmatrix.sync.aligned.m8n8.x4.shared.b16 {%0,%1,%2,%3}, [%4];\n"
                 : "=r"(r0), "=r"(r1), "=r"(r2), "=r"(r3) : "r"(addr));
}
__device__ __forceinline__ void mma16816(float* c, unsigned a0, unsigned a1,
                                         unsigned a2, unsigned a3,
                                         unsigned b0, unsigned b1) {
    asm volatile(
        "mma.sync.aligned.m16n8k16.row.col.f32.f16.f16.f32 "
        "{%0,%1,%2,%3},{%4,%5,%6,%7},{%8,%9},{%0,%1,%2,%3};\n"
        : "+f"(c[0]), "+f"(c[1]), "+f"(c[2]), "+f"(c[3])
        : "r"(a0), "r"(a1), "r"(a2), "r"(a3), "r"(b0), "r"(b1));
}
__device__ __forceinline__ void cpasync16(unsigned saddr, const void* g) {
    asm volatile("cp.async.cg.shared.global [%0], [%1], 16;\n" :: "r"(saddr), "l"(g));
}
__device__ __forceinline__ unsigned pack2h(float lo, float hi) {
    __half2 t = __floats2half2_rn(lo, hi);
    return *reinterpret_cast<unsigned*>(&t);
}
// paired-row byte offset (GEMM tile format)
__device__ __forceinline__ unsigned prow(int r, int seg16) {
    return (unsigned)((r >> 1) * 128 + (r & 1) * 64 + seg16 * 16);
}

// ========= fp16 GEMM (unchanged from R12) =========
#define BG_STAGE  16384
#define BG_SMEM   (4 * BG_STAGE)

__device__ __forceinline__ void load_tile(const __half* gbase, unsigned sbase,
                                          int ld, int k0) {
    int t = threadIdx.x;
    #pragma unroll
    for (int i = 0; i < 4; i++) {
        int c = t + i * 128;
        int row = c >> 2, seg = c & 3;
        cpasync16(sbase + swz(prow(row, seg)), gbase + (size_t)row * ld + k0 + seg * 8);
    }
}

__device__ __forceinline__ void ldsm_frags(const unsigned aA[4], const unsigned bA[4],
                                           unsigned off,
                                           unsigned fa[4][4], unsigned fb[4][4]) {
    #pragma unroll
    for (int mi = 0; mi < 4; mi++)
        ldsm4(aA[mi] ^ off, fa[mi][0], fa[mi][1], fa[mi][2], fa[mi][3]);
    #pragma unroll
    for (int np = 0; np < 4; np++)
        ldsm4(bA[np] ^ off, fb[np][0], fb[np][1], fb[np][2], fb[np][3]);
}

__device__ __forceinline__ void mma_tile(float acc[4][8][4],
                                         unsigned fa[4][4], unsigned fb[4][4]) {
    #pragma unroll
    for (int mi = 0; mi < 4; mi++)
        #pragma unroll
        for (int ni = 0; ni < 8; ni++) {
            unsigned b0 = fb[ni >> 1][ni & 1];
            unsigned b1 = fb[ni >> 1][2 + (ni & 1)];
            mma16816(acc[mi][ni], fa[mi][0], fa[mi][1], fa[mi][2], fa[mi][3], b0, b1);
        }
}

__device__ __forceinline__ float gelu_f(float xx) {
    return 0.5f * xx * (1.0f + tanhf(0.7978845608028654f *
                                     (xx + 0.044715f * xx * xx * xx)));
}

template<int EPI>
__global__ void __launch_bounds__(128, 2)
bgemm_kernel(const __half* __restrict__ A,
             const __half* __restrict__ Bt,
             float* __restrict__ C,
             __half* __restrict__ Hout,
             int M, int N, int K) {
    extern __shared__ __align__(128) char smem[];
    unsigned sbase = (unsigned)__cvta_generic_to_shared(smem);

    const int tid = threadIdx.x, lane = tid & 31, warp = tid >> 5;
    const int warpM = warp & 1, warpN = warp >> 1;
    const int rowBase = blockIdx.x * 128;
    const int colBase = blockIdx.y * 128;
    const __half* Ab = A  + (size_t)rowBase * K;
    const __half* Bb = Bt + (size_t)colBase * K;

    float acc[4][8][4];
    #pragma unroll
    for (int i = 0; i < 4; i++)
        #pragma unroll
        for (int j = 0; j < 8; j++)
            #pragma unroll
            for (int r = 0; r < 4; r++) acc[i][j][r] = 0.f;

    const int KT = K >> 5;
    #pragma unroll
    for (int s = 0; s < 3; s++) {
        unsigned st = sbase + s * BG_STAGE;
        load_tile(Ab, st, K, s << 5);
        load_tile(Bb, st + 8192, K, s << 5);
        asm volatile("cp.async.commit_group;\n");
    }

    unsigned aAB[4], bAB[4];
    #pragma unroll
    for (int mi = 0; mi < 4; mi++) {
        int row = warpM * 64 + mi * 16 + (lane & 15);
        aAB[mi] = swz(prow(row, lane >> 4));
    }
    #pragma unroll
    for (int np = 0; np < 4; np++) {
        int rown = warpN * 64 + np * 16 + (lane & 15);
        bAB[np] = 8192u + swz(prow(rown, lane >> 4));
    }

    unsigned fa[4][4], fb[4][4];

    for (int kt = 0; kt < KT; kt++) {
        asm volatile("cp.async.wait_group 2;\n");
        __syncthreads();

        unsigned stg = sbase + (unsigned)(kt & 3) * BG_STAGE;
        unsigned aA[4] = { stg + aAB[0], stg + aAB[1], stg + aAB[2], stg + aAB[3] };
        unsigned bA[4] = { stg + bAB[0], stg + bAB[1], stg + bAB[2], stg + bAB[3] };

        ldsm_frags(aA, bA, 0, fa, fb);

        const int next = kt + 3;
        if (next < KT) {
            unsigned ns = sbase + (unsigned)(next & 3) * BG_STAGE;
            load_tile(Ab, ns, K, next << 5);
            load_tile(Bb, ns + 8192, K, next << 5);
        }
        asm volatile("cp.async.commit_group;\n");

        mma_tile(acc, fa, fb);
        ldsm_frags(aA, bA, 32, fa, fb);
        mma_tile(acc, fa, fb);
    }

    #pragma unroll
    for (int mi = 0; mi < 4; mi++)
        #pragma unroll
        for (int ni = 0; ni < 8; ni++) {
            int row = rowBase + warpM * 64 + mi * 16 + (lane >> 2);
            int col = colBase + warpN * 64 + ni * 8 + 2 * (lane & 3);
            float v0 = acc[mi][ni][0] * WS_INV, v1 = acc[mi][ni][1] * WS_INV;
            float v2 = acc[mi][ni][2] * WS_INV, v3 = acc[mi][ni][3] * WS_INV;
            if (EPI == 2) {
                __half2* hp = (__half2*)(Hout + (size_t)row * N + col);
                __half2* hq = (__half2*)(Hout + (size_t)(row + 8) * N + col);
                *hp = __floats2half2_rn(gelu_f(v0), gelu_f(v1));
                *hq = __floats2half2_rn(gelu_f(v2), gelu_f(v3));
            } else {
                float* p = C + (size_t)row * N + col;
                float* q = C + (size_t)(row + 8) * N + col;
                if (EPI == 1) { v0 += p[0]; v1 += p[1]; v2 += q[0]; v3 += q[1]; }
                *(float2*)p = make_float2(v0, v1);
                *(float2*)q = make_float2(v2, v3);
            }
        }
}

// ========= Tensor-core flash attention =========
// Block = 128 threads (4 warps), 64 q-rows of one (b,h); warp owns 16 rows.
// Smem: bias[1024]f (4KB) | Qs 16KB (4 warps x 4 k32-slices x 1KB) |
//       2 x (Ks 8KB (4 slices x 2KB) + Vt 8KB)  => 52KB
#define AT_SMEM (4096 + 16384 + 2 * 16384)

__global__ void __launch_bounds__(128)
attn_kernel(const __half* __restrict__ qh,
            const __half* __restrict__ kh,
            const __half* __restrict__ vt,
            const int* __restrict__ mask,
            __half* __restrict__ ao) {
    extern __shared__ __align__(128) char asmem[];
    float* bias = (float*)asmem;
    unsigned sb = (unsigned)__cvta_generic_to_shared(asmem);
    const unsigned Qs  = sb + 4096;
    const unsigned KV0 = sb + 20480;

    const int tid = threadIdx.x, lane = tid & 31, warp = tid >> 5;
    const int q0 = blockIdx.x * 64;
    const int h = blockIdx.y, b = blockIdx.z;
    const int bh = b * H + h;
    const int nc = 2 * (blockIdx.x + 1);

    // mask bias for whole sequence (read each chunk from smem)
    for (int i = tid; i < SEQ; i += 128)
        bias[i] = (mask[b * SEQ + i] == 0) ? NEGB : 0.f;

    // stage Q: 4 warps x 4 slices x 16 rows x 4 segs
    {
        const __half* qb = qh + ((size_t)bh * SEQ + q0) * DH;
        #pragma unroll
        for (int i = 0; i < 8; i++) {
            int g = tid + i * 128;
            int seg = g & 3, r = (g >> 2) & 15, s = (g >> 6) & 3, w = g >> 8;
            cpasync16(Qs + w * 4096 + s * 1024 + swz(prow(r, seg)),
                      qb + (size_t)(w * 16 + r) * DH + s * 32 + seg * 8);
        }
    }
    // KV chunk loader
    auto load_kv = [&](int c, int buf) {
        int j0 = c * 32;
        unsigned Kb = KV0 + buf * 16384;
        const __half* kb = kh + ((size_t)bh * SEQ + j0) * DH;
        const __half* vb = vt + (size_t)bh * DH * SEQ + j0;
        #pragma unroll
        for (int i = 0; i < 4; i++) {
            int g = tid + i * 128;
            int seg = g & 3, r = (g >> 2) & 31, s = g >> 7;
            cpasync16(Kb + s * 2048 + swz(prow(r, seg)),
                      kb + (size_t)r * DH + s * 32 + seg * 8);
        }
        #pragma unroll
        for (int i = 0; i < 4; i++) {
            int g = tid + i * 128;
            int seg = g & 3, d = g >> 2;
            cpasync16(Kb + 8192 + swz(prow(d, seg)),
                      vb + (size_t)d * SEQ + seg * 8);
        }
    };

    load_kv(0, 0);
    asm volatile("cp.async.commit_group;\n");   // G0: Q + KV0
    load_kv(1, 1);
    asm volatile("cp.async.commit_group;\n");   // G1: KV1

    // per-thread ldsm bases
    const unsigned qA = Qs + warp * 4096 + swz(prow(lane & 15, lane >> 4));
    unsigned kB[2], vB[8];
    #pragma unroll
    for (int np = 0; np < 2; np++)
        kB[np] = swz(prow(np * 16 + (lane & 15), lane >> 4));
    #pragma unroll
    for (int np = 0; np < 8; np++)
        vB[np] = swz(prow(np * 16 + (lane & 15), lane >> 4));

    const int rowA = q0 + warp * 16 + (lane >> 2);
    const int rowB = rowA + 8;

    float o[16][4];
    #pragma unroll
    for (int i = 0; i < 16; i++)
        #pragma unroll
        for (int r = 0; r < 4; r++) o[i][r] = 0.f;
    float mA = -1e30f, mB = -1e30f, lA = 0.f, lB = 0.f;

    for (int c = 0; c < nc; c++) {
        asm volatile("cp.async.wait_group 1;\n");
        __syncthreads();
        unsigned Kb = KV0 + (unsigned)(c & 1) * 16384;
        unsigned Vb = Kb + 8192;

        // S = Q @ K^T  (16x32 per warp)
        float sc[4][4];
        #pragma unroll
        for (int i = 0; i < 4; i++)
            #pragma unroll
            for (int r = 0; r < 4; r++) sc[i][r] = 0.f;
        #pragma unroll
        for (int s = 0; s < 4; s++) {
            #pragma unroll
            for (int t = 0; t < 2; t++) {
                unsigned fa0, fa1, fa2, fa3;
                ldsm4((qA + s * 1024) ^ (t * 32), fa0, fa1, fa2, fa3);
                #pragma unroll
                for (int np = 0; np < 2; np++) {
                    unsigned b0, b1, b2, b3;
                    ldsm4((Kb + s * 2048 + kB[np]) ^ (t * 32), b0, b1, b2, b3);
                    mma16816(sc[2 * np],     fa0, fa1, fa2, fa3, b0, b2);
                    mma16816(sc[2 * np + 1], fa0, fa1, fa2, fa3, b1, b3);
                }
            }
        }

        // scale + mask (causal + padding)
        const int j0 = c * 32;
        #pragma unroll
        for (int ni = 0; ni < 4; ni++) {
            int jb = j0 + ni * 8 + 2 * (lane & 3);
            float b0 = bias[jb], b1 = bias[jb + 1];
            sc[ni][0] = (jb     <= rowA) ? sc[ni][0] * SCALE + b0 : -1e30f;
            sc[ni][1] = (jb + 1 <= rowA) ? sc[ni][1] * SCALE + b1 : -1e30f;
            sc[ni][2] = (jb     <= rowB) ? sc[ni][2] * SCALE + b0 : -1e30f;
            sc[ni][3] = (jb + 1 <= rowB) ? sc[ni][3] * SCALE + b1 : -1e30f;
        }

        // online softmax (rows owned by lane quads)
        float cmA = -1e30f, cmB = -1e30f;
        #pragma unroll
        for (int ni = 0; ni < 4; ni++) {
            cmA = fmaxf(cmA, fmaxf(sc[ni][0], sc[ni][1]));
            cmB = fmaxf(cmB, fmaxf(sc[ni][2], sc[ni][3]));
        }
        #pragma unroll
        for (int off = 1; off <= 2; off <<= 1) {
            cmA = fmaxf(cmA, __shfl_xor_sync(0xffffffffu, cmA, off));
            cmB = fmaxf(cmB, __shfl_xor_sync(0xffffffffu, cmB, off));
        }
        float newA = fmaxf(mA, cmA), newB = fmaxf(mB, cmB);
        float corrA = __expf(mA - newA), corrB = __expf(mB - newB);
        mA = newA; mB = newB;

        float sA = 0.f, sB = 0.f;
        #pragma unroll
        for (int ni = 0; ni < 4; ni++) {
            sc[ni][0] = __expf(sc[ni][0] - newA); sA += sc[ni][0];
            sc[ni][1] = __expf(sc[ni][1] - newA); sA += sc[ni][1];
            sc[ni][2] = __expf(sc[ni][2] - newB); sB += sc[ni][2];
            sc[ni][3] = __expf(sc[ni][3] - newB); sB += sc[ni][3];
        }
        #pragma unroll
        for (int off = 1; off <= 2; off <<= 1) {
            sA += __shfl_xor_sync(0xffffffffu, sA, off);
            sB += __shfl_xor_sync(0xffffffffu, sB, off);
        }
        lA = lA * corrA + sA;
        lB = lB * corrB + sB;
        #pragma unroll
        for (int ni = 0; ni < 16; ni++) {
            o[ni][0] *= corrA; o[ni][1] *= corrA;
            o[ni][2] *= corrB; o[ni][3] *= corrB;
        }

        // O += P @ V   (P fragments from sc; C-layout == A-halves)
        #pragma unroll
        for (int t = 0; t < 2; t++) {
            unsigned a0 = pack2h(sc[2 * t][0],     sc[2 * t][1]);
            unsigned a1 = pack2h(sc[2 * t][2],     sc[2 * t][3]);
            unsigned a2 = pack2h(sc[2 * t + 1][0], sc[2 * t + 1][1]);
            unsigned a3 = pack2h(sc[2 * t + 1][2], sc[2 * t + 1][3]);
            #pragma unroll
            for (int np = 0; np < 8; np++) {
                unsigned b0, b1, b2, b3;
                ldsm4((Vb + vB[np]) ^ (t * 32), b0, b1, b2, b3);
                mma16816(o[2 * np],     a0, a1, a2, a3, b0, b2);
                mma16816(o[2 * np + 1], a0, a1, a2, a3, b1, b3);
            }
        }

        __syncthreads();
        if (c + 2 < nc) load_kv(c + 2, c & 1);
        asm volatile("cp.async.commit_group;\n");
    }

    // epilogue
    const float invA = 1.f / lA, invB = 1.f / lB;
    const size_t baseA = ((size_t)(b * SEQ + rowA)) * D + h * DH;
    const size_t baseB = ((size_t)(b * SEQ + rowB)) * D + h * DH;
    #pragma unroll
    for (int ni = 0; ni < 16; ni++) {
        int col = ni * 8 + 2 * (lane & 3);
        *(__half2*)(ao + baseA + col) = __floats2half2_rn(o[ni][0] * invA, o[ni][1] * invA);
        *(__half2*)(ao + baseB + col) = __floats2half2_rn(o[ni][2] * invB, o[ni][3] * invB);
    }
}

// ---------------- Pool + head ----------------
__global__ void meanpool_kernel(const float* __restrict__ hs,
                                const int* __restrict__ mask,
                                float* __restrict__ mean) {
    int idx = blockIdx.x * blockDim.x + threadIdx.x;
    int b = idx / D;
    int d = idx % D;
    float acc = 0.f, msum = 0.f;
    const float* hb = hs + (size_t)b * SEQ * D + d;
    const int* mb = mask + b * SEQ;
    for (int s = 0; s < SEQ; s++) {
        float mf = (float)mb[s];
        acc = fmaf(mf, hb[(size_t)s * D], acc);
        msum += mf;
    }
    mean[idx] = acc / fmaxf(msum, 1e-9f);
}

__global__ void head1_kernel(const float* __restrict__ mean,
                             const float* __restrict__ Wc1,
                             const float* __restrict__ bc1,
                             float* __restrict__ t) {
    int idx = blockIdx.x * blockDim.x + threadIdx.x;
    int b = idx / D;
    int j = idx % D;
    float acc = bc1[j];
    const float* mb = mean + (size_t)b * D;
    for (int k = 0; k < D; k++)
        acc = fmaf(mb[k], Wc1[(size_t)k * D + j], acc);
    t[idx] = tanhf(acc);
}

__global__ void head2_kernel(const float* __restrict__ t,
                             const float* __restrict__ Wc2,
                             const float* __restrict__ bc2,
                             float* __restrict__ out) {
    __shared__ float red[256];
    __shared__ float logits[4];
    const int tid = threadIdx.x;
    float part[4] = {0.f, 0.f, 0.f, 0.f};
    for (int j = tid; j < D; j += 256) {
        float t0 = t[j], t1 = t[D + j];
        float w0 = Wc2[2 * j], w1 = Wc2[2 * j + 1];
        part[0] = fmaf(t0, w0, part[0]);
        part[1] = fmaf(t0, w1, part[1]);
        part[2] = fmaf(t1, w0, part[2]);
        part[3] = fmaf(t1, w1, part[3]);
    }
    for (int c = 0; c < 4; c++) {
        __syncthreads();
        red[tid] = part[c]; __syncthreads();
        for (int st = 128; st > 0; st >>= 1) {
            if (tid < st) red[tid] += red[tid + st];
            __syncthreads();
        }
        if (tid == 0) logits[c] = red[0] + bc2[c & 1];
    }
    __syncthreads();
    if (tid == 0) {
        for (int b = 0; b < BATCH; b++) {
            float l0 = logits[2 * b], l1 = logits[2 * b + 1];
            float m = fmaxf(l0, l1);
            float e0 = expf(l0 - m), e1 = expf(l1 - m);
            out[b] = e1 / (e0 + e1);
        }
    }
}

// ---------------- Launch ----------------
extern "C" void kernel_launch(void* const* d_in, const int* in_sizes, int n_in,
                              void* d_out, int out_size) {
    const int*   ids   = (const int*)d_in[0];
    const int*   amask = (const int*)d_in[1];
    const float* emb   = (const float*)d_in[2];
    const float* ln1_g = (const float*)d_in[3];
    const float* ln1_b = (const float*)d_in[4];
    const float* Wqkv  = (const float*)d_in[5];
    const float* Wo    = (const float*)d_in[6];
    const float* ln2_g = (const float*)d_in[7];
    const float* ln2_b = (const float*)d_in[8];
    const float* W1    = (const float*)d_in[9];
    const float* W2    = (const float*)d_in[10];
    const float* lnf_g = (const float*)d_in[11];
    const float* lnf_b = (const float*)d_in[12];
    const float* Wc1   = (const float*)d_in[13];
    const float* bc1   = (const float*)d_in[14];
    const float* Wc2   = (const float*)d_in[15];
    const float* bc2   = (const float*)d_in[16];
    float* out = (float*)d_out;

    float *x, *h, *qkv, *mean, *t;
    __half *ha_d, *ha_f, *qh, *kh, *vt, *wqkvT, *woT, *w1T, *w2T;
    cudaGetSymbolAddress((void**)&x,    g_x);
    cudaGetSymbolAddress((void**)&h,    g_h);
    cudaGetSymbolAddress((void**)&qkv,  g_qkv);
    cudaGetSymbolAddress((void**)&mean, g_mean);
    cudaGetSymbolAddress((void**)&t,    g_t);
    cudaGetSymbolAddress((void**)&ha_d, g_ha_d);
    cudaGetSymbolAddress((void**)&ha_f, g_ha_f);
    cudaGetSymbolAddress((void**)&qh,   g_qh);
    cudaGetSymbolAddress((void**)&kh,   g_kh);
    cudaGetSymbolAddress((void**)&vt,   g_vt);
    cudaGetSymbolAddress((void**)&wqkvT, g_wqkvT);
    cudaGetSymbolAddress((void**)&woT,   g_woT);
    cudaGetSymbolAddress((void**)&w1T,   g_w1T);
    cudaGetSymbolAddress((void**)&w2T,   g_w2T);

    cudaFuncSetAttribute(bgemm_kernel<0>,
                         cudaFuncAttributeMaxDynamicSharedMemorySize, BG_SMEM);
    cudaFuncSetAttribute(bgemm_kernel<1>,
                         cudaFuncAttributeMaxDynamicSharedMemorySize, BG_SMEM);
    cudaFuncSetAttribute(bgemm_kernel<2>,
                         cudaFuncAttributeMaxDynamicSharedMemorySize, BG_SMEM);
    cudaFuncSetAttribute(attn_kernel,
                         cudaFuncAttributeMaxDynamicSharedMemorySize, AT_SMEM);

    embed_kernel<<<(BS * D) / 256, 256>>>(ids, emb, x);

    for (int l = 0; l < LAYERS; l++) {
        // attention block
        ln_kernel<1><<<BS, 256>>>(x, ln1_g + (size_t)l * D, ln1_b + (size_t)l * D,
                                  nullptr, ha_d);
        transw_kernel<<<dim3(TD / 32, D / 32), dim3(32, 8)>>>(
            Wqkv + (size_t)l * D * TD, wqkvT, D, TD);
        bgemm_kernel<0><<<dim3(BS / 128, TD / 128), 128, BG_SMEM>>>(
            ha_d, wqkvT, qkv, nullptr, BS, TD, D);
        qkconv_kernel<<<BS, 256>>>(qkv, qh, kh);
        vtrans_kernel<<<dim3(SEQ / 32, DH / 32, BATCH * H), dim3(32, 8)>>>(qkv, vt);
        attn_kernel<<<dim3(SEQ / 64, H, BATCH), 128, AT_SMEM>>>(
            qh, kh, vt, amask, ha_d);
        transw_kernel<<<dim3(D / 32, D / 32), dim3(32, 8)>>>(
            Wo + (size_t)l * D * D, woT, D, D);
        bgemm_kernel<1><<<dim3(BS / 128, D / 128), 128, BG_SMEM>>>(
            ha_d, woT, x, nullptr, BS, D, D);
        // mlp block
        ln_kernel<1><<<BS, 256>>>(x, ln2_g + (size_t)l * D, ln2_b + (size_t)l * D,
                                  nullptr, ha_d);
        transw_kernel<<<dim3(FF / 32, D / 32), dim3(32, 8)>>>(
            W1 + (size_t)l * D * FF, w1T, D, FF);
        bgemm_kernel<2><<<dim3(BS / 128, FF / 128), 128, BG_SMEM>>>(
            ha_d, w1T, nullptr, ha_f, BS, FF, D);
        transw_kernel<<<dim3(D / 32, FF / 32), dim3(32, 8)>>>(
            W2 + (size_t)l * FF * D, w2T, FF, D);
        bgemm_kernel<1><<<dim3(BS / 128, D / 128), 128, BG_SMEM>>>(
            ha_f, w2T, x, nullptr, BS, D, FF);
    }

    ln_kernel<0><<<BS, 256>>>(x, lnf_g, lnf_b, h, nullptr);
    meanpool_kernel<<<(BATCH * D) / 256, 256>>>(h, amask, mean);
    head1_kernel<<<(BATCH * D) / 256, 256>>>(mean, Wc1, bc1, t);
    head2_kernel<<<1, 256>>>(t, Wc2, bc2, out);
}

// round 14
// speedup vs baseline: 5.0845x; 1.0038x over previous
#include <cuda_runtime.h>
#include <cuda_fp16.h>
#include <math.h>
#include <stdint.h>

// ---------------- Problem constants ----------------
#define LAYERS 2
#define D      2048
#define H      16
#define FF     8192
#define BATCH  2
#define SEQ    1024
#define DH     128
#define TD     (3 * D)
#define BS     (BATCH * SEQ)
#define NEGB   (-1e9f)
#define SCALE  0.08838834764831845f
#define SCALE2 (0.08838834764831845f * 1.4426950408889634f)  // * log2(e)
#define WS     512.0f
#define WS_INV (1.0f / 512.0f)

// ---------------- Scratch (static device globals) ----------------
__device__ float g_x   [BS * D];
__device__ float g_h   [BS * D];
__device__ float g_qkv [BS * TD];
__device__ float g_mean[BATCH * D];
__device__ float g_t   [BATCH * D];
// fp16 activation buffers
__device__ __half g_ha_d[BS * D];
__device__ __half g_ha_f[BS * FF];
// fp16 attention operands (head-major)
__device__ __half g_qh[BS * D];
__device__ __half g_kh[BS * D];
__device__ __half g_vt[BS * D];
// fp16 transposed scaled weights
__device__ __half g_wqkvT[TD * D];
__device__ __half g_woT  [D * D];
__device__ __half g_w1T  [FF * D];
__device__ __half g_w2T  [D * FF];

// ---------------- Embedding gather ----------------
__global__ void embed_kernel(const int* __restrict__ ids,
                             const float* __restrict__ emb,
                             float* __restrict__ x) {
    int idx = blockIdx.x * blockDim.x + threadIdx.x;
    int tok = ids[idx / D];
    x[idx] = emb[(size_t)tok * D + (idx % D)];
}

// ---------------- LayerNorm; HOUT=1 writes fp16 ----------------
template<int HOUT>
__global__ void ln_kernel(const float* __restrict__ x,
                          const float* __restrict__ g,
                          const float* __restrict__ b,
                          float* __restrict__ outf,
                          __half* __restrict__ outh) {
    __shared__ float row[D];
    __shared__ float red[256];
    const int tid = threadIdx.x;
    const float* xr = x + (size_t)blockIdx.x * D;

    float s = 0.f;
    for (int i = tid; i < D; i += 256) { float v = xr[i]; row[i] = v; s += v; }
    red[tid] = s; __syncthreads();
    for (int st = 128; st > 0; st >>= 1) {
        if (tid < st) red[tid] += red[tid + st];
        __syncthreads();
    }
    const float mean = red[0] * (1.0f / D);
    __syncthreads();

    float s2 = 0.f;
    for (int i = tid; i < D; i += 256) { float v = row[i] - mean; s2 += v * v; }
    red[tid] = s2; __syncthreads();
    for (int st = 128; st > 0; st >>= 1) {
        if (tid < st) red[tid] += red[tid + st];
        __syncthreads();
    }
    const float rstd = rsqrtf(red[0] * (1.0f / D) + 1e-5f);

    if (HOUT) {
        __half* orow = outh + (size_t)blockIdx.x * D;
        for (int i = tid; i < D; i += 256)
            orow[i] = __float2half_rn((row[i] - mean) * rstd * g[i] + b[i]);
    } else {
        float* orow = outf + (size_t)blockIdx.x * D;
        for (int i = tid; i < D; i += 256)
            orow[i] = (row[i] - mean) * rstd * g[i] + b[i];
    }
}

// ---------------- Transpose + scale weights ----------------
__global__ void transw_kernel(const float* __restrict__ W,
                              __half* __restrict__ Wt, int K, int N) {
    __shared__ float tile[32][33];
    int n0 = blockIdx.x * 32, k0 = blockIdx.y * 32;
    int tx = threadIdx.x, ty = threadIdx.y;
    #pragma unroll
    for (int i = 0; i < 32; i += 8)
        tile[ty + i][tx] = W[(size_t)(k0 + ty + i) * N + n0 + tx];
    __syncthreads();
    #pragma unroll
    for (int i = 0; i < 32; i += 8) {
        int nn = ty + i;
        Wt[(size_t)(n0 + nn) * K + k0 + tx] = __float2half_rn(tile[tx][nn] * WS);
    }
}

// ---------------- qkv -> fp16 head-major q/k ----------------
__global__ void qkconv_kernel(const float* __restrict__ qkv,
                              __half* __restrict__ qh,
                              __half* __restrict__ kh) {
    int t = blockIdx.x;
    int b = t / SEQ, sidx = t % SEQ;
    const float* src = qkv + (size_t)t * TD;
    for (int i = threadIdx.x; i < D; i += 256) {
        int h = i >> 7, d = i & 127;
        size_t o = ((size_t)(b * H + h) * SEQ + sidx) * DH + d;
        qh[o] = __float2half_rn(src[i]);
        kh[o] = __float2half_rn(src[D + i]);
    }
}

// ---------------- qkv V part -> fp16 transposed vt[b][h][d][j] ----------------
__global__ void vtrans_kernel(const float* __restrict__ qkv,
                              __half* __restrict__ vt) {
    __shared__ float tile[32][33];
    int j0 = blockIdx.x * 32, d0 = blockIdx.y * 32;
    int bh = blockIdx.z;
    int b = bh / H, h = bh % H;
    int tx = threadIdx.x, ty = threadIdx.y;
    #pragma unroll
    for (int i = 0; i < 32; i += 8)
        tile[ty + i][tx] = qkv[(size_t)(b * SEQ + j0 + ty + i) * TD +
                               2 * D + h * DH + d0 + tx];
    __syncthreads();
    #pragma unroll
    for (int i = 0; i < 32; i += 8) {
        int d = d0 + ty + i;
        vt[((size_t)bh * DH + d) * SEQ + j0 + tx] = __float2half_rn(tile[tx][ty + i]);
    }
}

// ---------------- Shared MMA helpers ----------------
__device__ __forceinline__ unsigned swz(unsigned o) { return o ^ ((o >> 3) & 0x70); }

__device__ __forceinline__ void ldsm4(unsigned addr, unsigned& r0, unsigned& r1,
                                      unsigned& r2, unsigned& r3) {
    asm volatile("ldmatrix.sync.aligned.m8n8.x4.shared.b16 {%0,%1,%2,%3}, [%4];\n"
                 : "=r"(r0), "=r"(r1), "=r"(r2), "=r"(r3) : "r"(addr));
}
__device__ __forceinline__ void mma16816(float* c, unsigned a0, unsigned a1,
                                         unsigned a2, unsigned a3,
                                         unsigned b0, unsigned b1) {
    asm volatile(
        "mma.sync.aligned.m16n8k16.row.col.f32.f16.f16.f32 "
        "{%0,%1,%2,%3},{%4,%5,%6,%7},{%8,%9},{%0,%1,%2,%3};\n"
        : "+f"(c[0]), "+f"(c[1]), "+f"(c[2]), "+f"(c[3])
        : "r"(a0), "r"(a1), "r"(a2), "r"(a3), "r"(b0), "r"(b1));
}
__device__ __forceinline__ void cpasync16(unsigned saddr, const void* g) {
    asm volatile("cp.async.cg.shared.global [%0], [%1], 16;\n" :: "r"(saddr), "l"(g));
}
// packed fp16 exp2 of (lo, hi)
__device__ __forceinline__ unsigned ex2h2(float lo, float hi) {
    __half2 t = __floats2half2_rn(lo, hi);
    unsigned u = *reinterpret_cast<unsigned*>(&t);
    unsigned r;
    asm("ex2.approx.f16x2 %0, %1;" : "=r"(r) : "r"(u));
    return r;
}
__device__ __forceinline__ unsigned prow(int r, int seg16) {
    return (unsigned)((r >> 1) * 128 + (r & 1) * 64 + seg16 * 16);
}

// ========= fp16 GEMM (unchanged) =========
#define BG_STAGE  16384
#define BG_SMEM   (4 * BG_STAGE)

__device__ __forceinline__ void load_tile(const __half* gbase, unsigned sbase,
                                          int ld, int k0) {
    int t = threadIdx.x;
    #pragma unroll
    for (int i = 0; i < 4; i++) {
        int c = t + i * 128;
        int row = c >> 2, seg = c & 3;
        cpasync16(sbase + swz(prow(row, seg)), gbase + (size_t)row * ld + k0 + seg * 8);
    }
}

__device__ __forceinline__ void ldsm_frags(const unsigned aA[4], const unsigned bA[4],
                                           unsigned off,
                                           unsigned fa[4][4], unsigned fb[4][4]) {
    #pragma unroll
    for (int mi = 0; mi < 4; mi++)
        ldsm4(aA[mi] ^ off, fa[mi][0], fa[mi][1], fa[mi][2], fa[mi][3]);
    #pragma unroll
    for (int np = 0; np < 4; np++)
        ldsm4(bA[np] ^ off, fb[np][0], fb[np][1], fb[np][2], fb[np][3]);
}

__device__ __forceinline__ void mma_tile(float acc[4][8][4],
                                         unsigned fa[4][4], unsigned fb[4][4]) {
    #pragma unroll
    for (int mi = 0; mi < 4; mi++)
        #pragma unroll
        for (int ni = 0; ni < 8; ni++) {
            unsigned b0 = fb[ni >> 1][ni & 1];
            unsigned b1 = fb[ni >> 1][2 + (ni & 1)];
            mma16816(acc[mi][ni], fa[mi][0], fa[mi][1], fa[mi][2], fa[mi][3], b0, b1);
        }
}

__device__ __forceinline__ float gelu_f(float xx) {
    return 0.5f * xx * (1.0f + tanhf(0.7978845608028654f *
                                     (xx + 0.044715f * xx * xx * xx)));
}

template<int EPI>
__global__ void __launch_bounds__(128, 2)
bgemm_kernel(const __half* __restrict__ A,
             const __half* __restrict__ Bt,
             float* __restrict__ C,
             __half* __restrict__ Hout,
             int M, int N, int K) {
    extern __shared__ __align__(128) char smem[];
    unsigned sbase = (unsigned)__cvta_generic_to_shared(smem);

    const int tid = threadIdx.x, lane = tid & 31, warp = tid >> 5;
    const int warpM = warp & 1, warpN = warp >> 1;
    const int rowBase = blockIdx.x * 128;
    const int colBase = blockIdx.y * 128;
    const __half* Ab = A  + (size_t)rowBase * K;
    const __half* Bb = Bt + (size_t)colBase * K;

    float acc[4][8][4];
    #pragma unroll
    for (int i = 0; i < 4; i++)
        #pragma unroll
        for (int j = 0; j < 8; j++)
            #pragma unroll
            for (int r = 0; r < 4; r++) acc[i][j][r] = 0.f;

    const int KT = K >> 5;
    #pragma unroll
    for (int s = 0; s < 3; s++) {
        unsigned st = sbase + s * BG_STAGE;
        load_tile(Ab, st, K, s << 5);
        load_tile(Bb, st + 8192, K, s << 5);
        asm volatile("cp.async.commit_group;\n");
    }

    unsigned aAB[4], bAB[4];
    #pragma unroll
    for (int mi = 0; mi < 4; mi++) {
        int row = warpM * 64 + mi * 16 + (lane & 15);
        aAB[mi] = swz(prow(row, lane >> 4));
    }
    #pragma unroll
    for (int np = 0; np < 4; np++) {
        int rown = warpN * 64 + np * 16 + (lane & 15);
        bAB[np] = 8192u + swz(prow(rown, lane >> 4));
    }

    unsigned fa[4][4], fb[4][4];

    for (int kt = 0; kt < KT; kt++) {
        asm volatile("cp.async.wait_group 2;\n");
        __syncthreads();

        unsigned stg = sbase + (unsigned)(kt & 3) * BG_STAGE;
        unsigned aA[4] = { stg + aAB[0], stg + aAB[1], stg + aAB[2], stg + aAB[3] };
        unsigned bA[4] = { stg + bAB[0], stg + bAB[1], stg + bAB[2], stg + bAB[3] };

        ldsm_frags(aA, bA, 0, fa, fb);

        const int next = kt + 3;
        if (next < KT) {
            unsigned ns = sbase + (unsigned)(next & 3) * BG_STAGE;
            load_tile(Ab, ns, K, next << 5);
            load_tile(Bb, ns + 8192, K, next << 5);
        }
        asm volatile("cp.async.commit_group;\n");

        mma_tile(acc, fa, fb);
        ldsm_frags(aA, bA, 32, fa, fb);
        mma_tile(acc, fa, fb);
    }

    #pragma unroll
    for (int mi = 0; mi < 4; mi++)
        #pragma unroll
        for (int ni = 0; ni < 8; ni++) {
            int row = rowBase + warpM * 64 + mi * 16 + (lane >> 2);
            int col = colBase + warpN * 64 + ni * 8 + 2 * (lane & 3);
            float v0 = acc[mi][ni][0] * WS_INV, v1 = acc[mi][ni][1] * WS_INV;
            float v2 = acc[mi][ni][2] * WS_INV, v3 = acc[mi][ni][3] * WS_INV;
            if (EPI == 2) {
                __half2* hp = (__half2*)(Hout + (size_t)row * N + col);
                __half2* hq = (__half2*)(Hout + (size_t)(row + 8) * N + col);
                *hp = __floats2half2_rn(gelu_f(v0), gelu_f(v1));
                *hq = __floats2half2_rn(gelu_f(v2), gelu_f(v3));
            } else {
                float* p = C + (size_t)row * N + col;
                float* q = C + (size_t)(row + 8) * N + col;
                if (EPI == 1) { v0 += p[0]; v1 += p[1]; v2 += q[0]; v3 += q[1]; }
                *(float2*)p = make_float2(v0, v1);
                *(float2*)q = make_float2(v2, v3);
            }
        }
}

// ========= Tensor-core flash attention (log2-domain softmax, fp16x2 ex2) =========
#define AT_SMEM (4096 + 16384 + 2 * 16384)

__global__ void __launch_bounds__(128)
attn_kernel(const __half* __restrict__ qh,
            const __half* __restrict__ kh,
            const __half* __restrict__ vt,
            const int* __restrict__ mask,
            __half* __restrict__ ao) {
    extern __shared__ __align__(128) char asmem[];
    float* bias = (float*)asmem;
    unsigned sb = (unsigned)__cvta_generic_to_shared(asmem);
    const unsigned Qs  = sb + 4096;
    const unsigned KV0 = sb + 20480;

    const int tid = threadIdx.x, lane = tid & 31, warp = tid >> 5;
    const int q0 = blockIdx.x * 64;
    const int h = blockIdx.y, b = blockIdx.z;
    const int bh = b * H + h;
    const int nc = 2 * (blockIdx.x + 1);

    for (int i = tid; i < SEQ; i += 128)
        bias[i] = (mask[b * SEQ + i] == 0) ? NEGB : 0.f;

    {
        const __half* qb = qh + ((size_t)bh * SEQ + q0) * DH;
        #pragma unroll
        for (int i = 0; i < 8; i++) {
            int g = tid + i * 128;
            int seg = g & 3, r = (g >> 2) & 15, s = (g >> 6) & 3, w = g >> 8;
            cpasync16(Qs + w * 4096 + s * 1024 + swz(prow(r, seg)),
                      qb + (size_t)(w * 16 + r) * DH + s * 32 + seg * 8);
        }
    }
    auto load_kv = [&](int c, int buf) {
        int j0 = c * 32;
        unsigned Kb = KV0 + buf * 16384;
        const __half* kb = kh + ((size_t)bh * SEQ + j0) * DH;
        const __half* vb = vt + (size_t)bh * DH * SEQ + j0;
        #pragma unroll
        for (int i = 0; i < 4; i++) {
            int g = tid + i * 128;
            int seg = g & 3, r = (g >> 2) & 31, s = g >> 7;
            cpasync16(Kb + s * 2048 + swz(prow(r, seg)),
                      kb + (size_t)r * DH + s * 32 + seg * 8);
        }
        #pragma unroll
        for (int i = 0; i < 4; i++) {
            int g = tid + i * 128;
            int seg = g & 3, d = g >> 2;
            cpasync16(Kb + 8192 + swz(prow(d, seg)),
                      vb + (size_t)d * SEQ + seg * 8);
        }
    };

    load_kv(0, 0);
    asm volatile("cp.async.commit_group;\n");
    load_kv(1, 1);
    asm volatile("cp.async.commit_group;\n");

    const unsigned qA = Qs + warp * 4096 + swz(prow(lane & 15, lane >> 4));
    unsigned kB[2], vB[8];
    #pragma unroll
    for (int np = 0; np < 2; np++)
        kB[np] = swz(prow(np * 16 + (lane & 15), lane >> 4));
    #pragma unroll
    for (int np = 0; np < 8; np++)
        vB[np] = swz(prow(np * 16 + (lane & 15), lane >> 4));

    const int rowA = q0 + warp * 16 + (lane >> 2);
    const int rowB = rowA + 8;

    float o[16][4];
    #pragma unroll
    for (int i = 0; i < 16; i++)
        #pragma unroll
        for (int r = 0; r < 4; r++) o[i][r] = 0.f;
    float mA = -1e30f, mB = -1e30f, lA = 0.f, lB = 0.f;

    for (int c = 0; c < nc; c++) {
        asm volatile("cp.async.wait_group 1;\n");
        __syncthreads();
        unsigned Kb = KV0 + (unsigned)(c & 1) * 16384;
        unsigned Vb = Kb + 8192;

        // S2 = (Q @ K^T) * SCALE*log2e + bias  (log2-domain scores)
        float sc[4][4];
        #pragma unroll
        for (int i = 0; i < 4; i++)
            #pragma unroll
            for (int r = 0; r < 4; r++) sc[i][r] = 0.f;
        #pragma unroll
        for (int s = 0; s < 4; s++) {
            #pragma unroll
            for (int t = 0; t < 2; t++) {
                unsigned fa0, fa1, fa2, fa3;
                ldsm4((qA + s * 1024) ^ (t * 32), fa0, fa1, fa2, fa3);
                #pragma unroll
                for (int np = 0; np < 2; np++) {
                    unsigned b0, b1, b2, b3;
                    ldsm4((Kb + s * 2048 + kB[np]) ^ (t * 32), b0, b1, b2, b3);
                    mma16816(sc[2 * np],     fa0, fa1, fa2, fa3, b0, b2);
                    mma16816(sc[2 * np + 1], fa0, fa1, fa2, fa3, b1, b3);
                }
            }
        }

        const int j0 = c * 32;
        #pragma unroll
        for (int ni = 0; ni < 4; ni++) {
            int jb = j0 + ni * 8 + 2 * (lane & 3);
            float b0 = bias[jb], b1 = bias[jb + 1];
            sc[ni][0] = (jb     <= rowA) ? sc[ni][0] * SCALE2 + b0 : -1e30f;
            sc[ni][1] = (jb + 1 <= rowA) ? sc[ni][1] * SCALE2 + b1 : -1e30f;
            sc[ni][2] = (jb     <= rowB) ? sc[ni][2] * SCALE2 + b0 : -1e30f;
            sc[ni][3] = (jb + 1 <= rowB) ? sc[ni][3] * SCALE2 + b1 : -1e30f;
        }

        // online softmax in log2 domain
        float cmA = -1e30f, cmB = -1e30f;
        #pragma unroll
        for (int ni = 0; ni < 4; ni++) {
            cmA = fmaxf(cmA, fmaxf(sc[ni][0], sc[ni][1]));
            cmB = fmaxf(cmB, fmaxf(sc[ni][2], sc[ni][3]));
        }
        #pragma unroll
        for (int off = 1; off <= 2; off <<= 1) {
            cmA = fmaxf(cmA, __shfl_xor_sync(0xffffffffu, cmA, off));
            cmB = fmaxf(cmB, __shfl_xor_sync(0xffffffffu, cmB, off));
        }
        float newA = fmaxf(mA, cmA), newB = fmaxf(mB, cmB);
        float corrA = exp2f(mA - newA), corrB = exp2f(mB - newB);
        mA = newA; mB = newB;

        // p fragments directly in fp16 via ex2.approx.f16x2
        unsigned hA[4], hB[4];
        float sA = 0.f, sB = 0.f;
        #pragma unroll
        for (int ni = 0; ni < 4; ni++) {
            hA[ni] = ex2h2(sc[ni][0] - newA, sc[ni][1] - newA);
            hB[ni] = ex2h2(sc[ni][2] - newB, sc[ni][3] - newB);
            float2 fa2 = __half22float2(*(__half2*)&hA[ni]);
            float2 fb2 = __half22float2(*(__half2*)&hB[ni]);
            sA += fa2.x + fa2.y;
            sB += fb2.x + fb2.y;
        }
        #pragma unroll
        for (int off = 1; off <= 2; off <<= 1) {
            sA += __shfl_xor_sync(0xffffffffu, sA, off);
            sB += __shfl_xor_sync(0xffffffffu, sB, off);
        }
        lA = lA * corrA + sA;
        lB = lB * corrB + sB;
        #pragma unroll
        for (int ni = 0; ni < 16; ni++) {
            o[ni][0] *= corrA; o[ni][1] *= corrA;
            o[ni][2] *= corrB; o[ni][3] *= corrB;
        }

        // O += P @ V
        #pragma unroll
        for (int t = 0; t < 2; t++) {
            unsigned a0 = hA[2 * t], a1 = hB[2 * t];
            unsigned a2 = hA[2 * t + 1], a3 = hB[2 * t + 1];
            #pragma unroll
            for (int np = 0; np < 8; np++) {
                unsigned b0, b1, b2, b3;
                ldsm4((Vb + vB[np]) ^ (t * 32), b0, b1, b2, b3);
                mma16816(o[2 * np],     a0, a1, a2, a3, b0, b2);
                mma16816(o[2 * np + 1], a0, a1, a2, a3, b1, b3);
            }
        }

        __syncthreads();
        if (c + 2 < nc) load_kv(c + 2, c & 1);
        asm volatile("cp.async.commit_group;\n");
    }

    const float invA = 1.f / lA, invB = 1.f / lB;
    const size_t baseA = ((size_t)(b * SEQ + rowA)) * D + h * DH;
    const size_t baseB = ((size_t)(b * SEQ + rowB)) * D + h * DH;
    #pragma unroll
    for (int ni = 0; ni < 16; ni++) {
        int col = ni * 8 + 2 * (lane & 3);
        *(__half2*)(ao + baseA + col) = __floats2half2_rn(o[ni][0] * invA, o[ni][1] * invA);
        *(__half2*)(ao + baseB + col) = __floats2half2_rn(o[ni][2] * invB, o[ni][3] * invB);
    }
}

// ---------------- Pool + head ----------------
__global__ void meanpool_kernel(const float* __restrict__ hs,
                                const int* __restrict__ mask,
                                float* __restrict__ mean) {
    int idx = blockIdx.x * blockDim.x + threadIdx.x;
    int b = idx / D;
    int d = idx % D;
    float acc = 0.f, msum = 0.f;
    const float* hb = hs + (size_t)b * SEQ * D + d;
    const int* mb = mask + b * SEQ;
    for (int s = 0; s < SEQ; s++) {
        float mf = (float)mb[s];
        acc = fmaf(mf, hb[(size_t)s * D], acc);
        msum += mf;
    }
    mean[idx] = acc / fmaxf(msum, 1e-9f);
}

__global__ void head1_kernel(const float* __restrict__ mean,
                             const float* __restrict__ Wc1,
                             const float* __restrict__ bc1,
                             float* __restrict__ t) {
    int idx = blockIdx.x * blockDim.x + threadIdx.x;
    int b = idx / D;
    int j = idx % D;
    float acc = bc1[j];
    const float* mb = mean + (size_t)b * D;
    for (int k = 0; k < D; k++)
        acc = fmaf(mb[k], Wc1[(size_t)k * D + j], acc);
    t[idx] = tanhf(acc);
}

__global__ void head2_kernel(const float* __restrict__ t,
                             const float* __restrict__ Wc2,
                             const float* __restrict__ bc2,
                             float* __restrict__ out) {
    __shared__ float red[256];
    __shared__ float logits[4];
    const int tid = threadIdx.x;
    float part[4] = {0.f, 0.f, 0.f, 0.f};
    for (int j = tid; j < D; j += 256) {
        float t0 = t[j], t1 = t[D + j];
        float w0 = Wc2[2 * j], w1 = Wc2[2 * j + 1];
        part[0] = fmaf(t0, w0, part[0]);
        part[1] = fmaf(t0, w1, part[1]);
        part[2] = fmaf(t1, w0, part[2]);
        part[3] = fmaf(t1, w1, part[3]);
    }
    for (int c = 0; c < 4; c++) {
        __syncthreads();
        red[tid] = part[c]; __syncthreads();
        for (int st = 128; st > 0; st >>= 1) {
            if (tid < st) red[tid] += red[tid + st];
            __syncthreads();
        }
        if (tid == 0) logits[c] = red[0] + bc2[c & 1];
    }
    __syncthreads();
    if (tid == 0) {
        for (int b = 0; b < BATCH; b++) {
            float l0 = logits[2 * b], l1 = logits[2 * b + 1];
            float m = fmaxf(l0, l1);
            float e0 = expf(l0 - m), e1 = expf(l1 - m);
            out[b] = e1 / (e0 + e1);
        }
    }
}

// ---------------- Launch ----------------
extern "C" void kernel_launch(void* const* d_in, const int* in_sizes, int n_in,
                              void* d_out, int out_size) {
    const int*   ids   = (const int*)d_in[0];
    const int*   amask = (const int*)d_in[1];
    const float* emb   = (const float*)d_in[2];
    const float* ln1_g = (const float*)d_in[3];
    const float* ln1_b = (const float*)d_in[4];
    const float* Wqkv  = (const float*)d_in[5];
    const float* Wo    = (const float*)d_in[6];
    const float* ln2_g = (const float*)d_in[7];
    const float* ln2_b = (const float*)d_in[8];
    const float* W1    = (const float*)d_in[9];
    const float* W2    = (const float*)d_in[10];
    const float* lnf_g = (const float*)d_in[11];
    const float* lnf_b = (const float*)d_in[12];
    const float* Wc1   = (const float*)d_in[13];
    const float* bc1   = (const float*)d_in[14];
    const float* Wc2   = (const float*)d_in[15];
    const float* bc2   = (const float*)d_in[16];
    float* out = (float*)d_out;

    float *x, *h, *qkv, *mean, *t;
    __half *ha_d, *ha_f, *qh, *kh, *vt, *wqkvT, *woT, *w1T, *w2T;
    cudaGetSymbolAddress((void**)&x,    g_x);
    cudaGetSymbolAddress((void**)&h,    g_h);
    cudaGetSymbolAddress((void**)&qkv,  g_qkv);
    cudaGetSymbolAddress((void**)&mean, g_mean);
    cudaGetSymbolAddress((void**)&t,    g_t);
    cudaGetSymbolAddress((void**)&ha_d, g_ha_d);
    cudaGetSymbolAddress((void**)&ha_f, g_ha_f);
    cudaGetSymbolAddress((void**)&qh,   g_qh);
    cudaGetSymbolAddress((void**)&kh,   g_kh);
    cudaGetSymbolAddress((void**)&vt,   g_vt);
    cudaGetSymbolAddress((void**)&wqkvT, g_wqkvT);
    cudaGetSymbolAddress((void**)&woT,   g_woT);
    cudaGetSymbolAddress((void**)&w1T,   g_w1T);
    cudaGetSymbolAddress((void**)&w2T,   g_w2T);

    cudaFuncSetAttribute(bgemm_kernel<0>,
                         cudaFuncAttributeMaxDynamicSharedMemorySize, BG_SMEM);
    cudaFuncSetAttribute(bgemm_kernel<1>,
                         cudaFuncAttributeMaxDynamicSharedMemorySize, BG_SMEM);
    cudaFuncSetAttribute(bgemm_kernel<2>,
                         cudaFuncAttributeMaxDynamicSharedMemorySize, BG_SMEM);
    cudaFuncSetAttribute(attn_kernel,
                         cudaFuncAttributeMaxDynamicSharedMemorySize, AT_SMEM);

    embed_kernel<<<(BS * D) / 256, 256>>>(ids, emb, x);

    for (int l = 0; l < LAYERS; l++) {
        // attention block
        ln_kernel<1><<<BS, 256>>>(x, ln1_g + (size_t)l * D, ln1_b + (size_t)l * D,
                                  nullptr, ha_d);
        transw_kernel<<<dim3(TD / 32, D / 32), dim3(32, 8)>>>(
            Wqkv + (size_t)l * D * TD, wqkvT, D, TD);
        bgemm_kernel<0><<<dim3(BS / 128, TD / 128), 128, BG_SMEM>>>(
            ha_d, wqkvT, qkv, nullptr, BS, TD, D);
        qkconv_kernel<<<BS, 256>>>(qkv, qh, kh);
        vtrans_kernel<<<dim3(SEQ / 32, DH / 32, BATCH * H), dim3(32, 8)>>>(qkv, vt);
        attn_kernel<<<dim3(SEQ / 64, H, BATCH), 128, AT_SMEM>>>(
            qh, kh, vt, amask, ha_d);
        transw_kernel<<<dim3(D / 32, D / 32), dim3(32, 8)>>>(
            Wo + (size_t)l * D * D, woT, D, D);
        bgemm_kernel<1><<<dim3(BS / 128, D / 128), 128, BG_SMEM>>>(
            ha_d, woT, x, nullptr, BS, D, D);
        // mlp block
        ln_kernel<1><<<BS, 256>>>(x, ln2_g + (size_t)l * D, ln2_b + (size_t)l * D,
                                  nullptr, ha_d);
        transw_kernel<<<dim3(FF / 32, D / 32), dim3(32, 8)>>>(
            W1 + (size_t)l * D * FF, w1T, D, FF);
        bgemm_kernel<2><<<dim3(BS / 128, FF / 128), 128, BG_SMEM>>>(
            ha_d, w1T, nullptr, ha_f, BS, FF, D);
        transw_kernel<<<dim3(D / 32, FF / 32), dim3(32, 8)>>>(
            W2 + (size_t)l * FF * D, w2T, FF, D);
        bgemm_kernel<1><<<dim3(BS / 128, D / 128), 128, BG_SMEM>>>(
            ha_f, w2T, x, nullptr, BS, D, FF);
    }

    ln_kernel<0><<<BS, 256>>>(x, lnf_g, lnf_b, h, nullptr);
    meanpool_kernel<<<(BATCH * D) / 256, 256>>>(h, amask, mean);
    head1_kernel<<<(BATCH * D) / 256, 256>>>(mean, Wc1, bc1, t);
    head2_kernel<<<1, 256>>>(t, Wc2, bc2, out);
}

// round 15
// speedup vs baseline: 5.2500x; 1.0325x over previous
#include <cuda_runtime.h>
#include <cuda_fp16.h>
#include <math.h>
#include <stdint.h>

// ---------------- Problem constants ----------------
#define LAYERS 2
#define D      2048
#define H      16
#define FF     8192
#define BATCH  2
#define SEQ    1024
#define DH     128
#define TD     (3 * D)
#define BS     (BATCH * SEQ)
#define NEGB   (-1e9f)
#define SCALE  0.08838834764831845f
#define SCALE2 (0.08838834764831845f * 1.4426950408889634f)
#define WS     512.0f
#define WS_INV (1.0f / 512.0f)

// ---------------- Scratch (static device globals) ----------------
__device__ float g_x   [BS * D];
__device__ float g_h   [BS * D];
__device__ float g_mean[BATCH * D];
__device__ float g_t   [BATCH * D];
// fp16 activation buffers
__device__ __half g_ha_d[BS * D];
__device__ __half g_ha_f[BS * FF];
// fp16 attention operands (head-major)
__device__ __half g_qh[BS * D];      // [b][h][q][d]
__device__ __half g_kh[BS * D];      // [b][h][j][d]
__device__ __half g_vh[BS * D];      // [b][h][j][d]
__device__ __half g_vt[BS * D];      // [b][h][d][j]
// fp16 transposed scaled weights (per layer)
__device__ __half g_wqkvT[LAYERS * TD * D];
__device__ __half g_woT  [LAYERS * D * D];
__device__ __half g_w1T  [LAYERS * FF * D];
__device__ __half g_w2T  [LAYERS * D * FF];

// ---------------- Embedding gather ----------------
__global__ void embed_kernel(const int* __restrict__ ids,
                             const float* __restrict__ emb,
                             float* __restrict__ x) {
    int idx = blockIdx.x * blockDim.x + threadIdx.x;
    int tok = ids[idx / D];
    x[idx] = emb[(size_t)tok * D + (idx % D)];
}

// ---------------- LayerNorm; HOUT=1 writes fp16 ----------------
template<int HOUT>
__global__ void ln_kernel(const float* __restrict__ x,
                          const float* __restrict__ g,
                          const float* __restrict__ b,
                          float* __restrict__ outf,
                          __half* __restrict__ outh) {
    __shared__ float row[D];
    __shared__ float red[256];
    const int tid = threadIdx.x;
    const float* xr = x + (size_t)blockIdx.x * D;

    float s = 0.f;
    for (int i = tid; i < D; i += 256) { float v = xr[i]; row[i] = v; s += v; }
    red[tid] = s; __syncthreads();
    for (int st = 128; st > 0; st >>= 1) {
        if (tid < st) red[tid] += red[tid + st];
        __syncthreads();
    }
    const float mean = red[0] * (1.0f / D);
    __syncthreads();

    float s2 = 0.f;
    for (int i = tid; i < D; i += 256) { float v = row[i] - mean; s2 += v * v; }
    red[tid] = s2; __syncthreads();
    for (int st = 128; st > 0; st >>= 1) {
        if (tid < st) red[tid] += red[tid + st];
        __syncthreads();
    }
    const float rstd = rsqrtf(red[0] * (1.0f / D) + 1e-5f);

    if (HOUT) {
        __half* orow = outh + (size_t)blockIdx.x * D;
        for (int i = tid; i < D; i += 256)
            orow[i] = __float2half_rn((row[i] - mean) * rstd * g[i] + b[i]);
    } else {
        float* orow = outf + (size_t)blockIdx.x * D;
        for (int i = tid; i < D; i += 256)
            orow[i] = (row[i] - mean) * rstd * g[i] + b[i];
    }
}

// ---------------- Transpose + scale weights: W[K,N] -> Wt[N,K] fp16*WS ----------------
// 64k x 32n tiles, half2 writes
__global__ void transw_kernel(const float* __restrict__ W,
                              __half* __restrict__ Wt, int K, int N) {
    __shared__ float tile[64][33];
    int n0 = blockIdx.x * 32, k0 = blockIdx.y * 64;
    int tx = threadIdx.x, ty = threadIdx.y;   // (32, 8)
    #pragma unroll
    for (int i = 0; i < 64; i += 8)
        tile[ty + i][tx] = W[(size_t)(k0 + ty + i) * N + n0 + tx];
    __syncthreads();
    #pragma unroll
    for (int i = 0; i < 32; i += 8) {
        int nn = ty + i;
        int n = n0 + nn;
        __half2 w2 = __floats2half2_rn(tile[2 * tx][nn] * WS,
                                       tile[2 * tx + 1][nn] * WS);
        *(__half2*)(Wt + (size_t)n * K + k0 + 2 * tx) = w2;
    }
}

// ---------------- fp16 V transpose: vh[bh][j][d] -> vt[bh][d][j] ----------------
__global__ void vtrans16_kernel(const __half* __restrict__ vh,
                                __half* __restrict__ vt) {
    __shared__ __half tile[32][34];
    int j0 = blockIdx.x * 32, d0 = blockIdx.y * 32;
    int bh = blockIdx.z;
    int tx = threadIdx.x, ty = threadIdx.y;   // (32, 8)
    #pragma unroll
    for (int i = 0; i < 32; i += 8)
        tile[ty + i][tx] = vh[((size_t)bh * SEQ + j0 + ty + i) * DH + d0 + tx];
    __syncthreads();
    #pragma unroll
    for (int i = 0; i < 32; i += 8)
        vt[((size_t)bh * DH + d0 + ty + i) * SEQ + j0 + tx] = tile[tx][ty + i];
}

// ---------------- Shared MMA helpers ----------------
__device__ __forceinline__ unsigned swz(unsigned o) { return o ^ ((o >> 3) & 0x70); }

__device__ __forceinline__ void ldsm4(unsigned addr, unsigned& r0, unsigned& r1,
                                      unsigned& r2, unsigned& r3) {
    asm volatile("ldmatrix.sync.aligned.m8n8.x4.shared.b16 {%0,%1,%2,%3}, [%4];\n"
                 : "=r"(r0), "=r"(r1), "=r"(r2), "=r"(r3) : "r"(addr));
}
__device__ __forceinline__ void mma16816(float* c, unsigned a0, unsigned a1,
                                         unsigned a2, unsigned a3,
                                         unsigned b0, unsigned b1) {
    asm volatile(
        "mma.sync.aligned.m16n8k16.row.col.f32.f16.f16.f32 "
        "{%0,%1,%2,%3},{%4,%5,%6,%7},{%8,%9},{%0,%1,%2,%3};\n"
        : "+f"(c[0]), "+f"(c[1]), "+f"(c[2]), "+f"(c[3])
        : "r"(a0), "r"(a1), "r"(a2), "r"(a3), "r"(b0), "r"(b1));
}
__device__ __forceinline__ void cpasync16(unsigned saddr, const void* g) {
    asm volatile("cp.async.cg.shared.global [%0], [%1], 16;\n" :: "r"(saddr), "l"(g));
}
__device__ __forceinline__ unsigned ex2h2(float lo, float hi) {
    __half2 t = __floats2half2_rn(lo, hi);
    unsigned u = *reinterpret_cast<unsigned*>(&t);
    unsigned r;
    asm("ex2.approx.f16x2 %0, %1;" : "=r"(r) : "r"(u));
    return r;
}
__device__ __forceinline__ unsigned prow(int r, int seg16) {
    return (unsigned)((r >> 1) * 128 + (r & 1) * 64 + seg16 * 16);
}

// ========= fp16 GEMM =========
// EPI: 0 = store fp32, 1 = residual add fp32, 2 = gelu->fp16, 3 = qkv split fp16 head-major
#define BG_STAGE  16384
#define BG_SMEM   (4 * BG_STAGE)

__device__ __forceinline__ void load_tile(const __half* gbase, unsigned sbase,
                                          int ld, int k0) {
    int t = threadIdx.x;
    #pragma unroll
    for (int i = 0; i < 4; i++) {
        int c = t + i * 128;
        int row = c >> 2, seg = c & 3;
        cpasync16(sbase + swz(prow(row, seg)), gbase + (size_t)row * ld + k0 + seg * 8);
    }
}

__device__ __forceinline__ void ldsm_frags(const unsigned aA[4], const unsigned bA[4],
                                           unsigned off,
                                           unsigned fa[4][4], unsigned fb[4][4]) {
    #pragma unroll
    for (int mi = 0; mi < 4; mi++)
        ldsm4(aA[mi] ^ off, fa[mi][0], fa[mi][1], fa[mi][2], fa[mi][3]);
    #pragma unroll
    for (int np = 0; np < 4; np++)
        ldsm4(bA[np] ^ off, fb[np][0], fb[np][1], fb[np][2], fb[np][3]);
}

__device__ __forceinline__ void mma_tile(float acc[4][8][4],
                                         unsigned fa[4][4], unsigned fb[4][4]) {
    #pragma unroll
    for (int mi = 0; mi < 4; mi++)
        #pragma unroll
        for (int ni = 0; ni < 8; ni++) {
            unsigned b0 = fb[ni >> 1][ni & 1];
            unsigned b1 = fb[ni >> 1][2 + (ni & 1)];
            mma16816(acc[mi][ni], fa[mi][0], fa[mi][1], fa[mi][2], fa[mi][3], b0, b1);
        }
}

__device__ __forceinline__ float gelu_f(float xx) {
    return 0.5f * xx * (1.0f + tanhf(0.7978845608028654f *
                                     (xx + 0.044715f * xx * xx * xx)));
}

template<int EPI>
__global__ void __launch_bounds__(128, 2)
bgemm_kernel(const __half* __restrict__ A,
             const __half* __restrict__ Bt,
             float* __restrict__ C,
             __half* __restrict__ Hout,
             __half* __restrict__ Qh,
             __half* __restrict__ Kh,
             __half* __restrict__ Vh,
             int M, int N, int K) {
    extern __shared__ __align__(128) char smem[];
    unsigned sbase = (unsigned)__cvta_generic_to_shared(smem);

    const int tid = threadIdx.x, lane = tid & 31, warp = tid >> 5;
    const int warpM = warp & 1, warpN = warp >> 1;
    const int rowBase = blockIdx.x * 128;
    const int colBase = blockIdx.y * 128;
    const __half* Ab = A  + (size_t)rowBase * K;
    const __half* Bb = Bt + (size_t)colBase * K;

    float acc[4][8][4];
    #pragma unroll
    for (int i = 0; i < 4; i++)
        #pragma unroll
        for (int j = 0; j < 8; j++)
            #pragma unroll
            for (int r = 0; r < 4; r++) acc[i][j][r] = 0.f;

    const int KT = K >> 5;
    #pragma unroll
    for (int s = 0; s < 3; s++) {
        unsigned st = sbase + s * BG_STAGE;
        load_tile(Ab, st, K, s << 5);
        load_tile(Bb, st + 8192, K, s << 5);
        asm volatile("cp.async.commit_group;\n");
    }

    unsigned aAB[4], bAB[4];
    #pragma unroll
    for (int mi = 0; mi < 4; mi++) {
        int row = warpM * 64 + mi * 16 + (lane & 15);
        aAB[mi] = swz(prow(row, lane >> 4));
    }
    #pragma unroll
    for (int np = 0; np < 4; np++) {
        int rown = warpN * 64 + np * 16 + (lane & 15);
        bAB[np] = 8192u + swz(prow(rown, lane >> 4));
    }

    unsigned fa[4][4], fb[4][4];

    for (int kt = 0; kt < KT; kt++) {
        asm volatile("cp.async.wait_group 2;\n");
        __syncthreads();

        unsigned stg = sbase + (unsigned)(kt & 3) * BG_STAGE;
        unsigned aA[4] = { stg + aAB[0], stg + aAB[1], stg + aAB[2], stg + aAB[3] };
        unsigned bA[4] = { stg + bAB[0], stg + bAB[1], stg + bAB[2], stg + bAB[3] };

        ldsm_frags(aA, bA, 0, fa, fb);

        const int next = kt + 3;
        if (next < KT) {
            unsigned ns = sbase + (unsigned)(next & 3) * BG_STAGE;
            load_tile(Ab, ns, K, next << 5);
            load_tile(Bb, ns + 8192, K, next << 5);
        }
        asm volatile("cp.async.commit_group;\n");

        mma_tile(acc, fa, fb);
        ldsm_frags(aA, bA, 32, fa, fb);
        mma_tile(acc, fa, fb);
    }

    #pragma unroll
    for (int mi = 0; mi < 4; mi++)
        #pragma unroll
        for (int ni = 0; ni < 8; ni++) {
            int row = rowBase + warpM * 64 + mi * 16 + (lane >> 2);
            int col = colBase + warpN * 64 + ni * 8 + 2 * (lane & 3);
            float v0 = acc[mi][ni][0] * WS_INV, v1 = acc[mi][ni][1] * WS_INV;
            float v2 = acc[mi][ni][2] * WS_INV, v3 = acc[mi][ni][3] * WS_INV;
            if (EPI == 2) {
                __half2* hp = (__half2*)(Hout + (size_t)row * N + col);
                __half2* hq = (__half2*)(Hout + (size_t)(row + 8) * N + col);
                *hp = __floats2half2_rn(gelu_f(v0), gelu_f(v1));
                *hq = __floats2half2_rn(gelu_f(v2), gelu_f(v3));
            } else if (EPI == 3) {
                // qkv split: head-major fp16
                int part = col >> 11;           // 0=q 1=k 2=v
                int hh = (col >> 7) & 15;
                int d  = col & 127;
                __half* dst = (part == 0) ? Qh : (part == 1) ? Kh : Vh;
                int bA0 = row >> 10, sA0 = row & 1023;
                int rB = row + 8;
                int bB0 = rB >> 10, sB0 = rB & 1023;
                *(__half2*)(dst + (((size_t)(bA0 * H + hh) * SEQ) + sA0) * DH + d) =
                    __floats2half2_rn(v0, v1);
                *(__half2*)(dst + (((size_t)(bB0 * H + hh) * SEQ) + sB0) * DH + d) =
                    __floats2half2_rn(v2, v3);
            } else {
                float* p = C + (size_t)row * N + col;
                float* q = C + (size_t)(row + 8) * N + col;
                if (EPI == 1) { v0 += p[0]; v1 += p[1]; v2 += q[0]; v3 += q[1]; }
                *(float2*)p = make_float2(v0, v1);
                *(float2*)q = make_float2(v2, v3);
            }
        }
}

// ========= Tensor-core flash attention (unchanged from R14) =========
#define AT_SMEM (4096 + 16384 + 2 * 16384)

__global__ void __launch_bounds__(128)
attn_kernel(const __half* __restrict__ qh,
            const __half* __restrict__ kh,
            const __half* __restrict__ vt,
            const int* __restrict__ mask,
            __half* __restrict__ ao) {
    extern __shared__ __align__(128) char asmem[];
    float* bias = (float*)asmem;
    unsigned sb = (unsigned)__cvta_generic_to_shared(asmem);
    const unsigned Qs  = sb + 4096;
    const unsigned KV0 = sb + 20480;

    const int tid = threadIdx.x, lane = tid & 31, warp = tid >> 5;
    const int q0 = blockIdx.x * 64;
    const int h = blockIdx.y, b = blockIdx.z;
    const int bh = b * H + h;
    const int nc = 2 * (blockIdx.x + 1);

    for (int i = tid; i < SEQ; i += 128)
        bias[i] = (mask[b * SEQ + i] == 0) ? NEGB : 0.f;

    {
        const __half* qb = qh + ((size_t)bh * SEQ + q0) * DH;
        #pragma unroll
        for (int i = 0; i < 8; i++) {
            int g = tid + i * 128;
            int seg = g & 3, r = (g >> 2) & 15, s = (g >> 6) & 3, w = g >> 8;
            cpasync16(Qs + w * 4096 + s * 1024 + swz(prow(r, seg)),
                      qb + (size_t)(w * 16 + r) * DH + s * 32 + seg * 8);
        }
    }
    auto load_kv = [&](int c, int buf) {
        int j0 = c * 32;
        unsigned Kb = KV0 + buf * 16384;
        const __half* kb = kh + ((size_t)bh * SEQ + j0) * DH;
        const __half* vb = vt + (size_t)bh * DH * SEQ + j0;
        #pragma unroll
        for (int i = 0; i < 4; i++) {
            int g = tid + i * 128;
            int seg = g & 3, r = (g >> 2) & 31, s = g >> 7;
            cpasync16(Kb + s * 2048 + swz(prow(r, seg)),
                      kb + (size_t)r * DH + s * 32 + seg * 8);
        }
        #pragma unroll
        for (int i = 0; i < 4; i++) {
            int g = tid + i * 128;
            int seg = g & 3, d = g >> 2;
            cpasync16(Kb + 8192 + swz(prow(d, seg)),
                      vb + (size_t)d * SEQ + seg * 8);
        }
    };

    load_kv(0, 0);
    asm volatile("cp.async.commit_group;\n");
    load_kv(1, 1);
    asm volatile("cp.async.commit_group;\n");

    const unsigned qA = Qs + warp * 4096 + swz(prow(lane & 15, lane >> 4));
    unsigned kB[2], vB[8];
    #pragma unroll
    for (int np = 0; np < 2; np++)
        kB[np] = swz(prow(np * 16 + (lane & 15), lane >> 4));
    #pragma unroll
    for (int np = 0; np < 8; np++)
        vB[np] = swz(prow(np * 16 + (lane & 15), lane >> 4));

    const int rowA = q0 + warp * 16 + (lane >> 2);
    const int rowB = rowA + 8;

    float o[16][4];
    #pragma unroll
    for (int i = 0; i < 16; i++)
        #pragma unroll
        for (int r = 0; r < 4; r++) o[i][r] = 0.f;
    float mA = -1e30f, mB = -1e30f, lA = 0.f, lB = 0.f;

    for (int c = 0; c < nc; c++) {
        asm volatile("cp.async.wait_group 1;\n");
        __syncthreads();
        unsigned Kb = KV0 + (unsigned)(c & 1) * 16384;
        unsigned Vb = Kb + 8192;

        float sc[4][4];
        #pragma unroll
        for (int i = 0; i < 4; i++)
            #pragma unroll
            for (int r = 0; r < 4; r++) sc[i][r] = 0.f;
        #pragma unroll
        for (int s = 0; s < 4; s++) {
            #pragma unroll
            for (int t = 0; t < 2; t++) {
                unsigned fa0, fa1, fa2, fa3;
                ldsm4((qA + s * 1024) ^ (t * 32), fa0, fa1, fa2, fa3);
                #pragma unroll
                for (int np = 0; np < 2; np++) {
                    unsigned b0, b1, b2, b3;
                    ldsm4((Kb + s * 2048 + kB[np]) ^ (t * 32), b0, b1, b2, b3);
                    mma16816(sc[2 * np],     fa0, fa1, fa2, fa3, b0, b2);
                    mma16816(sc[2 * np + 1], fa0, fa1, fa2, fa3, b1, b3);
                }
            }
        }

        const int j0 = c * 32;
        #pragma unroll
        for (int ni = 0; ni < 4; ni++) {
            int jb = j0 + ni * 8 + 2 * (lane & 3);
            float b0 = bias[jb], b1 = bias[jb + 1];
            sc[ni][0] = (jb     <= rowA) ? sc[ni][0] * SCALE2 + b0 : -1e30f;
            sc[ni][1] = (jb + 1 <= rowA) ? sc[ni][1] * SCALE2 + b1 : -1e30f;
            sc[ni][2] = (jb     <= rowB) ? sc[ni][2] * SCALE2 + b0 : -1e30f;
            sc[ni][3] = (jb + 1 <= rowB) ? sc[ni][3] * SCALE2 + b1 : -1e30f;
        }

        float cmA = -1e30f, cmB = -1e30f;
        #pragma unroll
        for (int ni = 0; ni < 4; ni++) {
            cmA = fmaxf(cmA, fmaxf(sc[ni][0], sc[ni][1]));
            cmB = fmaxf(cmB, fmaxf(sc[ni][2], sc[ni][3]));
        }
        #pragma unroll
        for (int off = 1; off <= 2; off <<= 1) {
            cmA = fmaxf(cmA, __shfl_xor_sync(0xffffffffu, cmA, off));
            cmB = fmaxf(cmB, __shfl_xor_sync(0xffffffffu, cmB, off));
        }
        float newA = fmaxf(mA, cmA), newB = fmaxf(mB, cmB);
        float corrA = exp2f(mA - newA), corrB = exp2f(mB - newB);
        mA = newA; mB = newB;

        unsigned hA[4], hB[4];
        float sA = 0.f, sB = 0.f;
        #pragma unroll
        for (int ni = 0; ni < 4; ni++) {
            hA[ni] = ex2h2(sc[ni][0] - newA, sc[ni][1] - newA);
            hB[ni] = ex2h2(sc[ni][2] - newB, sc[ni][3] - newB);
            float2 fa2 = __half22float2(*(__half2*)&hA[ni]);
            float2 fb2 = __half22float2(*(__half2*)&hB[ni]);
            sA += fa2.x + fa2.y;
            sB += fb2.x + fb2.y;
        }
        #pragma unroll
        for (int off = 1; off <= 2; off <<= 1) {
            sA += __shfl_xor_sync(0xffffffffu, sA, off);
            sB += __shfl_xor_sync(0xffffffffu, sB, off);
        }
        lA = lA * corrA + sA;
        lB = lB * corrB + sB;
        #pragma unroll
        for (int ni = 0; ni < 16; ni++) {
            o[ni][0] *= corrA; o[ni][1] *= corrA;
            o[ni][2] *= corrB; o[ni][3] *= corrB;
        }

        #pragma unroll
        for (int t = 0; t < 2; t++) {
            unsigned a0 = hA[2 * t], a1 = hB[2 * t];
            unsigned a2 = hA[2 * t + 1], a3 = hB[2 * t + 1];
            #pragma unroll
            for (int np = 0; np < 8; np++) {
                unsigned b0, b1, b2, b3;
                ldsm4((Vb + vB[np]) ^ (t * 32), b0, b1, b2, b3);
                mma16816(o[2 * np],     a0, a1, a2, a3, b0, b2);
                mma16816(o[2 * np + 1], a0, a1, a2, a3, b1, b3);
            }
        }

        __syncthreads();
        if (c + 2 < nc) load_kv(c + 2, c & 1);
        asm volatile("cp.async.commit_group;\n");
    }

    const float invA = 1.f / lA, invB = 1.f / lB;
    const size_t baseA = ((size_t)(b * SEQ + rowA)) * D + h * DH;
    const size_t baseB = ((size_t)(b * SEQ + rowB)) * D + h * DH;
    #pragma unroll
    for (int ni = 0; ni < 16; ni++) {
        int col = ni * 8 + 2 * (lane & 3);
        *(__half2*)(ao + baseA + col) = __floats2half2_rn(o[ni][0] * invA, o[ni][1] * invA);
        *(__half2*)(ao + baseB + col) = __floats2half2_rn(o[ni][2] * invB, o[ni][3] * invB);
    }
}

// ---------------- Pool + head ----------------
__global__ void meanpool_kernel(const float* __restrict__ hs,
                                const int* __restrict__ mask,
                                float* __restrict__ mean) {
    int idx = blockIdx.x * blockDim.x + threadIdx.x;
    int b = idx / D;
    int d = idx % D;
    float acc = 0.f, msum = 0.f;
    const float* hb = hs + (size_t)b * SEQ * D + d;
    const int* mb = mask + b * SEQ;
    for (int s = 0; s < SEQ; s++) {
        float mf = (float)mb[s];
        acc = fmaf(mf, hb[(size_t)s * D], acc);
        msum += mf;
    }
    mean[idx] = acc / fmaxf(msum, 1e-9f);
}

__global__ void head1_kernel(const float* __restrict__ mean,
                             const float* __restrict__ Wc1,
                             const float* __restrict__ bc1,
                             float* __restrict__ t) {
    int idx = blockIdx.x * blockDim.x + threadIdx.x;
    int b = idx / D;
    int j = idx % D;
    float acc = bc1[j];
    const float* mb = mean + (size_t)b * D;
    for (int k = 0; k < D; k++)
        acc = fmaf(mb[k], Wc1[(size_t)k * D + j], acc);
    t[idx] = tanhf(acc);
}

__global__ void head2_kernel(const float* __restrict__ t,
                             const float* __restrict__ Wc2,
                             const float* __restrict__ bc2,
                             float* __restrict__ out) {
    __shared__ float red[256];
    __shared__ float logits[4];
    const int tid = threadIdx.x;
    float part[4] = {0.f, 0.f, 0.f, 0.f};
    for (int j = tid; j < D; j += 256) {
        float t0 = t[j], t1 = t[D + j];
        float w0 = Wc2[2 * j], w1 = Wc2[2 * j + 1];
        part[0] = fmaf(t0, w0, part[0]);
        part[1] = fmaf(t0, w1, part[1]);
        part[2] = fmaf(t1, w0, part[2]);
        part[3] = fmaf(t1, w1, part[3]);
    }
    for (int c = 0; c < 4; c++) {
        __syncthreads();
        red[tid] = part[c]; __syncthreads();
        for (int st = 128; st > 0; st >>= 1) {
            if (tid < st) red[tid] += red[tid + st];
            __syncthreads();
        }
        if (tid == 0) logits[c] = red[0] + bc2[c & 1];
    }
    __syncthreads();
    if (tid == 0) {
        for (int b = 0; b < BATCH; b++) {
            float l0 = logits[2 * b], l1 = logits[2 * b + 1];
            float m = fmaxf(l0, l1);
            float e0 = expf(l0 - m), e1 = expf(l1 - m);
            out[b] = e1 / (e0 + e1);
        }
    }
}

// ---------------- Launch ----------------
extern "C" void kernel_launch(void* const* d_in, const int* in_sizes, int n_in,
                              void* d_out, int out_size) {
    const int*   ids   = (const int*)d_in[0];
    const int*   amask = (const int*)d_in[1];
    const float* emb   = (const float*)d_in[2];
    const float* ln1_g = (const float*)d_in[3];
    const float* ln1_b = (const float*)d_in[4];
    const float* Wqkv  = (const float*)d_in[5];
    const float* Wo    = (const float*)d_in[6];
    const float* ln2_g = (const float*)d_in[7];
    const float* ln2_b = (const float*)d_in[8];
    const float* W1    = (const float*)d_in[9];
    const float* W2    = (const float*)d_in[10];
    const float* lnf_g = (const float*)d_in[11];
    const float* lnf_b = (const float*)d_in[12];
    const float* Wc1   = (const float*)d_in[13];
    const float* bc1   = (const float*)d_in[14];
    const float* Wc2   = (const float*)d_in[15];
    const float* bc2   = (const float*)d_in[16];
    float* out = (float*)d_out;

    float *x, *h, *mean, *t;
    __half *ha_d, *ha_f, *qh, *kh, *vh, *vt, *wqkvT, *woT, *w1T, *w2T;
    cudaGetSymbolAddress((void**)&x,    g_x);
    cudaGetSymbolAddress((void**)&h,    g_h);
    cudaGetSymbolAddress((void**)&mean, g_mean);
    cudaGetSymbolAddress((void**)&t,    g_t);
    cudaGetSymbolAddress((void**)&ha_d, g_ha_d);
    cudaGetSymbolAddress((void**)&ha_f, g_ha_f);
    cudaGetSymbolAddress((void**)&qh,   g_qh);
    cudaGetSymbolAddress((void**)&kh,   g_kh);
    cudaGetSymbolAddress((void**)&vh,   g_vh);
    cudaGetSymbolAddress((void**)&vt,   g_vt);
    cudaGetSymbolAddress((void**)&wqkvT, g_wqkvT);
    cudaGetSymbolAddress((void**)&woT,   g_woT);
    cudaGetSymbolAddress((void**)&w1T,   g_w1T);
    cudaGetSymbolAddress((void**)&w2T,   g_w2T);

    cudaFuncSetAttribute(bgemm_kernel<1>,
                         cudaFuncAttributeMaxDynamicSharedMemorySize, BG_SMEM);
    cudaFuncSetAttribute(bgemm_kernel<2>,
                         cudaFuncAttributeMaxDynamicSharedMemorySize, BG_SMEM);
    cudaFuncSetAttribute(bgemm_kernel<3>,
                         cudaFuncAttributeMaxDynamicSharedMemorySize, BG_SMEM);
    cudaFuncSetAttribute(attn_kernel,
                         cudaFuncAttributeMaxDynamicSharedMemorySize, AT_SMEM);

    // Side stream: all weight transposes, fine-grained join events.
    cudaStream_t s2;
    cudaStreamCreateWithFlags(&s2, cudaStreamNonBlocking);
    cudaEvent_t evFork, evW[8];
    cudaEventCreateWithFlags(&evFork, cudaEventDisableTiming);
    for (int i = 0; i < 8; i++)
        cudaEventCreateWithFlags(&evW[i], cudaEventDisableTiming);

    cudaEventRecord(evFork, 0);
    cudaStreamWaitEvent(s2, evFork, 0);
    for (int l = 0; l < LAYERS; l++) {
        transw_kernel<<<dim3(TD / 32, D / 64), dim3(32, 8), 0, s2>>>(
            Wqkv + (size_t)l * D * TD, wqkvT + (size_t)l * TD * D, D, TD);
        cudaEventRecord(evW[l * 4 + 0], s2);
        transw_kernel<<<dim3(D / 32, D / 64), dim3(32, 8), 0, s2>>>(
            Wo + (size_t)l * D * D, woT + (size_t)l * D * D, D, D);
        cudaEventRecord(evW[l * 4 + 1], s2);
        transw_kernel<<<dim3(FF / 32, D / 64), dim3(32, 8), 0, s2>>>(
            W1 + (size_t)l * D * FF, w1T + (size_t)l * FF * D, D, FF);
        cudaEventRecord(evW[l * 4 + 2], s2);
        transw_kernel<<<dim3(D / 32, FF / 64), dim3(32, 8), 0, s2>>>(
            W2 + (size_t)l * FF * D, w2T + (size_t)l * D * FF, FF, D);
        cudaEventRecord(evW[l * 4 + 3], s2);
    }

    embed_kernel<<<(BS * D) / 256, 256>>>(ids, emb, x);

    for (int l = 0; l < LAYERS; l++) {
        // attention block
        ln_kernel<1><<<BS, 256>>>(x, ln1_g + (size_t)l * D, ln1_b + (size_t)l * D,
                                  nullptr, ha_d);
        cudaStreamWaitEvent(0, evW[l * 4 + 0], 0);
        bgemm_kernel<3><<<dim3(BS / 128, TD / 128), 128, BG_SMEM>>>(
            ha_d, wqkvT + (size_t)l * TD * D, nullptr, nullptr,
            qh, kh, vh, BS, TD, D);
        vtrans16_kernel<<<dim3(SEQ / 32, DH / 32, BATCH * H), dim3(32, 8)>>>(vh, vt);
        attn_kernel<<<dim3(SEQ / 64, H, BATCH), 128, AT_SMEM>>>(
            qh, kh, vt, amask, ha_d);
        cudaStreamWaitEvent(0, evW[l * 4 + 1], 0);
        bgemm_kernel<1><<<dim3(BS / 128, D / 128), 128, BG_SMEM>>>(
            ha_d, woT + (size_t)l * D * D, x, nullptr,
            nullptr, nullptr, nullptr, BS, D, D);
        // mlp block
        ln_kernel<1><<<BS, 256>>>(x, ln2_g + (size_t)l * D, ln2_b + (size_t)l * D,
                                  nullptr, ha_d);
        cudaStreamWaitEvent(0, evW[l * 4 + 2], 0);
        bgemm_kernel<2><<<dim3(BS / 128, FF / 128), 128, BG_SMEM>>>(
            ha_d, w1T + (size_t)l * FF * D, nullptr, ha_f,
            nullptr, nullptr, nullptr, BS, FF, D);
        cudaStreamWaitEvent(0, evW[l * 4 + 3], 0);
        bgemm_kernel<1><<<dim3(BS / 128, D / 128), 128, BG_SMEM>>>(
            ha_f, w2T + (size_t)l * D * FF, x, nullptr,
            nullptr, nullptr, nullptr, BS, D, FF);
    }

    ln_kernel<0><<<BS, 256>>>(x, lnf_g, lnf_b, h, nullptr);
    meanpool_kernel<<<(BATCH * D) / 256, 256>>>(h, amask, mean);
    head1_kernel<<<(BATCH * D) / 256, 256>>>(mean, Wc1, bc1, t);
    head2_kernel<<<1, 256>>>(t, Wc2, bc2, out);
}

// round 16
// speedup vs baseline: 5.3171x; 1.0128x over previous
#include <cuda_runtime.h>
#include <cuda_fp16.h>
#include <math.h>
#include <stdint.h>

// ---------------- Problem constants ----------------
#define LAYERS 2
#define D      2048
#define H      16
#define FF     8192
#define BATCH  2
#define SEQ    1024
#define DH     128
#define TD     (3 * D)
#define BS     (BATCH * SEQ)
#define NEGB   (-1e9f)
#define SCALE  0.08838834764831845f
#define SCALE2 (0.08838834764831845f * 1.4426950408889634f)
#define WS     512.0f
#define WS_INV (1.0f / 512.0f)

// ---------------- Scratch (static device globals) ----------------
__device__ float g_x   [BS * D];
__device__ float g_h   [BS * D];
__device__ float g_mean[BATCH * D];
__device__ float g_t   [BATCH * D];
// fp16 activation buffers
__device__ __half g_ha_d[BS * D];
__device__ __half g_ha_f[BS * FF];
// fp16 attention operands (head-major)
__device__ __half g_qh[BS * D];
__device__ __half g_kh[BS * D];
__device__ __half g_vh[BS * D];
__device__ __half g_vt[BS * D];
// split-KV partials: [split][b][h][row][d] fp32, and (m,l) pairs
__device__ float g_opart[2 * BS * D];
__device__ float g_ml   [2 * BATCH * H * SEQ * 2];
// fp16 transposed scaled weights (per layer)
__device__ __half g_wqkvT[LAYERS * TD * D];
__device__ __half g_woT  [LAYERS * D * D];
__device__ __half g_w1T  [LAYERS * FF * D];
__device__ __half g_w2T  [LAYERS * D * FF];

// ---------------- Embedding gather ----------------
__global__ void embed_kernel(const int* __restrict__ ids,
                             const float* __restrict__ emb,
                             float* __restrict__ x) {
    int idx = blockIdx.x * blockDim.x + threadIdx.x;
    int tok = ids[idx / D];
    x[idx] = emb[(size_t)tok * D + (idx % D)];
}

// ---------------- LayerNorm; HOUT=1 writes fp16 ----------------
template<int HOUT>
__global__ void ln_kernel(const float* __restrict__ x,
                          const float* __restrict__ g,
                          const float* __restrict__ b,
                          float* __restrict__ outf,
                          __half* __restrict__ outh) {
    __shared__ float row[D];
    __shared__ float red[256];
    const int tid = threadIdx.x;
    const float* xr = x + (size_t)blockIdx.x * D;

    float s = 0.f;
    for (int i = tid; i < D; i += 256) { float v = xr[i]; row[i] = v; s += v; }
    red[tid] = s; __syncthreads();
    for (int st = 128; st > 0; st >>= 1) {
        if (tid < st) red[tid] += red[tid + st];
        __syncthreads();
    }
    const float mean = red[0] * (1.0f / D);
    __syncthreads();

    float s2 = 0.f;
    for (int i = tid; i < D; i += 256) { float v = row[i] - mean; s2 += v * v; }
    red[tid] = s2; __syncthreads();
    for (int st = 128; st > 0; st >>= 1) {
        if (tid < st) red[tid] += red[tid + st];
        __syncthreads();
    }
    const float rstd = rsqrtf(red[0] * (1.0f / D) + 1e-5f);

    if (HOUT) {
        __half* orow = outh + (size_t)blockIdx.x * D;
        for (int i = tid; i < D; i += 256)
            orow[i] = __float2half_rn((row[i] - mean) * rstd * g[i] + b[i]);
    } else {
        float* orow = outf + (size_t)blockIdx.x * D;
        for (int i = tid; i < D; i += 256)
            orow[i] = (row[i] - mean) * rstd * g[i] + b[i];
    }
}

// ---------------- Transpose + scale weights ----------------
__global__ void transw_kernel(const float* __restrict__ W,
                              __half* __restrict__ Wt, int K, int N) {
    __shared__ float tile[64][33];
    int n0 = blockIdx.x * 32, k0 = blockIdx.y * 64;
    int tx = threadIdx.x, ty = threadIdx.y;   // (32, 8)
    #pragma unroll
    for (int i = 0; i < 64; i += 8)
        tile[ty + i][tx] = W[(size_t)(k0 + ty + i) * N + n0 + tx];
    __syncthreads();
    #pragma unroll
    for (int i = 0; i < 32; i += 8) {
        int nn = ty + i;
        int n = n0 + nn;
        __half2 w2 = __floats2half2_rn(tile[2 * tx][nn] * WS,
                                       tile[2 * tx + 1][nn] * WS);
        *(__half2*)(Wt + (size_t)n * K + k0 + 2 * tx) = w2;
    }
}

// ---------------- fp16 V transpose ----------------
__global__ void vtrans16_kernel(const __half* __restrict__ vh,
                                __half* __restrict__ vt) {
    __shared__ __half tile[32][34];
    int j0 = blockIdx.x * 32, d0 = blockIdx.y * 32;
    int bh = blockIdx.z;
    int tx = threadIdx.x, ty = threadIdx.y;
    #pragma unroll
    for (int i = 0; i < 32; i += 8)
        tile[ty + i][tx] = vh[((size_t)bh * SEQ + j0 + ty + i) * DH + d0 + tx];
    __syncthreads();
    #pragma unroll
    for (int i = 0; i < 32; i += 8)
        vt[((size_t)bh * DH + d0 + ty + i) * SEQ + j0 + tx] = tile[tx][ty + i];
}

// ---------------- Shared MMA helpers ----------------
__device__ __forceinline__ unsigned swz(unsigned o) { return o ^ ((o >> 3) & 0x70); }

__device__ __forceinline__ void ldsm4(unsigned addr, unsigned& r0, unsigned& r1,
                                      unsigned& r2, unsigned& r3) {
    asm volatile("ldmatrix.sync.aligned.m8n8.x4.shared.b16 {%0,%1,%2,%3}, [%4];\n"
                 : "=r"(r0), "=r"(r1), "=r"(r2), "=r"(r3) : "r"(addr));
}
__device__ __forceinline__ void mma16816(float* c, unsigned a0, unsigned a1,
                                         unsigned a2, unsigned a3,
                                         unsigned b0, unsigned b1) {
    asm volatile(
        "mma.sync.aligned.m16n8k16.row.col.f32.f16.f16.f32 "
        "{%0,%1,%2,%3},{%4,%5,%6,%7},{%8,%9},{%0,%1,%2,%3};\n"
        : "+f"(c[0]), "+f"(c[1]), "+f"(c[2]), "+f"(c[3])
        : "r"(a0), "r"(a1), "r"(a2), "r"(a3), "r"(b0), "r"(b1));
}
__device__ __forceinline__ void cpasync16(unsigned saddr, const void* g) {
    asm volatile("cp.async.cg.shared.global [%0], [%1], 16;\n" :: "r"(saddr), "l"(g));
}
__device__ __forceinline__ unsigned ex2h2(float lo, float hi) {
    __half2 t = __floats2half2_rn(lo, hi);
    unsigned u = *reinterpret_cast<unsigned*>(&t);
    unsigned r;
    asm("ex2.approx.f16x2 %0, %1;" : "=r"(r) : "r"(u));
    return r;
}
__device__ __forceinline__ unsigned prow(int r, int seg16) {
    return (unsigned)((r >> 1) * 128 + (r & 1) * 64 + seg16 * 16);
}

// ========= fp16 GEMM (unchanged) =========
#define BG_STAGE  16384
#define BG_SMEM   (4 * BG_STAGE)

__device__ __forceinline__ void load_tile(const __half* gbase, unsigned sbase,
                                          int ld, int k0) {
    int t = threadIdx.x;
    #pragma unroll
    for (int i = 0; i < 4; i++) {
        int c = t + i * 128;
        int row = c >> 2, seg = c & 3;
        cpasync16(sbase + swz(prow(row, seg)), gbase + (size_t)row * ld + k0 + seg * 8);
    }
}

__device__ __forceinline__ void ldsm_frags(const unsigned aA[4], const unsigned bA[4],
                                           unsigned off,
                                           unsigned fa[4][4], unsigned fb[4][4]) {
    #pragma unroll
    for (int mi = 0; mi < 4; mi++)
        ldsm4(aA[mi] ^ off, fa[mi][0], fa[mi][1], fa[mi][2], fa[mi][3]);
    #pragma unroll
    for (int np = 0; np < 4; np++)
        ldsm4(bA[np] ^ off, fb[np][0], fb[np][1], fb[np][2], fb[np][3]);
}

__device__ __forceinline__ void mma_tile(float acc[4][8][4],
                                         unsigned fa[4][4], unsigned fb[4][4]) {
    #pragma unroll
    for (int mi = 0; mi < 4; mi++)
        #pragma unroll
        for (int ni = 0; ni < 8; ni++) {
            unsigned b0 = fb[ni >> 1][ni & 1];
            unsigned b1 = fb[ni >> 1][2 + (ni & 1)];
            mma16816(acc[mi][ni], fa[mi][0], fa[mi][1], fa[mi][2], fa[mi][3], b0, b1);
        }
}

__device__ __forceinline__ float gelu_f(float xx) {
    return 0.5f * xx * (1.0f + tanhf(0.7978845608028654f *
                                     (xx + 0.044715f * xx * xx * xx)));
}

template<int EPI>
__global__ void __launch_bounds__(128, 2)
bgemm_kernel(const __half* __restrict__ A,
             const __half* __restrict__ Bt,
             float* __restrict__ C,
             __half* __restrict__ Hout,
             __half* __restrict__ Qh,
             __half* __restrict__ Kh,
             __half* __restrict__ Vh,
             int M, int N, int K) {
    extern __shared__ __align__(128) char smem[];
    unsigned sbase = (unsigned)__cvta_generic_to_shared(smem);

    const int tid = threadIdx.x, lane = tid & 31, warp = tid >> 5;
    const int warpM = warp & 1, warpN = warp >> 1;
    const int rowBase = blockIdx.x * 128;
    const int colBase = blockIdx.y * 128;
    const __half* Ab = A  + (size_t)rowBase * K;
    const __half* Bb = Bt + (size_t)colBase * K;

    float acc[4][8][4];
    #pragma unroll
    for (int i = 0; i < 4; i++)
        #pragma unroll
        for (int j = 0; j < 8; j++)
            #pragma unroll
            for (int r = 0; r < 4; r++) acc[i][j][r] = 0.f;

    const int KT = K >> 5;
    #pragma unroll
    for (int s = 0; s < 3; s++) {
        unsigned st = sbase + s * BG_STAGE;
        load_tile(Ab, st, K, s << 5);
        load_tile(Bb, st + 8192, K, s << 5);
        asm volatile("cp.async.commit_group;\n");
    }

    unsigned aAB[4], bAB[4];
    #pragma unroll
    for (int mi = 0; mi < 4; mi++) {
        int row = warpM * 64 + mi * 16 + (lane & 15);
        aAB[mi] = swz(prow(row, lane >> 4));
    }
    #pragma unroll
    for (int np = 0; np < 4; np++) {
        int rown = warpN * 64 + np * 16 + (lane & 15);
        bAB[np] = 8192u + swz(prow(rown, lane >> 4));
    }

    unsigned fa[4][4], fb[4][4];

    for (int kt = 0; kt < KT; kt++) {
        asm volatile("cp.async.wait_group 2;\n");
        __syncthreads();

        unsigned stg = sbase + (unsigned)(kt & 3) * BG_STAGE;
        unsigned aA[4] = { stg + aAB[0], stg + aAB[1], stg + aAB[2], stg + aAB[3] };
        unsigned bA[4] = { stg + bAB[0], stg + bAB[1], stg + bAB[2], stg + bAB[3] };

        ldsm_frags(aA, bA, 0, fa, fb);

        const int next = kt + 3;
        if (next < KT) {
            unsigned ns = sbase + (unsigned)(next & 3) * BG_STAGE;
            load_tile(Ab, ns, K, next << 5);
            load_tile(Bb, ns + 8192, K, next << 5);
        }
        asm volatile("cp.async.commit_group;\n");

        mma_tile(acc, fa, fb);
        ldsm_frags(aA, bA, 32, fa, fb);
        mma_tile(acc, fa, fb);
    }

    #pragma unroll
    for (int mi = 0; mi < 4; mi++)
        #pragma unroll
        for (int ni = 0; ni < 8; ni++) {
            int row = rowBase + warpM * 64 + mi * 16 + (lane >> 2);
            int col = colBase + warpN * 64 + ni * 8 + 2 * (lane & 3);
            float v0 = acc[mi][ni][0] * WS_INV, v1 = acc[mi][ni][1] * WS_INV;
            float v2 = acc[mi][ni][2] * WS_INV, v3 = acc[mi][ni][3] * WS_INV;
            if (EPI == 2) {
                __half2* hp = (__half2*)(Hout + (size_t)row * N + col);
                __half2* hq = (__half2*)(Hout + (size_t)(row + 8) * N + col);
                *hp = __floats2half2_rn(gelu_f(v0), gelu_f(v1));
                *hq = __floats2half2_rn(gelu_f(v2), gelu_f(v3));
            } else if (EPI == 3) {
                int part = col >> 11;
                int hh = (col >> 7) & 15;
                int d  = col & 127;
                __half* dst = (part == 0) ? Qh : (part == 1) ? Kh : Vh;
                int bA0 = row >> 10, sA0 = row & 1023;
                int rB = row + 8;
                int bB0 = rB >> 10, sB0 = rB & 1023;
                *(__half2*)(dst + (((size_t)(bA0 * H + hh) * SEQ) + sA0) * DH + d) =
                    __floats2half2_rn(v0, v1);
                *(__half2*)(dst + (((size_t)(bB0 * H + hh) * SEQ) + sB0) * DH + d) =
                    __floats2half2_rn(v2, v3);
            } else {
                float* p = C + (size_t)row * N + col;
                float* q = C + (size_t)(row + 8) * N + col;
                if (EPI == 1) { v0 += p[0]; v1 += p[1]; v2 += q[0]; v3 += q[1]; }
                *(float2*)p = make_float2(v0, v1);
                *(float2*)q = make_float2(v2, v3);
            }
        }
}

// ========= Split-KV tensor-core flash attention =========
// grid (SEQ/64, H*2, BATCH); split = blockIdx.y & 1.
// Block (q-block i, split s) handles chunks [s*(i+1), (s+1)*(i+1)).
// Writes unnormalized fp32 partials + (m,l).
#define AT_SMEM (4096 + 16384 + 2 * 16384)

__global__ void __launch_bounds__(128)
attn_kernel(const __half* __restrict__ qh,
            const __half* __restrict__ kh,
            const __half* __restrict__ vt,
            const int* __restrict__ mask,
            float* __restrict__ opart,
            float* __restrict__ ml) {
    extern __shared__ __align__(128) char asmem[];
    float* bias = (float*)asmem;
    unsigned sb = (unsigned)__cvta_generic_to_shared(asmem);
    const unsigned Qs  = sb + 4096;
    const unsigned KV0 = sb + 20480;

    const int tid = threadIdx.x, lane = tid & 31, warp = tid >> 5;
    const int qb_i = blockIdx.x;
    const int q0 = qb_i * 64;
    const int split = blockIdx.y & 1;
    const int h = blockIdx.y >> 1, b = blockIdx.z;
    const int bh = b * H + h;
    const int cbeg = split * (qb_i + 1);
    const int cend = (split + 1) * (qb_i + 1);

    for (int i = tid; i < SEQ; i += 128)
        bias[i] = (mask[b * SEQ + i] == 0) ? NEGB : 0.f;

    {
        const __half* qb = qh + ((size_t)bh * SEQ + q0) * DH;
        #pragma unroll
        for (int i = 0; i < 8; i++) {
            int g = tid + i * 128;
            int seg = g & 3, r = (g >> 2) & 15, s = (g >> 6) & 3, w = g >> 8;
            cpasync16(Qs + w * 4096 + s * 1024 + swz(prow(r, seg)),
                      qb + (size_t)(w * 16 + r) * DH + s * 32 + seg * 8);
        }
    }
    auto load_kv = [&](int c, int buf) {
        int j0 = c * 32;
        unsigned Kb = KV0 + buf * 16384;
        const __half* kb = kh + ((size_t)bh * SEQ + j0) * DH;
        const __half* vb = vt + (size_t)bh * DH * SEQ + j0;
        #pragma unroll
        for (int i = 0; i < 4; i++) {
            int g = tid + i * 128;
            int seg = g & 3, r = (g >> 2) & 31, s = g >> 7;
            cpasync16(Kb + s * 2048 + swz(prow(r, seg)),
                      kb + (size_t)r * DH + s * 32 + seg * 8);
        }
        #pragma unroll
        for (int i = 0; i < 4; i++) {
            int g = tid + i * 128;
            int seg = g & 3, d = g >> 2;
            cpasync16(Kb + 8192 + swz(prow(d, seg)),
                      vb + (size_t)d * SEQ + seg * 8);
        }
    };

    // prefetch first two chunks (cbeg+1 <= 17 < 32, always in-bounds memory)
    load_kv(cbeg, 0);
    asm volatile("cp.async.commit_group;\n");
    load_kv(cbeg + 1, 1);
    asm volatile("cp.async.commit_group;\n");

    const unsigned qA = Qs + warp * 4096 + swz(prow(lane & 15, lane >> 4));
    unsigned kB[2], vB[8];
    #pragma unroll
    for (int np = 0; np < 2; np++)
        kB[np] = swz(prow(np * 16 + (lane & 15), lane >> 4));
    #pragma unroll
    for (int np = 0; np < 8; np++)
        vB[np] = swz(prow(np * 16 + (lane & 15), lane >> 4));

    const int rowA = q0 + warp * 16 + (lane >> 2);
    const int rowB = rowA + 8;

    float o[16][4];
    #pragma unroll
    for (int i = 0; i < 16; i++)
        #pragma unroll
        for (int r = 0; r < 4; r++) o[i][r] = 0.f;
    float mA = -1e30f, mB = -1e30f, lA = 0.f, lB = 0.f;

    for (int c = cbeg; c < cend; c++) {
        asm volatile("cp.async.wait_group 1;\n");
        __syncthreads();
        unsigned Kb = KV0 + (unsigned)((c - cbeg) & 1) * 16384;
        unsigned Vb = Kb + 8192;

        float sc[4][4];
        #pragma unroll
        for (int i = 0; i < 4; i++)
            #pragma unroll
            for (int r = 0; r < 4; r++) sc[i][r] = 0.f;
        #pragma unroll
        for (int s = 0; s < 4; s++) {
            #pragma unroll
            for (int t = 0; t < 2; t++) {
                unsigned fa0, fa1, fa2, fa3;
                ldsm4((qA + s * 1024) ^ (t * 32), fa0, fa1, fa2, fa3);
                #pragma unroll
                for (int np = 0; np < 2; np++) {
                    unsigned b0, b1, b2, b3;
                    ldsm4((Kb + s * 2048 + kB[np]) ^ (t * 32), b0, b1, b2, b3);
                    mma16816(sc[2 * np],     fa0, fa1, fa2, fa3, b0, b2);
                    mma16816(sc[2 * np + 1], fa0, fa1, fa2, fa3, b1, b3);
                }
            }
        }

        const int j0 = c * 32;
        #pragma unroll
        for (int ni = 0; ni < 4; ni++) {
            int jb = j0 + ni * 8 + 2 * (lane & 3);
            float b0 = bias[jb], b1 = bias[jb + 1];
            sc[ni][0] = (jb     <= rowA) ? sc[ni][0] * SCALE2 + b0 : -1e30f;
            sc[ni][1] = (jb + 1 <= rowA) ? sc[ni][1] * SCALE2 + b1 : -1e30f;
            sc[ni][2] = (jb     <= rowB) ? sc[ni][2] * SCALE2 + b0 : -1e30f;
            sc[ni][3] = (jb + 1 <= rowB) ? sc[ni][3] * SCALE2 + b1 : -1e30f;
        }

        float cmA = -1e30f, cmB = -1e30f;
        #pragma unroll
        for (int ni = 0; ni < 4; ni++) {
            cmA = fmaxf(cmA, fmaxf(sc[ni][0], sc[ni][1]));
            cmB = fmaxf(cmB, fmaxf(sc[ni][2], sc[ni][3]));
        }
        #pragma unroll
        for (int off = 1; off <= 2; off <<= 1) {
            cmA = fmaxf(cmA, __shfl_xor_sync(0xffffffffu, cmA, off));
            cmB = fmaxf(cmB, __shfl_xor_sync(0xffffffffu, cmB, off));
        }
        float newA = fmaxf(mA, cmA), newB = fmaxf(mB, cmB);
        float corrA = exp2f(mA - newA), corrB = exp2f(mB - newB);
        mA = newA; mB = newB;

        unsigned hA[4], hB[4];
        float sA = 0.f, sB = 0.f;
        #pragma unroll
        for (int ni = 0; ni < 4; ni++) {
            hA[ni] = ex2h2(sc[ni][0] - newA, sc[ni][1] - newA);
            hB[ni] = ex2h2(sc[ni][2] - newB, sc[ni][3] - newB);
            float2 fa2 = __half22float2(*(__half2*)&hA[ni]);
            float2 fb2 = __half22float2(*(__half2*)&hB[ni]);
            sA += fa2.x + fa2.y;
            sB += fb2.x + fb2.y;
        }
        #pragma unroll
        for (int off = 1; off <= 2; off <<= 1) {
            sA += __shfl_xor_sync(0xffffffffu, sA, off);
            sB += __shfl_xor_sync(0xffffffffu, sB, off);
        }
        lA = lA * corrA + sA;
        lB = lB * corrB + sB;
        #pragma unroll
        for (int ni = 0; ni < 16; ni++) {
            o[ni][0] *= corrA; o[ni][1] *= corrA;
            o[ni][2] *= corrB; o[ni][3] *= corrB;
        }

        #pragma unroll
        for (int t = 0; t < 2; t++) {
            unsigned a0 = hA[2 * t], a1 = hB[2 * t];
            unsigned a2 = hA[2 * t + 1], a3 = hB[2 * t + 1];
            #pragma unroll
            for (int np = 0; np < 8; np++) {
                unsigned b0, b1, b2, b3;
                ldsm4((Vb + vB[np]) ^ (t * 32), b0, b1, b2, b3);
                mma16816(o[2 * np],     a0, a1, a2, a3, b0, b2);
                mma16816(o[2 * np + 1], a0, a1, a2, a3, b1, b3);
            }
        }

        __syncthreads();
        if (c + 2 < cend) load_kv(c + 2, (c - cbeg) & 1);
        asm volatile("cp.async.commit_group;\n");
    }

    // store unnormalized partials: opart[split][b][h][row][d], ml[split][b][h][row]
    const size_t sbh = (size_t)(split * BATCH + b) * H + h;
    const size_t pA = (sbh * SEQ + rowA) * DH;
    const size_t pB = (sbh * SEQ + rowB) * DH;
    #pragma unroll
    for (int ni = 0; ni < 16; ni++) {
        int col = ni * 8 + 2 * (lane & 3);
        *(float2*)(opart + pA + col) = make_float2(o[ni][0], o[ni][1]);
        *(float2*)(opart + pB + col) = make_float2(o[ni][2], o[ni][3]);
    }
    if ((lane & 3) == 0) {
        *(float2*)(ml + (sbh * SEQ + rowA) * 2) = make_float2(mA, lA);
        *(float2*)(ml + (sbh * SEQ + rowB) * 2) = make_float2(mB, lB);
    }
}

// ---------------- Merge split-KV partials -> fp16 token-major ----------------
__global__ void attmerge_kernel(const float* __restrict__ opart,
                                const float* __restrict__ ml,
                                __half* __restrict__ ao) {
    const int t = blockIdx.x;                 // token
    const int b = t / SEQ, q = t % SEQ;
    const int tid = threadIdx.x;
    #pragma unroll
    for (int i = 0; i < 8; i++) {
        int idx = tid + i * 256;              // over D
        int h = idx >> 7, d = idx & 127;
        size_t r0 = ((size_t)(0 * BATCH + b) * H + h) * SEQ + q;
        size_t r1 = ((size_t)(1 * BATCH + b) * H + h) * SEQ + q;
        float2 ml0 = *(const float2*)(ml + r0 * 2);
        float2 ml1 = *(const float2*)(ml + r1 * 2);
        float mm = fmaxf(ml0.x, ml1.x);
        float w0 = exp2f(ml0.x - mm), w1 = exp2f(ml1.x - mm);
        float l = ml0.y * w0 + ml1.y * w1;
        float o0 = opart[r0 * DH + d], o1 = opart[r1 * DH + d];
        ao[(size_t)t * D + idx] = __float2half_rn((o0 * w0 + o1 * w1) / l);
    }
}

// ---------------- Pool + head ----------------
__global__ void meanpool_kernel(const float* __restrict__ hs,
                                const int* __restrict__ mask,
                                float* __restrict__ mean) {
    int idx = blockIdx.x * blockDim.x + threadIdx.x;
    int b = idx / D;
    int d = idx % D;
    float acc = 0.f, msum = 0.f;
    const float* hb = hs + (size_t)b * SEQ * D + d;
    const int* mb = mask + b * SEQ;
    for (int s = 0; s < SEQ; s++) {
        float mf = (float)mb[s];
        acc = fmaf(mf, hb[(size_t)s * D], acc);
        msum += mf;
    }
    mean[idx] = acc / fmaxf(msum, 1e-9f);
}

__global__ void head1_kernel(const float* __restrict__ mean,
                             const float* __restrict__ Wc1,
                             const float* __restrict__ bc1,
                             float* __restrict__ t) {
    int idx = blockIdx.x * blockDim.x + threadIdx.x;
    int b = idx / D;
    int j = idx % D;
    float acc = bc1[j];
    const float* mb = mean + (size_t)b * D;
    for (int k = 0; k < D; k++)
        acc = fmaf(mb[k], Wc1[(size_t)k * D + j], acc);
    t[idx] = tanhf(acc);
}

__global__ void head2_kernel(const float* __restrict__ t,
                             const float* __restrict__ Wc2,
                             const float* __restrict__ bc2,
                             float* __restrict__ out) {
    __shared__ float red[256];
    __shared__ float logits[4];
    const int tid = threadIdx.x;
    float part[4] = {0.f, 0.f, 0.f, 0.f};
    for (int j = tid; j < D; j += 256) {
        float t0 = t[j], t1 = t[D + j];
        float w0 = Wc2[2 * j], w1 = Wc2[2 * j + 1];
        part[0] = fmaf(t0, w0, part[0]);
        part[1] = fmaf(t0, w1, part[1]);
        part[2] = fmaf(t1, w0, part[2]);
        part[3] = fmaf(t1, w1, part[3]);
    }
    for (int c = 0; c < 4; c++) {
        __syncthreads();
        red[tid] = part[c]; __syncthreads();
        for (int st = 128; st > 0; st >>= 1) {
            if (tid < st) red[tid] += red[tid + st];
            __syncthreads();
        }
        if (tid == 0) logits[c] = red[0] + bc2[c & 1];
    }
    __syncthreads();
    if (tid == 0) {
        for (int b = 0; b < BATCH; b++) {
            float l0 = logits[2 * b], l1 = logits[2 * b + 1];
            float m = fmaxf(l0, l1);
            float e0 = expf(l0 - m), e1 = expf(l1 - m);
            out[b] = e1 / (e0 + e1);
        }
    }
}

// ---------------- Launch ----------------
extern "C" void kernel_launch(void* const* d_in, const int* in_sizes, int n_in,
                              void* d_out, int out_size) {
    const int*   ids   = (const int*)d_in[0];
    const int*   amask = (const int*)d_in[1];
    const float* emb   = (const float*)d_in[2];
    const float* ln1_g = (const float*)d_in[3];
    const float* ln1_b = (const float*)d_in[4];
    const float* Wqkv  = (const float*)d_in[5];
    const float* Wo    = (const float*)d_in[6];
    const float* ln2_g = (const float*)d_in[7];
    const float* ln2_b = (const float*)d_in[8];
    const float* W1    = (const float*)d_in[9];
    const float* W2    = (const float*)d_in[10];
    const float* lnf_g = (const float*)d_in[11];
    const float* lnf_b = (const float*)d_in[12];
    const float* Wc1   = (const float*)d_in[13];
    const float* bc1   = (const float*)d_in[14];
    const float* Wc2   = (const float*)d_in[15];
    const float* bc2   = (const float*)d_in[16];
    float* out = (float*)d_out;

    float *x, *h, *mean, *t, *opart, *ml;
    __half *ha_d, *ha_f, *qh, *kh, *vh, *vt, *wqkvT, *woT, *w1T, *w2T;
    cudaGetSymbolAddress((void**)&x,    g_x);
    cudaGetSymbolAddress((void**)&h,    g_h);
    cudaGetSymbolAddress((void**)&mean, g_mean);
    cudaGetSymbolAddress((void**)&t,    g_t);
    cudaGetSymbolAddress((void**)&ha_d, g_ha_d);
    cudaGetSymbolAddress((void**)&ha_f, g_ha_f);
    cudaGetSymbolAddress((void**)&qh,   g_qh);
    cudaGetSymbolAddress((void**)&kh,   g_kh);
    cudaGetSymbolAddress((void**)&vh,   g_vh);
    cudaGetSymbolAddress((void**)&vt,   g_vt);
    cudaGetSymbolAddress((void**)&opart, g_opart);
    cudaGetSymbolAddress((void**)&ml,    g_ml);
    cudaGetSymbolAddress((void**)&wqkvT, g_wqkvT);
    cudaGetSymbolAddress((void**)&woT,   g_woT);
    cudaGetSymbolAddress((void**)&w1T,   g_w1T);
    cudaGetSymbolAddress((void**)&w2T,   g_w2T);

    cudaFuncSetAttribute(bgemm_kernel<1>,
                         cudaFuncAttributeMaxDynamicSharedMemorySize, BG_SMEM);
    cudaFuncSetAttribute(bgemm_kernel<2>,
                         cudaFuncAttributeMaxDynamicSharedMemorySize, BG_SMEM);
    cudaFuncSetAttribute(bgemm_kernel<3>,
                         cudaFuncAttributeMaxDynamicSharedMemorySize, BG_SMEM);
    cudaFuncSetAttribute(attn_kernel,
                         cudaFuncAttributeMaxDynamicSharedMemorySize, AT_SMEM);

    // Side stream: weight transposes, fine-grained join events.
    cudaStream_t s2;
    cudaStreamCreateWithFlags(&s2, cudaStreamNonBlocking);
    cudaEvent_t evFork, evW[8];
    cudaEventCreateWithFlags(&evFork, cudaEventDisableTiming);
    for (int i = 0; i < 8; i++)
        cudaEventCreateWithFlags(&evW[i], cudaEventDisableTiming);

    cudaEventRecord(evFork, 0);
    cudaStreamWaitEvent(s2, evFork, 0);
    for (int l = 0; l < LAYERS; l++) {
        transw_kernel<<<dim3(TD / 32, D / 64), dim3(32, 8), 0, s2>>>(
            Wqkv + (size_t)l * D * TD, wqkvT + (size_t)l * TD * D, D, TD);
        cudaEventRecord(evW[l * 4 + 0], s2);
        transw_kernel<<<dim3(D / 32, D / 64), dim3(32, 8), 0, s2>>>(
            Wo + (size_t)l * D * D, woT + (size_t)l * D * D, D, D);
        cudaEventRecord(evW[l * 4 + 1], s2);
        transw_kernel<<<dim3(FF / 32, D / 64), dim3(32, 8), 0, s2>>>(
            W1 + (size_t)l * D * FF, w1T + (size_t)l * FF * D, D, FF);
        cudaEventRecord(evW[l * 4 + 2], s2);
        transw_kernel<<<dim3(D / 32, FF / 64), dim3(32, 8), 0, s2>>>(
            W2 + (size_t)l * FF * D, w2T + (size_t)l * D * FF, FF, D);
        cudaEventRecord(evW[l * 4 + 3], s2);
    }

    embed_kernel<<<(BS * D) / 256, 256>>>(ids, emb, x);

    for (int l = 0; l < LAYERS; l++) {
        // attention block
        ln_kernel<1><<<BS, 256>>>(x, ln1_g + (size_t)l * D, ln1_b + (size_t)l * D,
                                  nullptr, ha_d);
        cudaStreamWaitEvent(0, evW[l * 4 + 0], 0);
        bgemm_kernel<3><<<dim3(BS / 128, TD / 128), 128, BG_SMEM>>>(
            ha_d, wqkvT + (size_t)l * TD * D, nullptr, nullptr,
            qh, kh, vh, BS, TD, D);
        vtrans16_kernel<<<dim3(SEQ / 32, DH / 32, BATCH * H), dim3(32, 8)>>>(vh, vt);
        attn_kernel<<<dim3(SEQ / 64, H * 2, BATCH), 128, AT_SMEM>>>(
            qh, kh, vt, amask, opart, ml);
        attmerge_kernel<<<BS, 256>>>(opart, ml, ha_d);
        cudaStreamWaitEvent(0, evW[l * 4 + 1], 0);
        bgemm_kernel<1><<<dim3(BS / 128, D / 128), 128, BG_SMEM>>>(
            ha_d, woT + (size_t)l * D * D, x, nullptr,
            nullptr, nullptr, nullptr, BS, D, D);
        // mlp block
        ln_kernel<1><<<BS, 256>>>(x, ln2_g + (size_t)l * D, ln2_b + (size_t)l * D,
                                  nullptr, ha_d);
        cudaStreamWaitEvent(0, evW[l * 4 + 2], 0);
        bgemm_kernel<2><<<dim3(BS / 128, FF / 128), 128, BG_SMEM>>>(
            ha_d, w1T + (size_t)l * FF * D, nullptr, ha_f,
            nullptr, nullptr, nullptr, BS, FF, D);
        cudaStreamWaitEvent(0, evW[l * 4 + 3], 0);
        bgemm_kernel<1><<<dim3(BS / 128, D / 128), 128, BG_SMEM>>>(
            ha_f, w2T + (size_t)l * D * FF, x, nullptr,
            nullptr, nullptr, nullptr, BS, D, FF);
    }

    ln_kernel<0><<<BS, 256>>>(x, lnf_g, lnf_b, h, nullptr);
    meanpool_kernel<<<(BATCH * D) / 256, 256>>>(h, amask, mean);
    head1_kernel<<<(BATCH * D) / 256, 256>>>(mean, Wc1, bc1, t);
    head2_kernel<<<1, 256>>>(t, Wc2, bc2, out);
}

// round 17
// speedup vs baseline: 5.5114x; 1.0365x over previous
#include <cuda_runtime.h>
#include <cuda_fp16.h>
#include <math.h>
#include <stdint.h>

// ---------------- Problem constants ----------------
#define LAYERS 2
#define D      2048
#define H      16
#define FF     8192
#define BATCH  2
#define SEQ    1024
#define DH     128
#define TD     (3 * D)
#define BS     (BATCH * SEQ)
#define NEGB   (-1e9f)
#define SCALE  0.08838834764831845f
#define SCALE2 (0.08838834764831845f * 1.4426950408889634f)
#define WS     512.0f
#define WS_INV (1.0f / 512.0f)
#define NPERS  296                     // persistent CTAs (148 SM x 2)

// ---------------- Scratch (static device globals) ----------------
__device__ float g_x   [BS * D];
__device__ float g_h   [BS * D];
__device__ float g_mean[BATCH * D];
__device__ float g_t   [BATCH * D];
// fp16 activation buffers
__device__ __half g_ha_d[BS * D];
__device__ __half g_ha_f[BS * FF];
// fp16 attention operands (head-major)
__device__ __half g_qh[BS * D];
__device__ __half g_kh[BS * D];
__device__ __half g_vt[BS * D];      // [b][h][d][j] (written transposed by EPI=3)
// split-KV partials
__device__ float g_opart[2 * BS * D];
__device__ float g_ml   [2 * BATCH * H * SEQ * 2];
// fp16 transposed scaled weights (per layer)
__device__ __half g_wqkvT[LAYERS * TD * D];
__device__ __half g_woT  [LAYERS * D * D];
__device__ __half g_w1T  [LAYERS * FF * D];
__device__ __half g_w2T  [LAYERS * D * FF];

// ---------------- Embedding gather ----------------
__global__ void embed_kernel(const int* __restrict__ ids,
                             const float* __restrict__ emb,
                             float* __restrict__ x) {
    int idx = blockIdx.x * blockDim.x + threadIdx.x;
    int tok = ids[idx / D];
    x[idx] = emb[(size_t)tok * D + (idx % D)];
}

// ---------------- LayerNorm; HOUT=1 writes fp16 ----------------
template<int HOUT>
__global__ void ln_kernel(const float* __restrict__ x,
                          const float* __restrict__ g,
                          const float* __restrict__ b,
                          float* __restrict__ outf,
                          __half* __restrict__ outh) {
    __shared__ float row[D];
    __shared__ float red[256];
    const int tid = threadIdx.x;
    const float* xr = x + (size_t)blockIdx.x * D;

    float s = 0.f;
    for (int i = tid; i < D; i += 256) { float v = xr[i]; row[i] = v; s += v; }
    red[tid] = s; __syncthreads();
    for (int st = 128; st > 0; st >>= 1) {
        if (tid < st) red[tid] += red[tid + st];
        __syncthreads();
    }
    const float mean = red[0] * (1.0f / D);
    __syncthreads();

    float s2 = 0.f;
    for (int i = tid; i < D; i += 256) { float v = row[i] - mean; s2 += v * v; }
    red[tid] = s2; __syncthreads();
    for (int st = 128; st > 0; st >>= 1) {
        if (tid < st) red[tid] += red[tid + st];
        __syncthreads();
    }
    const float rstd = rsqrtf(red[0] * (1.0f / D) + 1e-5f);

    if (HOUT) {
        __half* orow = outh + (size_t)blockIdx.x * D;
        for (int i = tid; i < D; i += 256)
            orow[i] = __float2half_rn((row[i] - mean) * rstd * g[i] + b[i]);
    } else {
        float* orow = outf + (size_t)blockIdx.x * D;
        for (int i = tid; i < D; i += 256)
            orow[i] = (row[i] - mean) * rstd * g[i] + b[i];
    }
}

// ---------------- Transpose + scale weights ----------------
__global__ void transw_kernel(const float* __restrict__ W,
                              __half* __restrict__ Wt, int K, int N) {
    __shared__ float tile[64][33];
    int n0 = blockIdx.x * 32, k0 = blockIdx.y * 64;
    int tx = threadIdx.x, ty = threadIdx.y;   // (32, 8)
    #pragma unroll
    for (int i = 0; i < 64; i += 8)
        tile[ty + i][tx] = W[(size_t)(k0 + ty + i) * N + n0 + tx];
    __syncthreads();
    #pragma unroll
    for (int i = 0; i < 32; i += 8) {
        int nn = ty + i;
        int n = n0 + nn;
        __half2 w2 = __floats2half2_rn(tile[2 * tx][nn] * WS,
                                       tile[2 * tx + 1][nn] * WS);
        *(__half2*)(Wt + (size_t)n * K + k0 + 2 * tx) = w2;
    }
}

// ---------------- Shared MMA helpers ----------------
__device__ __forceinline__ unsigned swz(unsigned o) { return o ^ ((o >> 3) & 0x70); }

__device__ __forceinline__ void ldsm4(unsigned addr, unsigned& r0, unsigned& r1,
                                      unsigned& r2, unsigned& r3) {
    asm volatile("ldmatrix.sync.aligned.m8n8.x4.shared.b16 {%0,%1,%2,%3}, [%4];\n"
                 : "=r"(r0), "=r"(r1), "=r"(r2), "=r"(r3) : "r"(addr));
}
__device__ __forceinline__ void mma16816(float* c, unsigned a0, unsigned a1,
                                         unsigned a2, unsigned a3,
                                         unsigned b0, unsigned b1) {
    asm volatile(
        "mma.sync.aligned.m16n8k16.row.col.f32.f16.f16.f32 "
        "{%0,%1,%2,%3},{%4,%5,%6,%7},{%8,%9},{%0,%1,%2,%3};\n"
        : "+f"(c[0]), "+f"(c[1]), "+f"(c[2]), "+f"(c[3])
        : "r"(a0), "r"(a1), "r"(a2), "r"(a3), "r"(b0), "r"(b1));
}
__device__ __forceinline__ void cpasync16(unsigned saddr, const void* g) {
    asm volatile("cp.async.cg.shared.global [%0], [%1], 16;\n" :: "r"(saddr), "l"(g));
}
__device__ __forceinline__ unsigned ex2h2(float lo, float hi) {
    __half2 t = __floats2half2_rn(lo, hi);
    unsigned u = *reinterpret_cast<unsigned*>(&t);
    unsigned r;
    asm("ex2.approx.f16x2 %0, %1;" : "=r"(r) : "r"(u));
    return r;
}
__device__ __forceinline__ unsigned prow(int r, int seg16) {
    return (unsigned)((r >> 1) * 128 + (r & 1) * 64 + seg16 * 16);
}

// ========= persistent fp16 GEMM =========
// EPI: 0 = store fp32, 1 = residual add fp32, 2 = gelu->fp16,
//      3 = qkv split fp16 head-major (V written transposed)
#define BG_STAGE  16384
#define BG_SMEM   (4 * BG_STAGE)

__device__ __forceinline__ void load_tile(const __half* gbase, unsigned sbase,
                                          int ld, int k0) {
    int t = threadIdx.x;
    #pragma unroll
    for (int i = 0; i < 4; i++) {
        int c = t + i * 128;
        int row = c >> 2, seg = c & 3;
        cpasync16(sbase + swz(prow(row, seg)), gbase + (size_t)row * ld + k0 + seg * 8);
    }
}

__device__ __forceinline__ void ldsm_frags(const unsigned aA[4], const unsigned bA[4],
                                           unsigned off,
                                           unsigned fa[4][4], unsigned fb[4][4]) {
    #pragma unroll
    for (int mi = 0; mi < 4; mi++)
        ldsm4(aA[mi] ^ off, fa[mi][0], fa[mi][1], fa[mi][2], fa[mi][3]);
    #pragma unroll
    for (int np = 0; np < 4; np++)
        ldsm4(bA[np] ^ off, fb[np][0], fb[np][1], fb[np][2], fb[np][3]);
}

__device__ __forceinline__ void mma_tile(float acc[4][8][4],
                                         unsigned fa[4][4], unsigned fb[4][4]) {
    #pragma unroll
    for (int mi = 0; mi < 4; mi++)
        #pragma unroll
        for (int ni = 0; ni < 8; ni++) {
            unsigned b0 = fb[ni >> 1][ni & 1];
            unsigned b1 = fb[ni >> 1][2 + (ni & 1)];
            mma16816(acc[mi][ni], fa[mi][0], fa[mi][1], fa[mi][2], fa[mi][3], b0, b1);
        }
}

__device__ __forceinline__ float gelu_f(float xx) {
    return 0.5f * xx * (1.0f + tanhf(0.7978845608028654f *
                                     (xx + 0.044715f * xx * xx * xx)));
}

template<int EPI>
__global__ void __launch_bounds__(128, 2)
bgemm_kernel(const __half* __restrict__ A,
             const __half* __restrict__ Bt,
             float* __restrict__ C,
             __half* __restrict__ Hout,
             __half* __restrict__ Qh,
             __half* __restrict__ Kh,
             __half* __restrict__ Vt,
             int M, int N, int K) {
    extern __shared__ __align__(128) char smem[];
    unsigned sbase = (unsigned)__cvta_generic_to_shared(smem);

    const int tid = threadIdx.x, lane = tid & 31, warp = tid >> 5;
    const int warpM = warp & 1, warpN = warp >> 1;
    const int mt = M >> 7;
    const int nT = mt * (N >> 7);

    // per-thread ldsm base offsets (tile-invariant)
    unsigned aAB[4], bAB[4];
    #pragma unroll
    for (int mi = 0; mi < 4; mi++) {
        int row = warpM * 64 + mi * 16 + (lane & 15);
        aAB[mi] = swz(prow(row, lane >> 4));
    }
    #pragma unroll
    for (int np = 0; np < 4; np++) {
        int rown = warpN * 64 + np * 16 + (lane & 15);
        bAB[np] = 8192u + swz(prow(rown, lane >> 4));
    }

    const int KT = K >> 5;

    for (int tile = blockIdx.x; tile < nT; tile += gridDim.x) {
        const int rowBase = (tile % mt) * 128;
        const int colBase = (tile / mt) * 128;
        const __half* Ab = A  + (size_t)rowBase * K;
        const __half* Bb = Bt + (size_t)colBase * K;

        __syncthreads();    // all warps done reading smem from previous tile

        float acc[4][8][4];
        #pragma unroll
        for (int i = 0; i < 4; i++)
            #pragma unroll
            for (int j = 0; j < 8; j++)
                #pragma unroll
                for (int r = 0; r < 4; r++) acc[i][j][r] = 0.f;

        #pragma unroll
        for (int s = 0; s < 3; s++) {
            unsigned st = sbase + s * BG_STAGE;
            load_tile(Ab, st, K, s << 5);
            load_tile(Bb, st + 8192, K, s << 5);
            asm volatile("cp.async.commit_group;\n");
        }

        unsigned fa[4][4], fb[4][4];

        for (int kt = 0; kt < KT; kt++) {
            asm volatile("cp.async.wait_group 2;\n");
            __syncthreads();

            unsigned stg = sbase + (unsigned)(kt & 3) * BG_STAGE;
            unsigned aA[4] = { stg + aAB[0], stg + aAB[1], stg + aAB[2], stg + aAB[3] };
            unsigned bA[4] = { stg + bAB[0], stg + bAB[1], stg + bAB[2], stg + bAB[3] };

            ldsm_frags(aA, bA, 0, fa, fb);

            const int next = kt + 3;
            if (next < KT) {
                unsigned ns = sbase + (unsigned)(next & 3) * BG_STAGE;
                load_tile(Ab, ns, K, next << 5);
                load_tile(Bb, ns + 8192, K, next << 5);
            }
            asm volatile("cp.async.commit_group;\n");

            mma_tile(acc, fa, fb);
            ldsm_frags(aA, bA, 32, fa, fb);
            mma_tile(acc, fa, fb);
        }
        asm volatile("cp.async.wait_group 0;\n");   // drain tail empties

        #pragma unroll
        for (int mi = 0; mi < 4; mi++)
            #pragma unroll
            for (int ni = 0; ni < 8; ni++) {
                int row = rowBase + warpM * 64 + mi * 16 + (lane >> 2);
                int col = colBase + warpN * 64 + ni * 8 + 2 * (lane & 3);
                float v0 = acc[mi][ni][0] * WS_INV, v1 = acc[mi][ni][1] * WS_INV;
                float v2 = acc[mi][ni][2] * WS_INV, v3 = acc[mi][ni][3] * WS_INV;
                if (EPI == 2) {
                    __half2* hp = (__half2*)(Hout + (size_t)row * N + col);
                    __half2* hq = (__half2*)(Hout + (size_t)(row + 8) * N + col);
                    *hp = __floats2half2_rn(gelu_f(v0), gelu_f(v1));
                    *hq = __floats2half2_rn(gelu_f(v2), gelu_f(v3));
                } else if (EPI == 3) {
                    int part = col >> 11;           // 0=q 1=k 2=v
                    int hh = (col >> 7) & 15;
                    int d  = col & 127;
                    int bA0 = row >> 10, sA0 = row & 1023;
                    int rB = row + 8;
                    int bB0 = rB >> 10, sB0 = rB & 1023;
                    if (part < 2) {
                        __half* dst = (part == 0) ? Qh : Kh;
                        *(__half2*)(dst + (((size_t)(bA0 * H + hh) * SEQ) + sA0) * DH + d) =
                            __floats2half2_rn(v0, v1);
                        *(__half2*)(dst + (((size_t)(bB0 * H + hh) * SEQ) + sB0) * DH + d) =
                            __floats2half2_rn(v2, v3);
                    } else {
                        // V written transposed: vt[bh][d][j]
                        size_t baseA = ((size_t)(bA0 * H + hh) * DH);
                        size_t baseB = ((size_t)(bB0 * H + hh) * DH);
                        Vt[(baseA + d)     * SEQ + sA0] = __float2half_rn(v0);
                        Vt[(baseA + d + 1) * SEQ + sA0] = __float2half_rn(v1);
                        Vt[(baseB + d)     * SEQ + sB0] = __float2half_rn(v2);
                        Vt[(baseB + d + 1) * SEQ + sB0] = __float2half_rn(v3);
                    }
                } else {
                    float* p = C + (size_t)row * N + col;
                    float* q = C + (size_t)(row + 8) * N + col;
                    if (EPI == 1) { v0 += p[0]; v1 += p[1]; v2 += q[0]; v3 += q[1]; }
                    *(float2*)p = make_float2(v0, v1);
                    *(float2*)q = make_float2(v2, v3);
                }
            }
    }
}

// ========= Split-KV tensor-core flash attention (unchanged from R16) =========
#define AT_SMEM (4096 + 16384 + 2 * 16384)

__global__ void __launch_bounds__(128)
attn_kernel(const __half* __restrict__ qh,
            const __half* __restrict__ kh,
            const __half* __restrict__ vt,
            const int* __restrict__ mask,
            float* __restrict__ opart,
            float* __restrict__ ml) {
    extern __shared__ __align__(128) char asmem[];
    float* bias = (float*)asmem;
    unsigned sb = (unsigned)__cvta_generic_to_shared(asmem);
    const unsigned Qs  = sb + 4096;
    const unsigned KV0 = sb + 20480;

    const int tid = threadIdx.x, lane = tid & 31, warp = tid >> 5;
    const int qb_i = blockIdx.x;
    const int q0 = qb_i * 64;
    const int split = blockIdx.y & 1;
    const int h = blockIdx.y >> 1, b = blockIdx.z;
    const int bh = b * H + h;
    const int cbeg = split * (qb_i + 1);
    const int cend = (split + 1) * (qb_i + 1);

    for (int i = tid; i < SEQ; i += 128)
        bias[i] = (mask[b * SEQ + i] == 0) ? NEGB : 0.f;

    {
        const __half* qb = qh + ((size_t)bh * SEQ + q0) * DH;
        #pragma unroll
        for (int i = 0; i < 8; i++) {
            int g = tid + i * 128;
            int seg = g & 3, r = (g >> 2) & 15, s = (g >> 6) & 3, w = g >> 8;
            cpasync16(Qs + w * 4096 + s * 1024 + swz(prow(r, seg)),
                      qb + (size_t)(w * 16 + r) * DH + s * 32 + seg * 8);
        }
    }
    auto load_kv = [&](int c, int buf) {
        int j0 = c * 32;
        unsigned Kb = KV0 + buf * 16384;
        const __half* kb = kh + ((size_t)bh * SEQ + j0) * DH;
        const __half* vb = vt + (size_t)bh * DH * SEQ + j0;
        #pragma unroll
        for (int i = 0; i < 4; i++) {
            int g = tid + i * 128;
            int seg = g & 3, r = (g >> 2) & 31, s = g >> 7;
            cpasync16(Kb + s * 2048 + swz(prow(r, seg)),
                      kb + (size_t)r * DH + s * 32 + seg * 8);
        }
        #pragma unroll
        for (int i = 0; i < 4; i++) {
            int g = tid + i * 128;
            int seg = g & 3, d = g >> 2;
            cpasync16(Kb + 8192 + swz(prow(d, seg)),
                      vb + (size_t)d * SEQ + seg * 8);
        }
    };

    load_kv(cbeg, 0);
    asm volatile("cp.async.commit_group;\n");
    load_kv(cbeg + 1, 1);
    asm volatile("cp.async.commit_group;\n");

    const unsigned qA = Qs + warp * 4096 + swz(prow(lane & 15, lane >> 4));
    unsigned kB[2], vB[8];
    #pragma unroll
    for (int np = 0; np < 2; np++)
        kB[np] = swz(prow(np * 16 + (lane & 15), lane >> 4));
    #pragma unroll
    for (int np = 0; np < 8; np++)
        vB[np] = swz(prow(np * 16 + (lane & 15), lane >> 4));

    const int rowA = q0 + warp * 16 + (lane >> 2);
    const int rowB = rowA + 8;

    float o[16][4];
    #pragma unroll
    for (int i = 0; i < 16; i++)
        #pragma unroll
        for (int r = 0; r < 4; r++) o[i][r] = 0.f;
    float mA = -1e30f, mB = -1e30f, lA = 0.f, lB = 0.f;

    for (int c = cbeg; c < cend; c++) {
        asm volatile("cp.async.wait_group 1;\n");
        __syncthreads();
        unsigned Kb = KV0 + (unsigned)((c - cbeg) & 1) * 16384;
        unsigned Vb = Kb + 8192;

        float sc[4][4];
        #pragma unroll
        for (int i = 0; i < 4; i++)
            #pragma unroll
            for (int r = 0; r < 4; r++) sc[i][r] = 0.f;
        #pragma unroll
        for (int s = 0; s < 4; s++) {
            #pragma unroll
            for (int t = 0; t < 2; t++) {
                unsigned fa0, fa1, fa2, fa3;
                ldsm4((qA + s * 1024) ^ (t * 32), fa0, fa1, fa2, fa3);
                #pragma unroll
                for (int np = 0; np < 2; np++) {
                    unsigned b0, b1, b2, b3;
                    ldsm4((Kb + s * 2048 + kB[np]) ^ (t * 32), b0, b1, b2, b3);
                    mma16816(sc[2 * np],     fa0, fa1, fa2, fa3, b0, b2);
                    mma16816(sc[2 * np + 1], fa0, fa1, fa2, fa3, b1, b3);
                }
            }
        }

        const int j0 = c * 32;
        #pragma unroll
        for (int ni = 0; ni < 4; ni++) {
            int jb = j0 + ni * 8 + 2 * (lane & 3);
            float b0 = bias[jb], b1 = bias[jb + 1];
            sc[ni][0] = (jb     <= rowA) ? sc[ni][0] * SCALE2 + b0 : -1e30f;
            sc[ni][1] = (jb + 1 <= rowA) ? sc[ni][1] * SCALE2 + b1 : -1e30f;
            sc[ni][2] = (jb     <= rowB) ? sc[ni][2] * SCALE2 + b0 : -1e30f;
            sc[ni][3] = (jb + 1 <= rowB) ? sc[ni][3] * SCALE2 + b1 : -1e30f;
        }

        float cmA = -1e30f, cmB = -1e30f;
        #pragma unroll
        for (int ni = 0; ni < 4; ni++) {
            cmA = fmaxf(cmA, fmaxf(sc[ni][0], sc[ni][1]));
            cmB = fmaxf(cmB, fmaxf(sc[ni][2], sc[ni][3]));
        }
        #pragma unroll
        for (int off = 1; off <= 2; off <<= 1) {
            cmA = fmaxf(cmA, __shfl_xor_sync(0xffffffffu, cmA, off));
            cmB = fmaxf(cmB, __shfl_xor_sync(0xffffffffu, cmB, off));
        }
        float newA = fmaxf(mA, cmA), newB = fmaxf(mB, cmB);
        float corrA = exp2f(mA - newA), corrB = exp2f(mB - newB);
        mA = newA; mB = newB;

        unsigned hA[4], hB[4];
        float sA = 0.f, sB = 0.f;
        #pragma unroll
        for (int ni = 0; ni < 4; ni++) {
            hA[ni] = ex2h2(sc[ni][0] - newA, sc[ni][1] - newA);
            hB[ni] = ex2h2(sc[ni][2] - newB, sc[ni][3] - newB);
            float2 fa2 = __half22float2(*(__half2*)&hA[ni]);
            float2 fb2 = __half22float2(*(__half2*)&hB[ni]);
            sA += fa2.x + fa2.y;
            sB += fb2.x + fb2.y;
        }
        #pragma unroll
        for (int off = 1; off <= 2; off <<= 1) {
            sA += __shfl_xor_sync(0xffffffffu, sA, off);
            sB += __shfl_xor_sync(0xffffffffu, sB, off);
        }
        lA = lA * corrA + sA;
        lB = lB * corrB + sB;
        #pragma unroll
        for (int ni = 0; ni < 16; ni++) {
            o[ni][0] *= corrA; o[ni][1] *= corrA;
            o[ni][2] *= corrB; o[ni][3] *= corrB;
        }

        #pragma unroll
        for (int t = 0; t < 2; t++) {
            unsigned a0 = hA[2 * t], a1 = hB[2 * t];
            unsigned a2 = hA[2 * t + 1], a3 = hB[2 * t + 1];
            #pragma unroll
            for (int np = 0; np < 8; np++) {
                unsigned b0, b1, b2, b3;
                ldsm4((Vb + vB[np]) ^ (t * 32), b0, b1, b2, b3);
                mma16816(o[2 * np],     a0, a1, a2, a3, b0, b2);
                mma16816(o[2 * np + 1], a0, a1, a2, a3, b1, b3);
            }
        }

        __syncthreads();
        if (c + 2 < cend) load_kv(c + 2, (c - cbeg) & 1);
        asm volatile("cp.async.commit_group;\n");
    }

    const size_t sbh = (size_t)(split * BATCH + b) * H + h;
    const size_t pA = (sbh * SEQ + rowA) * DH;
    const size_t pB = (sbh * SEQ + rowB) * DH;
    #pragma unroll
    for (int ni = 0; ni < 16; ni++) {
        int col = ni * 8 + 2 * (lane & 3);
        *(float2*)(opart + pA + col) = make_float2(o[ni][0], o[ni][1]);
        *(float2*)(opart + pB + col) = make_float2(o[ni][2], o[ni][3]);
    }
    if ((lane & 3) == 0) {
        *(float2*)(ml + (sbh * SEQ + rowA) * 2) = make_float2(mA, lA);
        *(float2*)(ml + (sbh * SEQ + rowB) * 2) = make_float2(mB, lB);
    }
}

// ---------------- Merge split-KV partials -> fp16 token-major ----------------
__global__ void attmerge_kernel(const float* __restrict__ opart,
                                const float* __restrict__ ml,
                                __half* __restrict__ ao) {
    const int t = blockIdx.x;
    const int b = t / SEQ, q = t % SEQ;
    const int tid = threadIdx.x;
    #pragma unroll
    for (int i = 0; i < 8; i++) {
        int idx = tid + i * 256;
        int h = idx >> 7, d = idx & 127;
        size_t r0 = ((size_t)(0 * BATCH + b) * H + h) * SEQ + q;
        size_t r1 = ((size_t)(1 * BATCH + b) * H + h) * SEQ + q;
        float2 ml0 = *(const float2*)(ml + r0 * 2);
        float2 ml1 = *(const float2*)(ml + r1 * 2);
        float mm = fmaxf(ml0.x, ml1.x);
        float w0 = exp2f(ml0.x - mm), w1 = exp2f(ml1.x - mm);
        float l = ml0.y * w0 + ml1.y * w1;
        float o0 = opart[r0 * DH + d], o1 = opart[r1 * DH + d];
        ao[(size_t)t * D + idx] = __float2half_rn((o0 * w0 + o1 * w1) / l);
    }
}

// ---------------- Pool + head ----------------
__global__ void meanpool_kernel(const float* __restrict__ hs,
                                const int* __restrict__ mask,
                                float* __restrict__ mean) {
    int idx = blockIdx.x * blockDim.x + threadIdx.x;
    int b = idx / D;
    int d = idx % D;
    float acc = 0.f, msum = 0.f;
    const float* hb = hs + (size_t)b * SEQ * D + d;
    const int* mb = mask + b * SEQ;
    for (int s = 0; s < SEQ; s++) {
        float mf = (float)mb[s];
        acc = fmaf(mf, hb[(size_t)s * D], acc);
        msum += mf;
    }
    mean[idx] = acc / fmaxf(msum, 1e-9f);
}

__global__ void head1_kernel(const float* __restrict__ mean,
                             const float* __restrict__ Wc1,
                             const float* __restrict__ bc1,
                             float* __restrict__ t) {
    int idx = blockIdx.x * blockDim.x + threadIdx.x;
    int b = idx / D;
    int j = idx % D;
    float acc = bc1[j];
    const float* mb = mean + (size_t)b * D;
    for (int k = 0; k < D; k++)
        acc = fmaf(mb[k], Wc1[(size_t)k * D + j], acc);
    t[idx] = tanhf(acc);
}

__global__ void head2_kernel(const float* __restrict__ t,
                             const float* __restrict__ Wc2,
                             const float* __restrict__ bc2,
                             float* __restrict__ out) {
    __shared__ float red[256];
    __shared__ float logits[4];
    const int tid = threadIdx.x;
    float part[4] = {0.f, 0.f, 0.f, 0.f};
    for (int j = tid; j < D; j += 256) {
        float t0 = t[j], t1 = t[D + j];
        float w0 = Wc2[2 * j], w1 = Wc2[2 * j + 1];
        part[0] = fmaf(t0, w0, part[0]);
        part[1] = fmaf(t0, w1, part[1]);
        part[2] = fmaf(t1, w0, part[2]);
        part[3] = fmaf(t1, w1, part[3]);
    }
    for (int c = 0; c < 4; c++) {
        __syncthreads();
        red[tid] = part[c]; __syncthreads();
        for (int st = 128; st > 0; st >>= 1) {
            if (tid < st) red[tid] += red[tid + st];
            __syncthreads();
        }
        if (tid == 0) logits[c] = red[0] + bc2[c & 1];
    }
    __syncthreads();
    if (tid == 0) {
        for (int b = 0; b < BATCH; b++) {
            float l0 = logits[2 * b], l1 = logits[2 * b + 1];
            float m = fmaxf(l0, l1);
            float e0 = expf(l0 - m), e1 = expf(l1 - m);
            out[b] = e1 / (e0 + e1);
        }
    }
}

// ---------------- Launch ----------------
extern "C" void kernel_launch(void* const* d_in, const int* in_sizes, int n_in,
                              void* d_out, int out_size) {
    const int*   ids   = (const int*)d_in[0];
    const int*   amask = (const int*)d_in[1];
    const float* emb   = (const float*)d_in[2];
    const float* ln1_g = (const float*)d_in[3];
    const float* ln1_b = (const float*)d_in[4];
    const float* Wqkv  = (const float*)d_in[5];
    const float* Wo    = (const float*)d_in[6];
    const float* ln2_g = (const float*)d_in[7];
    const float* ln2_b = (const float*)d_in[8];
    const float* W1    = (const float*)d_in[9];
    const float* W2    = (const float*)d_in[10];
    const float* lnf_g = (const float*)d_in[11];
    const float* lnf_b = (const float*)d_in[12];
    const float* Wc1   = (const float*)d_in[13];
    const float* bc1   = (const float*)d_in[14];
    const float* Wc2   = (const float*)d_in[15];
    const float* bc2   = (const float*)d_in[16];
    float* out = (float*)d_out;

    float *x, *h, *mean, *t, *opart, *ml;
    __half *ha_d, *ha_f, *qh, *kh, *vt, *wqkvT, *woT, *w1T, *w2T;
    cudaGetSymbolAddress((void**)&x,    g_x);
    cudaGetSymbolAddress((void**)&h,    g_h);
    cudaGetSymbolAddress((void**)&mean, g_mean);
    cudaGetSymbolAddress((void**)&t,    g_t);
    cudaGetSymbolAddress((void**)&ha_d, g_ha_d);
    cudaGetSymbolAddress((void**)&ha_f, g_ha_f);
    cudaGetSymbolAddress((void**)&qh,   g_qh);
    cudaGetSymbolAddress((void**)&kh,   g_kh);
    cudaGetSymbolAddress((void**)&vt,   g_vt);
    cudaGetSymbolAddress((void**)&opart, g_opart);
    cudaGetSymbolAddress((void**)&ml,    g_ml);
    cudaGetSymbolAddress((void**)&wqkvT, g_wqkvT);
    cudaGetSymbolAddress((void**)&woT,   g_woT);
    cudaGetSymbolAddress((void**)&w1T,   g_w1T);
    cudaGetSymbolAddress((void**)&w2T,   g_w2T);

    cudaFuncSetAttribute(bgemm_kernel<1>,
                         cudaFuncAttributeMaxDynamicSharedMemorySize, BG_SMEM);
    cudaFuncSetAttribute(bgemm_kernel<2>,
                         cudaFuncAttributeMaxDynamicSharedMemorySize, BG_SMEM);
    cudaFuncSetAttribute(bgemm_kernel<3>,
                         cudaFuncAttributeMaxDynamicSharedMemorySize, BG_SMEM);
    cudaFuncSetAttribute(attn_kernel,
                         cudaFuncAttributeMaxDynamicSharedMemorySize, AT_SMEM);

    // Side stream: weight transposes, fine-grained join events.
    cudaStream_t s2;
    cudaStreamCreateWithFlags(&s2, cudaStreamNonBlocking);
    cudaEvent_t evFork, evW[8];
    cudaEventCreateWithFlags(&evFork, cudaEventDisableTiming);
    for (int i = 0; i < 8; i++)
        cudaEventCreateWithFlags(&evW[i], cudaEventDisableTiming);

    cudaEventRecord(evFork, 0);
    cudaStreamWaitEvent(s2, evFork, 0);
    for (int l = 0; l < LAYERS; l++) {
        transw_kernel<<<dim3(TD / 32, D / 64), dim3(32, 8), 0, s2>>>(
            Wqkv + (size_t)l * D * TD, wqkvT + (size_t)l * TD * D, D, TD);
        cudaEventRecord(evW[l * 4 + 0], s2);
        transw_kernel<<<dim3(D / 32, D / 64), dim3(32, 8), 0, s2>>>(
            Wo + (size_t)l * D * D, woT + (size_t)l * D * D, D, D);
        cudaEventRecord(evW[l * 4 + 1], s2);
        transw_kernel<<<dim3(FF / 32, D / 64), dim3(32, 8), 0, s2>>>(
            W1 + (size_t)l * D * FF, w1T + (size_t)l * FF * D, D, FF);
        cudaEventRecord(evW[l * 4 + 2], s2);
        transw_kernel<<<dim3(D / 32, FF / 64), dim3(32, 8), 0, s2>>>(
            W2 + (size_t)l * FF * D, w2T + (size_t)l * D * FF, FF, D);
        cudaEventRecord(evW[l * 4 + 3], s2);
    }

    embed_kernel<<<(BS * D) / 256, 256>>>(ids, emb, x);

    for (int l = 0; l < LAYERS; l++) {
        // attention block
        ln_kernel<1><<<BS, 256>>>(x, ln1_g + (size_t)l * D, ln1_b + (size_t)l * D,
                                  nullptr, ha_d);
        cudaStreamWaitEvent(0, evW[l * 4 + 0], 0);
        bgemm_kernel<3><<<NPERS, 128, BG_SMEM>>>(
            ha_d, wqkvT + (size_t)l * TD * D, nullptr, nullptr,
            qh, kh, vt, BS, TD, D);
        attn_kernel<<<dim3(SEQ / 64, H * 2, BATCH), 128, AT_SMEM>>>(
            qh, kh, vt, amask, opart, ml);
        attmerge_kernel<<<BS, 256>>>(opart, ml, ha_d);
        cudaStreamWaitEvent(0, evW[l * 4 + 1], 0);
        bgemm_kernel<1><<<NPERS, 128, BG_SMEM>>>(
            ha_d, woT + (size_t)l * D * D, x, nullptr,
            nullptr, nullptr, nullptr, BS, D, D);
        // mlp block
        ln_kernel<1><<<BS, 256>>>(x, ln2_g + (size_t)l * D, ln2_b + (size_t)l * D,
                                  nullptr, ha_d);
        cudaStreamWaitEvent(0, evW[l * 4 + 2], 0);
        bgemm_kernel<2><<<NPERS, 128, BG_SMEM>>>(
            ha_d, w1T + (size_t)l * FF * D, nullptr, ha_f,
            nullptr, nullptr, nullptr, BS, FF, D);
        cudaStreamWaitEvent(0, evW[l * 4 + 3], 0);
        bgemm_kernel<1><<<NPERS, 128, BG_SMEM>>>(
            ha_f, w2T + (size_t)l * D * FF, x, nullptr,
            nullptr, nullptr, nullptr, BS, D, FF);
    }

    ln_kernel<0><<<BS, 256>>>(x, lnf_g, lnf_b, h, nullptr);
    meanpool_kernel<<<(BATCH * D) / 256, 256>>>(h, amask, mean);
    head1_kernel<<<(BATCH * D) / 256, 256>>>(mean, Wc1, bc1, t);
    head2_kernel<<<1, 256>>>(t, Wc2, bc2, out);
}